// round 10
// baseline (speedup 1.0000x reference)
#include <cuda_runtime.h>
#include <cuda_bf16.h>
#include <math.h>
#include <stdint.h>

typedef __nv_bfloat16 bf16;

// B=32, L=512, T=4096, E=F=256, NB=256
// Output: concat(rounded_duration[B*L], pitch[B*T], energy[B*T], variance_embedding[B*T*E])

// -------- scratch (device globals) --------
__device__ float g_X   [33554432];   // [B,T,E] fp32 length-regulated x (exact path)
__device__ bf16  g_Xhi [33554432];   // hi/lo bf16 split of X
__device__ bf16  g_Xlo [33554432];
__device__ bf16  g_H1hi[33554432];   // hidden1 (post conv1+relu, then LN in-place)
__device__ bf16  g_H1lo[33554432];
__device__ bf16  g_H2hi[33554432];   // hidden2 (post conv2+relu)
__device__ bf16  g_H2lo[33554432];
__device__ float g_H1  [ 4194304];   // duration-path fp32 hiddens
__device__ float g_H2  [ 4194304];
__device__ bf16  g_Wsp [4][589824];  // split weights [n=256, k'=2304] = [Whi|Wlo|Whi]
__device__ int   g_cs  [16384];      // cumsum durations

// ==================================================================
// helpers
// ==================================================================
__device__ __forceinline__ uint32_t smem_u32(const void* p) {
    uint32_t a;
    asm("{ .reg .u64 t; cvta.to.shared.u64 t, %1; cvt.u32.u64 %0, t; }" : "=r"(a) : "l"(p));
    return a;
}
#define SWZ(o) ((o) ^ (((o) >> 3) & 0x70))

__device__ __forceinline__ void cpa16(uint32_t dst, const void* src, int pred) {
    int sz = pred ? 16 : 0;
    asm volatile("cp.async.cg.shared.global [%0], [%1], 16, %2;" :: "r"(dst), "l"(src), "r"(sz));
}
__device__ __forceinline__ uint32_t pack2(float lo, float hi) {
    uint32_t r;
    asm("cvt.rn.bf16x2.f32 %0, %1, %2;" : "=r"(r) : "f"(hi), "f"(lo));
    return r;
}
__device__ __forceinline__ float bf16_round(float v) {
    return __bfloat162float(__float2bfloat16(v));
}
__device__ __forceinline__ void ldm4(uint32_t r[4], uint32_t addr) {
    asm volatile("ldmatrix.sync.aligned.m8n8.x4.shared.b16 {%0,%1,%2,%3}, [%4];"
        : "=r"(r[0]), "=r"(r[1]), "=r"(r[2]), "=r"(r[3]) : "r"(addr));
}
__device__ __forceinline__ void mma16816(float c[4], const uint32_t a[4],
                                         uint32_t b0, uint32_t b1) {
    asm volatile("mma.sync.aligned.m16n8k16.row.col.f32.bf16.bf16.f32 "
        "{%0,%1,%2,%3}, {%4,%5,%6,%7}, {%8,%9}, {%0,%1,%2,%3};"
        : "+f"(c[0]), "+f"(c[1]), "+f"(c[2]), "+f"(c[3])
        : "r"(a[0]), "r"(a[1]), "r"(a[2]), "r"(a[3]), "r"(b0), "r"(b1));
}

// ==================================================================
// split-bf16 HMMA conv(k=3, 256->256) GEMM
// C = Ahi*Whi + Ahi*Wlo + Alo*Whi  (virtual K' = 2304, chunks of 64)
// W layout: [n=256, 2304] = [Whi(768) | Wlo(768) | Whi(768)]
// out: relu(C + bias) written as hi/lo bf16 pair.
// Tile 128(M) x 128(N), double-buffered cp.async, SW128 swizzle.
// ==================================================================
#define HSTG 32768            // per-stage: A 16KB + B 16KB

__global__ __launch_bounds__(256, 2)
void hmma_conv_sp(const bf16* __restrict__ Ahi, const bf16* __restrict__ Alo,
                  const bf16* __restrict__ W, const float* __restrict__ bias,
                  bf16* __restrict__ outhi, bf16* __restrict__ outlo, int S)
{
    extern __shared__ char sm[];
    uint32_t smb = smem_u32(sm);
    int tid  = threadIdx.x;
    int lane = tid & 31;
    int wid  = tid >> 5;
    int warp_m = (wid & 3) * 32;     // 4 warps over M
    int warp_n = (wid >> 2) * 64;    // 2 warps over N

    int m0 = blockIdx.x * 128;
    int b  = m0 / S;
    int t0 = m0 - b * S;
    int n0 = blockIdx.y * 128;

    auto load_chunk = [&](int ci, int stg) {
        int part = ci / 12;               // 0: Ahi*Whi, 1: Ahi*Wlo, 2: Alo*Whi
        int cc   = ci - part * 12;
        int k0in = cc * 64;
        int tap = k0in >> 8, c0 = k0in & 255;
        const bf16* Ab = ((part == 2) ? Alo : Ahi) + (size_t)b * S * 256;
        int k0w = ci * 64;
        uint32_t Asm = smb + stg * HSTG;
        uint32_t Bsm = Asm + 16384;
        #pragma unroll
        for (int j = 0; j < 4; j++) {                 // A: 128 rows x 128B
            int u = tid + 256 * j, row = u >> 3, c16 = u & 7;
            int tr = t0 + row + tap - 1;
            cpa16(Asm + SWZ(row * 128 + c16 * 16),
                  Ab + (size_t)tr * 256 + c0 + c16 * 8,
                  (unsigned)tr < (unsigned)S);
        }
        #pragma unroll
        for (int j = 0; j < 4; j++) {                 // B: 128 n-rows x 128B
            int u = tid + 256 * j, n = u >> 3, c16 = u & 7;
            cpa16(Bsm + SWZ(n * 128 + c16 * 16),
                  W + (size_t)(n0 + n) * 2304 + k0w + c16 * 8, 1);
        }
    };

    float acc[2][8][4];
    #pragma unroll
    for (int i = 0; i < 2; i++)
        #pragma unroll
        for (int j = 0; j < 8; j++)
            #pragma unroll
            for (int e = 0; e < 4; e++) acc[i][j][e] = 0.f;

    int g = lane >> 3;
    int arow = ((g & 1) << 3) + (lane & 7);
    int akk  = (g >> 1) << 3;
    int brow = ((g >> 1) << 3) + (lane & 7);
    int bkk  = (g & 1) << 3;

    load_chunk(0, 0);
    asm volatile("cp.async.commit_group;" ::: "memory");

    const int NC = 36;                    // 2304 / 64
    for (int i = 0; i < NC; i++) {
        if (i + 1 < NC) {
            load_chunk(i + 1, (i + 1) & 1);
            asm volatile("cp.async.commit_group;" ::: "memory");
            asm volatile("cp.async.wait_group 1;" ::: "memory");
        } else {
            asm volatile("cp.async.wait_group 0;" ::: "memory");
        }
        __syncthreads();

        uint32_t Asm = smb + (i & 1) * HSTG;
        uint32_t Bsm = Asm + 16384;
        #pragma unroll
        for (int ks = 0; ks < 4; ks++) {
            int kk = ks * 16;
            uint32_t a[2][4], bq[4][4];
            #pragma unroll
            for (int mt = 0; mt < 2; mt++) {
                int row = warp_m + mt * 16 + arow;
                ldm4(a[mt], Asm + SWZ(row * 128 + (kk + akk) * 2));
            }
            #pragma unroll
            for (int q = 0; q < 4; q++) {
                int n = warp_n + q * 16 + brow;
                ldm4(bq[q], Bsm + SWZ(n * 128 + (kk + bkk) * 2));
            }
            #pragma unroll
            for (int mt = 0; mt < 2; mt++)
                #pragma unroll
                for (int nb = 0; nb < 8; nb++) {
                    int q = nb >> 1, h = (nb & 1) * 2;
                    mma16816(acc[mt][nb], a[mt], bq[q][h], bq[q][h + 1]);
                }
        }
        __syncthreads();
    }

    // epilogue: bias + relu -> hi/lo bf16
    int colq = (lane & 3) * 2;
    int rowq = lane >> 2;
    #pragma unroll
    for (int mt = 0; mt < 2; mt++) {
        #pragma unroll
        for (int nb = 0; nb < 8; nb++) {
            int col = n0 + warp_n + nb * 8 + colq;
            float bs0 = bias[col], bs1 = bias[col + 1];
            int tokA = m0 + warp_m + mt * 16 + rowq;
            int tokB = tokA + 8;
            float v0 = fmaxf(acc[mt][nb][0] + bs0, 0.f);
            float v1 = fmaxf(acc[mt][nb][1] + bs1, 0.f);
            float v2 = fmaxf(acc[mt][nb][2] + bs0, 0.f);
            float v3 = fmaxf(acc[mt][nb][3] + bs1, 0.f);
            float h0 = bf16_round(v0), h1 = bf16_round(v1);
            float h2 = bf16_round(v2), h3 = bf16_round(v3);
            *(uint32_t*)(outhi + (size_t)tokA * 256 + col) = pack2(h0, h1);
            *(uint32_t*)(outhi + (size_t)tokB * 256 + col) = pack2(h2, h3);
            *(uint32_t*)(outlo + (size_t)tokA * 256 + col) = pack2(v0 - h0, v1 - h1);
            *(uint32_t*)(outlo + (size_t)tokB * 256 + col) = pack2(v2 - h2, v3 - h3);
        }
    }
}

// ==================================================================
// weight repack with hi/lo split:
// src w[pred][kk][c][n] f32 -> g_Wsp[mat][n*2304 + blk*768 + kk*256 + c]
// blk 0 = Whi, blk 1 = Wlo, blk 2 = Whi.  mats: 0=(w1,p1) 1=(w2,p1) 2=(w1,p2) 3=(w2,p2)
// ==================================================================
__global__ void repack_w_sp(const float* __restrict__ w1, const float* __restrict__ w2)
{
    int e = blockIdx.x * 256 + threadIdx.x;      // 4 * 589824 total
    int mat = e / 589824;
    int r   = e - mat * 589824;
    int n = r / 2304, kq = r - n * 2304;
    int blk = kq / 768, k = kq - blk * 768;
    int kk = k >> 8, c = k & 255;
    int p = (mat >> 1) + 1;
    const float* src = (mat & 1) ? w2 : w1;
    float w = src[(((size_t)p * 3 + kk) * 256 + c) * 256 + n];
    float hi = __bfloat162float(__float2bfloat16(w));
    g_Wsp[mat][r] = __float2bfloat16(blk == 1 ? (w - hi) : w);
}

// ==================================================================
// LayerNorm on hi/lo pair (warp per token), fp32 stats, hi/lo out
// ==================================================================
__global__ void ln_pair_kernel(bf16* __restrict__ hi, bf16* __restrict__ lo,
                               const float* __restrict__ sc, const float* __restrict__ bi,
                               int ntok)
{
    int w = threadIdx.x >> 5, lane = threadIdx.x & 31;
    int t = blockIdx.x * 8 + w;
    if (t >= ntok) return;
    size_t base = (size_t)t * 256 + lane * 8;
    uint4 rh = *(uint4*)(hi + base);
    uint4 rl = *(uint4*)(lo + base);
    uint32_t ph[4] = {rh.x, rh.y, rh.z, rh.w};
    uint32_t pl[4] = {rl.x, rl.y, rl.z, rl.w};
    float v[8];
    #pragma unroll
    for (int j = 0; j < 4; j++) {
        v[2*j]   = __bfloat162float(((bf16*)&ph[j])[0]) + __bfloat162float(((bf16*)&pl[j])[0]);
        v[2*j+1] = __bfloat162float(((bf16*)&ph[j])[1]) + __bfloat162float(((bf16*)&pl[j])[1]);
    }
    float s = 0.f, q = 0.f;
    #pragma unroll
    for (int j = 0; j < 8; j++) { s += v[j]; q += v[j] * v[j]; }
    #pragma unroll
    for (int o = 16; o; o >>= 1) {
        s += __shfl_xor_sync(0xffffffffu, s, o);
        q += __shfl_xor_sync(0xffffffffu, q, o);
    }
    float m = s * (1.f / 256.f);
    float r = rsqrtf(q * (1.f / 256.f) - m * m + 1e-5f);
    float4 s0 = *(const float4*)(sc + lane * 8);
    float4 s1 = *(const float4*)(sc + lane * 8 + 4);
    float4 b0 = *(const float4*)(bi + lane * 8);
    float4 b1 = *(const float4*)(bi + lane * 8 + 4);
    float sa[8] = {s0.x, s0.y, s0.z, s0.w, s1.x, s1.y, s1.z, s1.w};
    float ba[8] = {b0.x, b0.y, b0.z, b0.w, b1.x, b1.y, b1.z, b1.w};
    uint32_t oh[4], ol[4];
    #pragma unroll
    for (int j = 0; j < 4; j++) {
        float o0 = (v[2*j]   - m) * r * sa[2*j]   + ba[2*j];
        float o1 = (v[2*j+1] - m) * r * sa[2*j+1] + ba[2*j+1];
        float h0 = bf16_round(o0), h1 = bf16_round(o1);
        oh[j] = pack2(h0, h1);
        ol[j] = pack2(o0 - h0, o1 - h1);
    }
    *(uint4*)(hi + base) = make_uint4(oh[0], oh[1], oh[2], oh[3]);
    *(uint4*)(lo + base) = make_uint4(ol[0], ol[1], ol[2], ol[3]);
}

// ==================================================================
// fused LN + linear F->1 + mask on hi/lo pair (warp per token)
// ==================================================================
__global__ void lnlin_pair_kernel(const bf16* __restrict__ hi, const bf16* __restrict__ lo,
                                  const float* __restrict__ sc, const float* __restrict__ bi,
                                  const float* __restrict__ lw, const float* __restrict__ lb,
                                  const unsigned char* __restrict__ mask,
                                  float* __restrict__ out, int ntok)
{
    int w = threadIdx.x >> 5, lane = threadIdx.x & 31;
    int t = blockIdx.x * 8 + w;
    if (t >= ntok) return;
    size_t base = (size_t)t * 256 + lane * 8;
    uint4 rh = *(const uint4*)(hi + base);
    uint4 rl = *(const uint4*)(lo + base);
    uint32_t ph[4] = {rh.x, rh.y, rh.z, rh.w};
    uint32_t pl[4] = {rl.x, rl.y, rl.z, rl.w};
    float v[8];
    #pragma unroll
    for (int j = 0; j < 4; j++) {
        v[2*j]   = __bfloat162float(((bf16*)&ph[j])[0]) + __bfloat162float(((bf16*)&pl[j])[0]);
        v[2*j+1] = __bfloat162float(((bf16*)&ph[j])[1]) + __bfloat162float(((bf16*)&pl[j])[1]);
    }
    float s = 0.f, q = 0.f;
    #pragma unroll
    for (int j = 0; j < 8; j++) { s += v[j]; q += v[j] * v[j]; }
    #pragma unroll
    for (int o = 16; o; o >>= 1) {
        s += __shfl_xor_sync(0xffffffffu, s, o);
        q += __shfl_xor_sync(0xffffffffu, q, o);
    }
    float m = s * (1.f / 256.f);
    float r = rsqrtf(q * (1.f / 256.f) - m * m + 1e-5f);
    float4 s0 = *(const float4*)(sc + lane * 8);
    float4 s1 = *(const float4*)(sc + lane * 8 + 4);
    float4 b0 = *(const float4*)(bi + lane * 8);
    float4 b1 = *(const float4*)(bi + lane * 8 + 4);
    float4 w0 = *(const float4*)(lw + lane * 8);
    float4 w1 = *(const float4*)(lw + lane * 8 + 4);
    float sa[8] = {s0.x, s0.y, s0.z, s0.w, s1.x, s1.y, s1.z, s1.w};
    float ba[8] = {b0.x, b0.y, b0.z, b0.w, b1.x, b1.y, b1.z, b1.w};
    float wa[8] = {w0.x, w0.y, w0.z, w0.w, w1.x, w1.y, w1.z, w1.w};
    float d = 0.f;
    #pragma unroll
    for (int j = 0; j < 8; j++)
        d += ((v[j] - m) * r * sa[j] + ba[j]) * wa[j];
    #pragma unroll
    for (int o = 16; o; o >>= 1) d += __shfl_xor_sync(0xffffffffu, d, o);
    if (lane == 0) {
        float val = d + lb[0];
        if (mask[t]) val = 0.f;
        out[t] = val;
    }
}

// ==================================================================
// fp32 duration-path GEMM (exact, proven R1 code)
// ==================================================================
#define BM 128
#define BN 128
#define BK 16
#define NKT 48

__device__ __forceinline__ void cg_load(const float* __restrict__ inb,
                                        const float* __restrict__ W,
                                        int S, int t0, int n0, int kt, int tid,
                                        float4 av[2], float4 bv[2]) {
    int kc = kt * BK;
    int kk = kc >> 8, c0 = kc & 255;
    #pragma unroll
    for (int it = 0; it < 2; it++) {
        int idx = tid + it * 256;
        int m = idx >> 2, v = idx & 3;
        int t = t0 + m + kk - 1;
        float4 a = make_float4(0.f, 0.f, 0.f, 0.f);
        if (t >= 0 && t < S)
            a = *(const float4*)(inb + (size_t)t * 256 + c0 + v * 4);
        av[it] = a;
        int k = idx >> 5, nv = idx & 31;
        bv[it] = *(const float4*)(W + (size_t)(kc + k) * 256 + n0 + nv * 4);
    }
}
__device__ __forceinline__ void cg_store(float* As, float* Bs, int tid,
                                         const float4 av[2], const float4 bv[2]) {
    #pragma unroll
    for (int it = 0; it < 2; it++) {
        int idx = tid + it * 256;
        int m = idx >> 2, v = idx & 3;
        float vals[4] = {av[it].x, av[it].y, av[it].z, av[it].w};
        #pragma unroll
        for (int w = 0; w < 4; w++)
            *(float2*)&As[(v * 4 + w) * 256 + 2 * m] = make_float2(vals[w], vals[w]);
        int k = idx >> 5, nv = idx & 31;
        *(float4*)&Bs[k * BN + nv * 4] = bv[it];
    }
}
union U64F2 { unsigned long long u; float2 f; };
__device__ __forceinline__ void cg_compute(const float* As, const float* Bs,
                                           int ty, int tx, unsigned long long acc[8][4]) {
    #pragma unroll
    for (int k = 0; k < BK; k++) {
        const float* ar = As + k * 256 + 16 * ty;
        ulonglong2 q0 = *(const ulonglong2*)(ar + 0);
        ulonglong2 q1 = *(const ulonglong2*)(ar + 4);
        ulonglong2 q2 = *(const ulonglong2*)(ar + 8);
        ulonglong2 q3 = *(const ulonglong2*)(ar + 12);
        unsigned long long a8[8] = {q0.x, q0.y, q1.x, q1.y, q2.x, q2.y, q3.x, q3.y};
        const float* br = Bs + k * BN + 8 * tx;
        ulonglong2 p0 = *(const ulonglong2*)(br + 0);
        ulonglong2 p1 = *(const ulonglong2*)(br + 4);
        unsigned long long b4[4] = {p0.x, p0.y, p1.x, p1.y};
        #pragma unroll
        for (int i = 0; i < 8; i++)
            #pragma unroll
            for (int j = 0; j < 4; j++)
                asm("fma.rn.f32x2 %0, %1, %2, %0;" : "+l"(acc[i][j]) : "l"(a8[i]), "l"(b4[j]));
    }
}
__global__ __launch_bounds__(256) void conv_gemm_kernel(
    const float* __restrict__ in, const float* __restrict__ W,
    const float* __restrict__ bias, float* __restrict__ out, int S)
{
    __shared__ float sm[12288];
    float* As0 = sm;        float* Bs0 = sm + 4096;
    float* As1 = sm + 6144; float* Bs1 = sm + 10240;
    int tid = threadIdx.x;
    int m0 = blockIdx.x * BM;
    int b  = m0 / S;
    int t0 = m0 - b * S;
    int n0 = blockIdx.y * BN;
    int ty = tid >> 4, tx = tid & 15;
    const float* inb = in + (size_t)b * S * 256;
    unsigned long long acc[8][4];
    #pragma unroll
    for (int i = 0; i < 8; i++)
        #pragma unroll
        for (int j = 0; j < 4; j++) acc[i][j] = 0ull;
    float4 av[2], bv[2];
    cg_load(inb, W, S, t0, n0, 0, tid, av, bv);
    cg_store(As0, Bs0, tid, av, bv);
    __syncthreads();
    for (int kt = 0; kt < NKT; kt++) {
        const float* Ac = (kt & 1) ? As1 : As0;
        const float* Bc = (kt & 1) ? Bs1 : Bs0;
        float* An = (kt & 1) ? As0 : As1;
        float* Bn = (kt & 1) ? Bs0 : Bs1;
        if (kt + 1 < NKT) cg_load(inb, W, S, t0, n0, kt + 1, tid, av, bv);
        cg_compute(Ac, Bc, ty, tx, acc);
        if (kt + 1 < NKT) cg_store(An, Bn, tid, av, bv);
        __syncthreads();
    }
    const float* bp = bias + n0 + 8 * tx;
    float bs8[8];
    #pragma unroll
    for (int j = 0; j < 8; j++) bs8[j] = bp[j];
    #pragma unroll
    for (int i = 0; i < 8; i++) {
        int t = t0 + 8 * ty + i;
        float* orow = out + ((size_t)b * S + t) * 256 + n0 + 8 * tx;
        float o[8];
        #pragma unroll
        for (int j = 0; j < 4; j++) { U64F2 c; c.u = acc[i][j]; o[2*j] = c.f.x; o[2*j+1] = c.f.y; }
        #pragma unroll
        for (int j = 0; j < 8; j++) o[j] = fmaxf(o[j] + bs8[j], 0.f);
        *(float4*)(orow)     = make_float4(o[0], o[1], o[2], o[3]);
        *(float4*)(orow + 4) = make_float4(o[4], o[5], o[6], o[7]);
    }
}

__global__ void ln_kernel(float* __restrict__ h, const float* __restrict__ sc,
                          const float* __restrict__ bi, int ntok)
{
    int w = threadIdx.x >> 5, lane = threadIdx.x & 31;
    int t = blockIdx.x * 8 + w;
    if (t >= ntok) return;
    float* row = h + (size_t)t * 256;
    float4 v0 = *(float4*)(row + lane * 4);
    float4 v1 = *(float4*)(row + 128 + lane * 4);
    float s = v0.x + v0.y + v0.z + v0.w + v1.x + v1.y + v1.z + v1.w;
    float q = v0.x*v0.x + v0.y*v0.y + v0.z*v0.z + v0.w*v0.w
            + v1.x*v1.x + v1.y*v1.y + v1.z*v1.z + v1.w*v1.w;
    #pragma unroll
    for (int o = 16; o; o >>= 1) {
        s += __shfl_xor_sync(0xffffffffu, s, o);
        q += __shfl_xor_sync(0xffffffffu, q, o);
    }
    float m = s * (1.f / 256.f);
    float r = rsqrtf(q * (1.f / 256.f) - m * m + 1e-5f);
    int f0 = lane * 4, f1 = 128 + lane * 4;
    float4 s0 = *(const float4*)(sc + f0), s1 = *(const float4*)(sc + f1);
    float4 b0 = *(const float4*)(bi + f0), b1 = *(const float4*)(bi + f1);
    v0.x = (v0.x - m)*r*s0.x + b0.x;  v0.y = (v0.y - m)*r*s0.y + b0.y;
    v0.z = (v0.z - m)*r*s0.z + b0.z;  v0.w = (v0.w - m)*r*s0.w + b0.w;
    v1.x = (v1.x - m)*r*s1.x + b1.x;  v1.y = (v1.y - m)*r*s1.y + b1.y;
    v1.z = (v1.z - m)*r*s1.z + b1.z;  v1.w = (v1.w - m)*r*s1.w + b1.w;
    *(float4*)(row + lane * 4)       = v0;
    *(float4*)(row + 128 + lane * 4) = v1;
}

__global__ void dur_final_kernel(const float* __restrict__ h, const float* __restrict__ lw,
                                 const float* __restrict__ lb,
                                 const unsigned char* __restrict__ mask,
                                 const int* __restrict__ scale,
                                 float* __restrict__ out, int ntok)
{
    int w = threadIdx.x >> 5, lane = threadIdx.x & 31;
    int t = blockIdx.x * 8 + w;
    if (t >= ntok) return;
    const float* row = h + (size_t)t * 256;
    float4 v0 = *(const float4*)(row + lane * 4);
    float4 v1 = *(const float4*)(row + 128 + lane * 4);
    float4 w0 = *(const float4*)(lw + lane * 4);
    float4 w1 = *(const float4*)(lw + 128 + lane * 4);
    float d = v0.x*w0.x + v0.y*w0.y + v0.z*w0.z + v0.w*w0.w
            + v1.x*w1.x + v1.y*w1.y + v1.z*w1.z + v1.w*w1.w;
    #pragma unroll
    for (int o = 16; o; o >>= 1) d += __shfl_xor_sync(0xffffffffu, d, o);
    if (lane == 0) {
        float val = d + lb[0];
        if (mask[t]) val = 0.f;
        out[t] = fmaxf(rintf(expf(val) * (float)(*scale)), 0.f);
    }
}

// ==================================================================
// cumsum / length-regulate / embedding add
// ==================================================================
__global__ void cumsum_kernel(const int* __restrict__ dur, int* __restrict__ cs)
{
    __shared__ int s[512];
    int b = blockIdx.x, t = threadIdx.x;
    s[t] = dur[b * 512 + t];
    __syncthreads();
    for (int off = 1; off < 512; off <<= 1) {
        int v = (t >= off) ? s[t - off] : 0;
        __syncthreads();
        s[t] += v;
        __syncthreads();
    }
    cs[b * 512 + t] = s[t];
}

__global__ void length_reg_kernel(const float* __restrict__ hidden,
                                  const int* __restrict__ cs,
                                  float* __restrict__ X,
                                  bf16* __restrict__ Xhi, bf16* __restrict__ Xlo)
{
    __shared__ int scs[512];
    int tid = threadIdx.x;
    int base = blockIdx.x * 4;
    int b    = base >> 12;
    int tloc = base & 4095;
    const int* csb = cs + b * 512;
    scs[tid] = csb[tid];
    scs[tid + 256] = csb[tid + 256];
    __syncthreads();
    int g = tid >> 6, lane = tid & 63;
    int t = tloc + g;
    int lo = 0, hi = 512;
    while (lo < hi) { int mid = (lo + hi) >> 1; if (scs[mid] <= t) lo = mid + 1; else hi = mid; }
    int idx = lo < 512 ? lo : 511;
    bool valid = t < scs[511];
    float4 v = make_float4(0.f, 0.f, 0.f, 0.f);
    if (valid) v = *(const float4*)(hidden + ((size_t)b * 512 + idx) * 256 + lane * 4);
    size_t off = ((size_t)b * 4096 + t) * 256 + lane * 4;
    *(float4*)(X + off) = v;
    float hx = bf16_round(v.x), hy = bf16_round(v.y);
    float hz = bf16_round(v.z), hw = bf16_round(v.w);
    *(uint2*)(Xhi + off) = make_uint2(pack2(hx, hy), pack2(hz, hw));
    *(uint2*)(Xlo + off) = make_uint2(pack2(v.x - hx, v.y - hy), pack2(v.z - hz, v.w - hw));
}

__global__ void add_emb_kernel(const float* __restrict__ X, const float* __restrict__ tgt,
                               const float* __restrict__ bins, const float* __restrict__ emb,
                               float* __restrict__ outp,
                               bf16* __restrict__ Xhi, bf16* __restrict__ Xlo, int wxb)
{
    __shared__ float sb[256];
    int tid = threadIdx.x;
    sb[tid] = bins[tid];
    __syncthreads();
    int base = blockIdx.x * 4;
    int g = tid >> 6, lane = tid & 63;
    int t = base + g;
    float v = tgt[t];
    int lo = 0, hi = 256;
    while (lo < hi) { int mid = (lo + hi) >> 1; if (sb[mid] < v) lo = mid + 1; else hi = mid; }
    int idx = lo < 256 ? lo : 255;
    size_t off = (size_t)t * 256 + lane * 4;
    float4 a = *(const float4*)(X + off);
    float4 e = *(const float4*)(emb + (size_t)idx * 256 + lane * 4);
    a.x += e.x; a.y += e.y; a.z += e.z; a.w += e.w;
    *(float4*)(outp + off) = a;
    if (wxb) {
        float hx = bf16_round(a.x), hy = bf16_round(a.y);
        float hz = bf16_round(a.z), hw = bf16_round(a.w);
        *(uint2*)(Xhi + off) = make_uint2(pack2(hx, hy), pack2(hz, hw));
        *(uint2*)(Xlo + off) = make_uint2(pack2(a.x - hx, a.y - hy), pack2(a.z - hz, a.w - hw));
    }
}

// ==================================================================
// launch
// ==================================================================
extern "C" void kernel_launch(void* const* d_in, const int* in_sizes, int n_in,
                              void* d_out, int out_size)
{
    const float*         hidden    = (const float*)d_in[0];
    const unsigned char* mask      = (const unsigned char*)d_in[1];
    const unsigned char* fmask     = (const unsigned char*)d_in[2];
    const int*           dur_tgt   = (const int*)d_in[3];
    const float*         pitch_tgt = (const float*)d_in[4];
    const float*         energy_tgt= (const float*)d_in[5];
    const int*           dscale    = (const int*)d_in[6];
    const float*         w1        = (const float*)d_in[7];
    const float*         b1        = (const float*)d_in[8];
    const float*         l1s       = (const float*)d_in[9];
    const float*         l1b       = (const float*)d_in[10];
    const float*         w2        = (const float*)d_in[11];
    const float*         b2        = (const float*)d_in[12];
    const float*         l2s       = (const float*)d_in[13];
    const float*         l2b       = (const float*)d_in[14];
    const float*         lw        = (const float*)d_in[15];
    const float*         lb        = (const float*)d_in[16];
    const float*         pbins     = (const float*)d_in[17];
    const float*         pemb      = (const float*)d_in[18];
    const float*         ebins     = (const float*)d_in[19];
    const float*         eemb      = (const float*)d_in[20];

    cudaFuncSetAttribute(hmma_conv_sp, cudaFuncAttributeMaxDynamicSharedMemorySize, 2 * HSTG);

    float* X;  bf16 *Xhi, *Xlo, *H1hi, *H1lo, *H2hi, *H2lo, *Wsp;
    float *H1, *H2;  int* cs;
    cudaGetSymbolAddress((void**)&X,    g_X);
    cudaGetSymbolAddress((void**)&Xhi,  g_Xhi);
    cudaGetSymbolAddress((void**)&Xlo,  g_Xlo);
    cudaGetSymbolAddress((void**)&H1hi, g_H1hi);
    cudaGetSymbolAddress((void**)&H1lo, g_H1lo);
    cudaGetSymbolAddress((void**)&H2hi, g_H2hi);
    cudaGetSymbolAddress((void**)&H2lo, g_H2lo);
    cudaGetSymbolAddress((void**)&H1,   g_H1);
    cudaGetSymbolAddress((void**)&H2,   g_H2);
    cudaGetSymbolAddress((void**)&cs,   g_cs);
    cudaGetSymbolAddress((void**)&Wsp,  g_Wsp);

    float* out_rd     = (float*)d_out;
    float* out_pitch  = out_rd + 32 * 512;
    float* out_energy = out_pitch + 32 * 4096;
    float* out_ve     = out_energy + 32 * 4096;

    repack_w_sp<<<9216, 256>>>(w1, w2);

    // ---- duration predictor (fp32 exact; S=512, 16384 tokens) ----
    {
        dim3 g(16384 / 128, 2);
        conv_gemm_kernel<<<g, 256>>>(hidden, w1, b1, H1, 512);
        ln_kernel<<<16384 / 8, 256>>>(H1, l1s, l1b, 16384);
        conv_gemm_kernel<<<g, 256>>>(H1, w2, b2, H2, 512);
        ln_kernel<<<16384 / 8, 256>>>(H2, l2s, l2b, 16384);
        dur_final_kernel<<<16384 / 8, 256>>>(H2, lw, lb, mask, dscale, out_rd, 16384);
    }

    // ---- length regulate ----
    cumsum_kernel<<<32, 512>>>(dur_tgt, cs);
    length_reg_kernel<<<32 * 4096 / 4, 256>>>(hidden, cs, X, Xhi, Xlo);

    const int NT = 131072;
    dim3 gg(NT / 128, 2);

    // ---- pitch predictor (split-bf16 HMMA) ----
    hmma_conv_sp<<<gg, 256, 2 * HSTG>>>(Xhi,  Xlo,  Wsp + 0 * 589824, b1 + 256, H1hi, H1lo, 4096);
    ln_pair_kernel<<<NT / 8, 256>>>(H1hi, H1lo, l1s + 256, l1b + 256, NT);
    hmma_conv_sp<<<gg, 256, 2 * HSTG>>>(H1hi, H1lo, Wsp + 1 * 589824, b2 + 256, H2hi, H2lo, 4096);
    lnlin_pair_kernel<<<NT / 8, 256>>>(H2hi, H2lo, l2s + 256, l2b + 256,
                                       lw + 256, lb + 1, fmask, out_pitch, NT);
    add_emb_kernel<<<NT / 4, 256>>>(X, pitch_tgt, pbins, pemb, X, Xhi, Xlo, 1);

    // ---- energy predictor (split-bf16 HMMA) ----
    hmma_conv_sp<<<gg, 256, 2 * HSTG>>>(Xhi,  Xlo,  Wsp + 2 * 589824, b1 + 512, H1hi, H1lo, 4096);
    ln_pair_kernel<<<NT / 8, 256>>>(H1hi, H1lo, l1s + 512, l1b + 512, NT);
    hmma_conv_sp<<<gg, 256, 2 * HSTG>>>(H1hi, H1lo, Wsp + 3 * 589824, b2 + 512, H2hi, H2lo, 4096);
    lnlin_pair_kernel<<<NT / 8, 256>>>(H2hi, H2lo, l2s + 512, l2b + 512,
                                       lw + 512, lb + 2, fmask, out_energy, NT);
    add_emb_kernel<<<NT / 4, 256>>>(X, energy_tgt, ebins, eemb, out_ve, nullptr, nullptr, 0);
}

// round 11
// speedup vs baseline: 1.0003x; 1.0003x over previous
#include <cuda_runtime.h>
#include <cuda_bf16.h>
#include <math.h>
#include <stdint.h>

typedef __nv_bfloat16 bf16;

// B=32, L=512, T=4096, E=F=256, NB=256
// Output: concat(rounded_duration[B*L], pitch[B*T], energy[B*T], variance_embedding[B*T*E])

// -------- scratch (device globals) --------
__device__ float g_X   [33554432];   // [B,T,E] fp32 length-regulated x (exact path)
__device__ bf16  g_Xhi [33554432];   // hi/lo bf16 split of X
__device__ bf16  g_Xlo [33554432];
__device__ bf16  g_H1hi[33554432];   // hidden1 (post conv1+relu, then LN in-place)
__device__ bf16  g_H1lo[33554432];
__device__ bf16  g_H2hi[33554432];   // hidden2 (post conv2+relu)
__device__ bf16  g_H2lo[33554432];
__device__ float g_H1  [ 4194304];   // duration-path fp32 hiddens
__device__ float g_H2  [ 4194304];
__device__ bf16  g_Wsp [4][589824];  // split weights [n=256, k'=2304] = [Whi|Wlo|Whi]
__device__ int   g_cs  [16384];      // cumsum durations

// ==================================================================
// helpers
// ==================================================================
__device__ __forceinline__ uint32_t smem_u32(const void* p) {
    uint32_t a;
    asm("{ .reg .u64 t; cvta.to.shared.u64 t, %1; cvt.u32.u64 %0, t; }" : "=r"(a) : "l"(p));
    return a;
}
#define SWZ(o) ((o) ^ (((o) >> 3) & 0x70))

__device__ __forceinline__ void cpa16(uint32_t dst, const void* src, int pred) {
    int sz = pred ? 16 : 0;
    asm volatile("cp.async.cg.shared.global [%0], [%1], 16, %2;" :: "r"(dst), "l"(src), "r"(sz));
}
__device__ __forceinline__ uint32_t pack2(float lo, float hi) {
    uint32_t r;
    asm("cvt.rn.bf16x2.f32 %0, %1, %2;" : "=r"(r) : "f"(hi), "f"(lo));
    return r;
}
__device__ __forceinline__ float bf16_round(float v) {
    return __bfloat162float(__float2bfloat16(v));
}
__device__ __forceinline__ void ldm4(uint32_t r[4], uint32_t addr) {
    asm volatile("ldmatrix.sync.aligned.m8n8.x4.shared.b16 {%0,%1,%2,%3}, [%4];"
        : "=r"(r[0]), "=r"(r[1]), "=r"(r[2]), "=r"(r[3]) : "r"(addr));
}
__device__ __forceinline__ void mma16816(float c[4], const uint32_t a[4],
                                         uint32_t b0, uint32_t b1) {
    asm volatile("mma.sync.aligned.m16n8k16.row.col.f32.bf16.bf16.f32 "
        "{%0,%1,%2,%3}, {%4,%5,%6,%7}, {%8,%9}, {%0,%1,%2,%3};"
        : "+f"(c[0]), "+f"(c[1]), "+f"(c[2]), "+f"(c[3])
        : "r"(a[0]), "r"(a[1]), "r"(a[2]), "r"(a[3]), "r"(b0), "r"(b1));
}

// ==================================================================
// split-bf16 HMMA conv(k=3, 256->256) GEMM
// C = Ahi*Whi + Ahi*Wlo + Alo*Whi  (virtual K' = 2304, chunks of 64)
// W layout: [n=256, 2304] = [Whi(768) | Wlo(768) | Whi(768)]
// out: relu(C + bias) written as hi/lo bf16 pair.
// Tile 128(M) x 128(N), double-buffered cp.async, SW128 swizzle.
// ==================================================================
#define HSTG 32768            // per-stage: A 16KB + B 16KB

__global__ __launch_bounds__(256, 2)
void hmma_conv_sp(const bf16* __restrict__ Ahi, const bf16* __restrict__ Alo,
                  const bf16* __restrict__ W, const float* __restrict__ bias,
                  bf16* __restrict__ outhi, bf16* __restrict__ outlo, int S)
{
    extern __shared__ char sm[];
    uint32_t smb = smem_u32(sm);
    int tid  = threadIdx.x;
    int lane = tid & 31;
    int wid  = tid >> 5;
    int warp_m = (wid & 3) * 32;     // 4 warps over M
    int warp_n = (wid >> 2) * 64;    // 2 warps over N

    int m0 = blockIdx.x * 128;
    int b  = m0 / S;
    int t0 = m0 - b * S;
    int n0 = blockIdx.y * 128;

    auto load_chunk = [&](int ci, int stg) {
        int part = ci / 12;               // 0: Ahi*Whi, 1: Ahi*Wlo, 2: Alo*Whi
        int cc   = ci - part * 12;
        int k0in = cc * 64;
        int tap = k0in >> 8, c0 = k0in & 255;
        const bf16* Ab = ((part == 2) ? Alo : Ahi) + (size_t)b * S * 256;
        int k0w = ci * 64;
        uint32_t Asm = smb + stg * HSTG;
        uint32_t Bsm = Asm + 16384;
        #pragma unroll
        for (int j = 0; j < 4; j++) {                 // A: 128 rows x 128B
            int u = tid + 256 * j, row = u >> 3, c16 = u & 7;
            int tr = t0 + row + tap - 1;
            cpa16(Asm + SWZ(row * 128 + c16 * 16),
                  Ab + (size_t)tr * 256 + c0 + c16 * 8,
                  (unsigned)tr < (unsigned)S);
        }
        #pragma unroll
        for (int j = 0; j < 4; j++) {                 // B: 128 n-rows x 128B
            int u = tid + 256 * j, n = u >> 3, c16 = u & 7;
            cpa16(Bsm + SWZ(n * 128 + c16 * 16),
                  W + (size_t)(n0 + n) * 2304 + k0w + c16 * 8, 1);
        }
    };

    float acc[2][8][4];
    #pragma unroll
    for (int i = 0; i < 2; i++)
        #pragma unroll
        for (int j = 0; j < 8; j++)
            #pragma unroll
            for (int e = 0; e < 4; e++) acc[i][j][e] = 0.f;

    int g = lane >> 3;
    int arow = ((g & 1) << 3) + (lane & 7);
    int akk  = (g >> 1) << 3;
    int brow = ((g >> 1) << 3) + (lane & 7);
    int bkk  = (g & 1) << 3;

    load_chunk(0, 0);
    asm volatile("cp.async.commit_group;" ::: "memory");

    const int NC = 36;                    // 2304 / 64
    for (int i = 0; i < NC; i++) {
        if (i + 1 < NC) {
            load_chunk(i + 1, (i + 1) & 1);
            asm volatile("cp.async.commit_group;" ::: "memory");
            asm volatile("cp.async.wait_group 1;" ::: "memory");
        } else {
            asm volatile("cp.async.wait_group 0;" ::: "memory");
        }
        __syncthreads();

        uint32_t Asm = smb + (i & 1) * HSTG;
        uint32_t Bsm = Asm + 16384;
        #pragma unroll
        for (int ks = 0; ks < 4; ks++) {
            int kk = ks * 16;
            uint32_t a[2][4], bq[4][4];
            #pragma unroll
            for (int mt = 0; mt < 2; mt++) {
                int row = warp_m + mt * 16 + arow;
                ldm4(a[mt], Asm + SWZ(row * 128 + (kk + akk) * 2));
            }
            #pragma unroll
            for (int q = 0; q < 4; q++) {
                int n = warp_n + q * 16 + brow;
                ldm4(bq[q], Bsm + SWZ(n * 128 + (kk + bkk) * 2));
            }
            #pragma unroll
            for (int mt = 0; mt < 2; mt++)
                #pragma unroll
                for (int nb = 0; nb < 8; nb++) {
                    int q = nb >> 1, h = (nb & 1) * 2;
                    mma16816(acc[mt][nb], a[mt], bq[q][h], bq[q][h + 1]);
                }
        }
        __syncthreads();
    }

    // epilogue: bias + relu -> hi/lo bf16
    int colq = (lane & 3) * 2;
    int rowq = lane >> 2;
    #pragma unroll
    for (int mt = 0; mt < 2; mt++) {
        #pragma unroll
        for (int nb = 0; nb < 8; nb++) {
            int col = n0 + warp_n + nb * 8 + colq;
            float bs0 = bias[col], bs1 = bias[col + 1];
            int tokA = m0 + warp_m + mt * 16 + rowq;
            int tokB = tokA + 8;
            float v0 = fmaxf(acc[mt][nb][0] + bs0, 0.f);
            float v1 = fmaxf(acc[mt][nb][1] + bs1, 0.f);
            float v2 = fmaxf(acc[mt][nb][2] + bs0, 0.f);
            float v3 = fmaxf(acc[mt][nb][3] + bs1, 0.f);
            float h0 = bf16_round(v0), h1 = bf16_round(v1);
            float h2 = bf16_round(v2), h3 = bf16_round(v3);
            *(uint32_t*)(outhi + (size_t)tokA * 256 + col) = pack2(h0, h1);
            *(uint32_t*)(outhi + (size_t)tokB * 256 + col) = pack2(h2, h3);
            *(uint32_t*)(outlo + (size_t)tokA * 256 + col) = pack2(v0 - h0, v1 - h1);
            *(uint32_t*)(outlo + (size_t)tokB * 256 + col) = pack2(v2 - h2, v3 - h3);
        }
    }
}

// ==================================================================
// weight repack with hi/lo split:
// src w[pred][kk][c][n] f32 -> g_Wsp[mat][n*2304 + blk*768 + kk*256 + c]
// blk 0 = Whi, blk 1 = Wlo, blk 2 = Whi.  mats: 0=(w1,p1) 1=(w2,p1) 2=(w1,p2) 3=(w2,p2)
// ==================================================================
__global__ void repack_w_sp(const float* __restrict__ w1, const float* __restrict__ w2)
{
    int e = blockIdx.x * 256 + threadIdx.x;      // 4 * 589824 total
    int mat = e / 589824;
    int r   = e - mat * 589824;
    int n = r / 2304, kq = r - n * 2304;
    int blk = kq / 768, k = kq - blk * 768;
    int kk = k >> 8, c = k & 255;
    int p = (mat >> 1) + 1;
    const float* src = (mat & 1) ? w2 : w1;
    float w = src[(((size_t)p * 3 + kk) * 256 + c) * 256 + n];
    float hi = __bfloat162float(__float2bfloat16(w));
    g_Wsp[mat][r] = __float2bfloat16(blk == 1 ? (w - hi) : w);
}

// ==================================================================
// LayerNorm on hi/lo pair (warp per token), fp32 stats, hi/lo out
// ==================================================================
__global__ void ln_pair_kernel(bf16* __restrict__ hi, bf16* __restrict__ lo,
                               const float* __restrict__ sc, const float* __restrict__ bi,
                               int ntok)
{
    int w = threadIdx.x >> 5, lane = threadIdx.x & 31;
    int t = blockIdx.x * 8 + w;
    if (t >= ntok) return;
    size_t base = (size_t)t * 256 + lane * 8;
    uint4 rh = *(uint4*)(hi + base);
    uint4 rl = *(uint4*)(lo + base);
    uint32_t ph[4] = {rh.x, rh.y, rh.z, rh.w};
    uint32_t pl[4] = {rl.x, rl.y, rl.z, rl.w};
    float v[8];
    #pragma unroll
    for (int j = 0; j < 4; j++) {
        v[2*j]   = __bfloat162float(((bf16*)&ph[j])[0]) + __bfloat162float(((bf16*)&pl[j])[0]);
        v[2*j+1] = __bfloat162float(((bf16*)&ph[j])[1]) + __bfloat162float(((bf16*)&pl[j])[1]);
    }
    float s = 0.f, q = 0.f;
    #pragma unroll
    for (int j = 0; j < 8; j++) { s += v[j]; q += v[j] * v[j]; }
    #pragma unroll
    for (int o = 16; o; o >>= 1) {
        s += __shfl_xor_sync(0xffffffffu, s, o);
        q += __shfl_xor_sync(0xffffffffu, q, o);
    }
    float m = s * (1.f / 256.f);
    float r = rsqrtf(q * (1.f / 256.f) - m * m + 1e-5f);
    float4 s0 = *(const float4*)(sc + lane * 8);
    float4 s1 = *(const float4*)(sc + lane * 8 + 4);
    float4 b0 = *(const float4*)(bi + lane * 8);
    float4 b1 = *(const float4*)(bi + lane * 8 + 4);
    float sa[8] = {s0.x, s0.y, s0.z, s0.w, s1.x, s1.y, s1.z, s1.w};
    float ba[8] = {b0.x, b0.y, b0.z, b0.w, b1.x, b1.y, b1.z, b1.w};
    uint32_t oh[4], ol[4];
    #pragma unroll
    for (int j = 0; j < 4; j++) {
        float o0 = (v[2*j]   - m) * r * sa[2*j]   + ba[2*j];
        float o1 = (v[2*j+1] - m) * r * sa[2*j+1] + ba[2*j+1];
        float h0 = bf16_round(o0), h1 = bf16_round(o1);
        oh[j] = pack2(h0, h1);
        ol[j] = pack2(o0 - h0, o1 - h1);
    }
    *(uint4*)(hi + base) = make_uint4(oh[0], oh[1], oh[2], oh[3]);
    *(uint4*)(lo + base) = make_uint4(ol[0], ol[1], ol[2], ol[3]);
}

// ==================================================================
// fused LN + linear F->1 + mask on hi/lo pair (warp per token)
// ==================================================================
__global__ void lnlin_pair_kernel(const bf16* __restrict__ hi, const bf16* __restrict__ lo,
                                  const float* __restrict__ sc, const float* __restrict__ bi,
                                  const float* __restrict__ lw, const float* __restrict__ lb,
                                  const unsigned char* __restrict__ mask,
                                  float* __restrict__ out, int ntok)
{
    int w = threadIdx.x >> 5, lane = threadIdx.x & 31;
    int t = blockIdx.x * 8 + w;
    if (t >= ntok) return;
    size_t base = (size_t)t * 256 + lane * 8;
    uint4 rh = *(const uint4*)(hi + base);
    uint4 rl = *(const uint4*)(lo + base);
    uint32_t ph[4] = {rh.x, rh.y, rh.z, rh.w};
    uint32_t pl[4] = {rl.x, rl.y, rl.z, rl.w};
    float v[8];
    #pragma unroll
    for (int j = 0; j < 4; j++) {
        v[2*j]   = __bfloat162float(((bf16*)&ph[j])[0]) + __bfloat162float(((bf16*)&pl[j])[0]);
        v[2*j+1] = __bfloat162float(((bf16*)&ph[j])[1]) + __bfloat162float(((bf16*)&pl[j])[1]);
    }
    float s = 0.f, q = 0.f;
    #pragma unroll
    for (int j = 0; j < 8; j++) { s += v[j]; q += v[j] * v[j]; }
    #pragma unroll
    for (int o = 16; o; o >>= 1) {
        s += __shfl_xor_sync(0xffffffffu, s, o);
        q += __shfl_xor_sync(0xffffffffu, q, o);
    }
    float m = s * (1.f / 256.f);
    float r = rsqrtf(q * (1.f / 256.f) - m * m + 1e-5f);
    float4 s0 = *(const float4*)(sc + lane * 8);
    float4 s1 = *(const float4*)(sc + lane * 8 + 4);
    float4 b0 = *(const float4*)(bi + lane * 8);
    float4 b1 = *(const float4*)(bi + lane * 8 + 4);
    float4 w0 = *(const float4*)(lw + lane * 8);
    float4 w1 = *(const float4*)(lw + lane * 8 + 4);
    float sa[8] = {s0.x, s0.y, s0.z, s0.w, s1.x, s1.y, s1.z, s1.w};
    float ba[8] = {b0.x, b0.y, b0.z, b0.w, b1.x, b1.y, b1.z, b1.w};
    float wa[8] = {w0.x, w0.y, w0.z, w0.w, w1.x, w1.y, w1.z, w1.w};
    float d = 0.f;
    #pragma unroll
    for (int j = 0; j < 8; j++)
        d += ((v[j] - m) * r * sa[j] + ba[j]) * wa[j];
    #pragma unroll
    for (int o = 16; o; o >>= 1) d += __shfl_xor_sync(0xffffffffu, d, o);
    if (lane == 0) {
        float val = d + lb[0];
        if (mask[t]) val = 0.f;
        out[t] = val;
    }
}

// ==================================================================
// fp32 duration-path GEMM (exact, proven R1 code)
// ==================================================================
#define BM 128
#define BN 128
#define BK 16
#define NKT 48

__device__ __forceinline__ void cg_load(const float* __restrict__ inb,
                                        const float* __restrict__ W,
                                        int S, int t0, int n0, int kt, int tid,
                                        float4 av[2], float4 bv[2]) {
    int kc = kt * BK;
    int kk = kc >> 8, c0 = kc & 255;
    #pragma unroll
    for (int it = 0; it < 2; it++) {
        int idx = tid + it * 256;
        int m = idx >> 2, v = idx & 3;
        int t = t0 + m + kk - 1;
        float4 a = make_float4(0.f, 0.f, 0.f, 0.f);
        if (t >= 0 && t < S)
            a = *(const float4*)(inb + (size_t)t * 256 + c0 + v * 4);
        av[it] = a;
        int k = idx >> 5, nv = idx & 31;
        bv[it] = *(const float4*)(W + (size_t)(kc + k) * 256 + n0 + nv * 4);
    }
}
__device__ __forceinline__ void cg_store(float* As, float* Bs, int tid,
                                         const float4 av[2], const float4 bv[2]) {
    #pragma unroll
    for (int it = 0; it < 2; it++) {
        int idx = tid + it * 256;
        int m = idx >> 2, v = idx & 3;
        float vals[4] = {av[it].x, av[it].y, av[it].z, av[it].w};
        #pragma unroll
        for (int w = 0; w < 4; w++)
            *(float2*)&As[(v * 4 + w) * 256 + 2 * m] = make_float2(vals[w], vals[w]);
        int k = idx >> 5, nv = idx & 31;
        *(float4*)&Bs[k * BN + nv * 4] = bv[it];
    }
}
union U64F2 { unsigned long long u; float2 f; };
__device__ __forceinline__ void cg_compute(const float* As, const float* Bs,
                                           int ty, int tx, unsigned long long acc[8][4]) {
    #pragma unroll
    for (int k = 0; k < BK; k++) {
        const float* ar = As + k * 256 + 16 * ty;
        ulonglong2 q0 = *(const ulonglong2*)(ar + 0);
        ulonglong2 q1 = *(const ulonglong2*)(ar + 4);
        ulonglong2 q2 = *(const ulonglong2*)(ar + 8);
        ulonglong2 q3 = *(const ulonglong2*)(ar + 12);
        unsigned long long a8[8] = {q0.x, q0.y, q1.x, q1.y, q2.x, q2.y, q3.x, q3.y};
        const float* br = Bs + k * BN + 8 * tx;
        ulonglong2 p0 = *(const ulonglong2*)(br + 0);
        ulonglong2 p1 = *(const ulonglong2*)(br + 4);
        unsigned long long b4[4] = {p0.x, p0.y, p1.x, p1.y};
        #pragma unroll
        for (int i = 0; i < 8; i++)
            #pragma unroll
            for (int j = 0; j < 4; j++)
                asm("fma.rn.f32x2 %0, %1, %2, %0;" : "+l"(acc[i][j]) : "l"(a8[i]), "l"(b4[j]));
    }
}
__global__ __launch_bounds__(256) void conv_gemm_kernel(
    const float* __restrict__ in, const float* __restrict__ W,
    const float* __restrict__ bias, float* __restrict__ out, int S)
{
    __shared__ float sm[12288];
    float* As0 = sm;        float* Bs0 = sm + 4096;
    float* As1 = sm + 6144; float* Bs1 = sm + 10240;
    int tid = threadIdx.x;
    int m0 = blockIdx.x * BM;
    int b  = m0 / S;
    int t0 = m0 - b * S;
    int n0 = blockIdx.y * BN;
    int ty = tid >> 4, tx = tid & 15;
    const float* inb = in + (size_t)b * S * 256;
    unsigned long long acc[8][4];
    #pragma unroll
    for (int i = 0; i < 8; i++)
        #pragma unroll
        for (int j = 0; j < 4; j++) acc[i][j] = 0ull;
    float4 av[2], bv[2];
    cg_load(inb, W, S, t0, n0, 0, tid, av, bv);
    cg_store(As0, Bs0, tid, av, bv);
    __syncthreads();
    for (int kt = 0; kt < NKT; kt++) {
        const float* Ac = (kt & 1) ? As1 : As0;
        const float* Bc = (kt & 1) ? Bs1 : Bs0;
        float* An = (kt & 1) ? As0 : As1;
        float* Bn = (kt & 1) ? Bs0 : Bs1;
        if (kt + 1 < NKT) cg_load(inb, W, S, t0, n0, kt + 1, tid, av, bv);
        cg_compute(Ac, Bc, ty, tx, acc);
        if (kt + 1 < NKT) cg_store(An, Bn, tid, av, bv);
        __syncthreads();
    }
    const float* bp = bias + n0 + 8 * tx;
    float bs8[8];
    #pragma unroll
    for (int j = 0; j < 8; j++) bs8[j] = bp[j];
    #pragma unroll
    for (int i = 0; i < 8; i++) {
        int t = t0 + 8 * ty + i;
        float* orow = out + ((size_t)b * S + t) * 256 + n0 + 8 * tx;
        float o[8];
        #pragma unroll
        for (int j = 0; j < 4; j++) { U64F2 c; c.u = acc[i][j]; o[2*j] = c.f.x; o[2*j+1] = c.f.y; }
        #pragma unroll
        for (int j = 0; j < 8; j++) o[j] = fmaxf(o[j] + bs8[j], 0.f);
        *(float4*)(orow)     = make_float4(o[0], o[1], o[2], o[3]);
        *(float4*)(orow + 4) = make_float4(o[4], o[5], o[6], o[7]);
    }
}

__global__ void ln_kernel(float* __restrict__ h, const float* __restrict__ sc,
                          const float* __restrict__ bi, int ntok)
{
    int w = threadIdx.x >> 5, lane = threadIdx.x & 31;
    int t = blockIdx.x * 8 + w;
    if (t >= ntok) return;
    float* row = h + (size_t)t * 256;
    float4 v0 = *(float4*)(row + lane * 4);
    float4 v1 = *(float4*)(row + 128 + lane * 4);
    float s = v0.x + v0.y + v0.z + v0.w + v1.x + v1.y + v1.z + v1.w;
    float q = v0.x*v0.x + v0.y*v0.y + v0.z*v0.z + v0.w*v0.w
            + v1.x*v1.x + v1.y*v1.y + v1.z*v1.z + v1.w*v1.w;
    #pragma unroll
    for (int o = 16; o; o >>= 1) {
        s += __shfl_xor_sync(0xffffffffu, s, o);
        q += __shfl_xor_sync(0xffffffffu, q, o);
    }
    float m = s * (1.f / 256.f);
    float r = rsqrtf(q * (1.f / 256.f) - m * m + 1e-5f);
    int f0 = lane * 4, f1 = 128 + lane * 4;
    float4 s0 = *(const float4*)(sc + f0), s1 = *(const float4*)(sc + f1);
    float4 b0 = *(const float4*)(bi + f0), b1 = *(const float4*)(bi + f1);
    v0.x = (v0.x - m)*r*s0.x + b0.x;  v0.y = (v0.y - m)*r*s0.y + b0.y;
    v0.z = (v0.z - m)*r*s0.z + b0.z;  v0.w = (v0.w - m)*r*s0.w + b0.w;
    v1.x = (v1.x - m)*r*s1.x + b1.x;  v1.y = (v1.y - m)*r*s1.y + b1.y;
    v1.z = (v1.z - m)*r*s1.z + b1.z;  v1.w = (v1.w - m)*r*s1.w + b1.w;
    *(float4*)(row + lane * 4)       = v0;
    *(float4*)(row + 128 + lane * 4) = v1;
}

__global__ void dur_final_kernel(const float* __restrict__ h, const float* __restrict__ lw,
                                 const float* __restrict__ lb,
                                 const unsigned char* __restrict__ mask,
                                 const int* __restrict__ scale,
                                 float* __restrict__ out, int ntok)
{
    int w = threadIdx.x >> 5, lane = threadIdx.x & 31;
    int t = blockIdx.x * 8 + w;
    if (t >= ntok) return;
    const float* row = h + (size_t)t * 256;
    float4 v0 = *(const float4*)(row + lane * 4);
    float4 v1 = *(const float4*)(row + 128 + lane * 4);
    float4 w0 = *(const float4*)(lw + lane * 4);
    float4 w1 = *(const float4*)(lw + 128 + lane * 4);
    float d = v0.x*w0.x + v0.y*w0.y + v0.z*w0.z + v0.w*w0.w
            + v1.x*w1.x + v1.y*w1.y + v1.z*w1.z + v1.w*w1.w;
    #pragma unroll
    for (int o = 16; o; o >>= 1) d += __shfl_xor_sync(0xffffffffu, d, o);
    if (lane == 0) {
        float val = d + lb[0];
        if (mask[t]) val = 0.f;
        out[t] = fmaxf(rintf(expf(val) * (float)(*scale)), 0.f);
    }
}

// ==================================================================
// cumsum / length-regulate / embedding add
// ==================================================================
__global__ void cumsum_kernel(const int* __restrict__ dur, int* __restrict__ cs)
{
    __shared__ int s[512];
    int b = blockIdx.x, t = threadIdx.x;
    s[t] = dur[b * 512 + t];
    __syncthreads();
    for (int off = 1; off < 512; off <<= 1) {
        int v = (t >= off) ? s[t - off] : 0;
        __syncthreads();
        s[t] += v;
        __syncthreads();
    }
    cs[b * 512 + t] = s[t];
}

__global__ void length_reg_kernel(const float* __restrict__ hidden,
                                  const int* __restrict__ cs,
                                  float* __restrict__ X,
                                  bf16* __restrict__ Xhi, bf16* __restrict__ Xlo)
{
    __shared__ int scs[512];
    int tid = threadIdx.x;
    int base = blockIdx.x * 4;
    int b    = base >> 12;
    int tloc = base & 4095;
    const int* csb = cs + b * 512;
    scs[tid] = csb[tid];
    scs[tid + 256] = csb[tid + 256];
    __syncthreads();
    int g = tid >> 6, lane = tid & 63;
    int t = tloc + g;
    int lo = 0, hi = 512;
    while (lo < hi) { int mid = (lo + hi) >> 1; if (scs[mid] <= t) lo = mid + 1; else hi = mid; }
    int idx = lo < 512 ? lo : 511;
    bool valid = t < scs[511];
    float4 v = make_float4(0.f, 0.f, 0.f, 0.f);
    if (valid) v = *(const float4*)(hidden + ((size_t)b * 512 + idx) * 256 + lane * 4);
    size_t off = ((size_t)b * 4096 + t) * 256 + lane * 4;
    *(float4*)(X + off) = v;
    float hx = bf16_round(v.x), hy = bf16_round(v.y);
    float hz = bf16_round(v.z), hw = bf16_round(v.w);
    *(uint2*)(Xhi + off) = make_uint2(pack2(hx, hy), pack2(hz, hw));
    *(uint2*)(Xlo + off) = make_uint2(pack2(v.x - hx, v.y - hy), pack2(v.z - hz, v.w - hw));
}

__global__ void add_emb_kernel(const float* __restrict__ X, const float* __restrict__ tgt,
                               const float* __restrict__ bins, const float* __restrict__ emb,
                               float* __restrict__ outp,
                               bf16* __restrict__ Xhi, bf16* __restrict__ Xlo, int wxb)
{
    __shared__ float sb[256];
    int tid = threadIdx.x;
    sb[tid] = bins[tid];
    __syncthreads();
    int base = blockIdx.x * 4;
    int g = tid >> 6, lane = tid & 63;
    int t = base + g;
    float v = tgt[t];
    int lo = 0, hi = 256;
    while (lo < hi) { int mid = (lo + hi) >> 1; if (sb[mid] < v) lo = mid + 1; else hi = mid; }
    int idx = lo < 256 ? lo : 255;
    size_t off = (size_t)t * 256 + lane * 4;
    float4 a = *(const float4*)(X + off);
    float4 e = *(const float4*)(emb + (size_t)idx * 256 + lane * 4);
    a.x += e.x; a.y += e.y; a.z += e.z; a.w += e.w;
    *(float4*)(outp + off) = a;
    if (wxb) {
        float hx = bf16_round(a.x), hy = bf16_round(a.y);
        float hz = bf16_round(a.z), hw = bf16_round(a.w);
        *(uint2*)(Xhi + off) = make_uint2(pack2(hx, hy), pack2(hz, hw));
        *(uint2*)(Xlo + off) = make_uint2(pack2(a.x - hx, a.y - hy), pack2(a.z - hz, a.w - hw));
    }
}

// ==================================================================
// launch
// ==================================================================
extern "C" void kernel_launch(void* const* d_in, const int* in_sizes, int n_in,
                              void* d_out, int out_size)
{
    const float*         hidden    = (const float*)d_in[0];
    const unsigned char* mask      = (const unsigned char*)d_in[1];
    const unsigned char* fmask     = (const unsigned char*)d_in[2];
    const int*           dur_tgt   = (const int*)d_in[3];
    const float*         pitch_tgt = (const float*)d_in[4];
    const float*         energy_tgt= (const float*)d_in[5];
    const int*           dscale    = (const int*)d_in[6];
    const float*         w1        = (const float*)d_in[7];
    const float*         b1        = (const float*)d_in[8];
    const float*         l1s       = (const float*)d_in[9];
    const float*         l1b       = (const float*)d_in[10];
    const float*         w2        = (const float*)d_in[11];
    const float*         b2        = (const float*)d_in[12];
    const float*         l2s       = (const float*)d_in[13];
    const float*         l2b       = (const float*)d_in[14];
    const float*         lw        = (const float*)d_in[15];
    const float*         lb        = (const float*)d_in[16];
    const float*         pbins     = (const float*)d_in[17];
    const float*         pemb      = (const float*)d_in[18];
    const float*         ebins     = (const float*)d_in[19];
    const float*         eemb      = (const float*)d_in[20];

    cudaFuncSetAttribute(hmma_conv_sp, cudaFuncAttributeMaxDynamicSharedMemorySize, 2 * HSTG);

    float* X;  bf16 *Xhi, *Xlo, *H1hi, *H1lo, *H2hi, *H2lo, *Wsp;
    float *H1, *H2;  int* cs;
    cudaGetSymbolAddress((void**)&X,    g_X);
    cudaGetSymbolAddress((void**)&Xhi,  g_Xhi);
    cudaGetSymbolAddress((void**)&Xlo,  g_Xlo);
    cudaGetSymbolAddress((void**)&H1hi, g_H1hi);
    cudaGetSymbolAddress((void**)&H1lo, g_H1lo);
    cudaGetSymbolAddress((void**)&H2hi, g_H2hi);
    cudaGetSymbolAddress((void**)&H2lo, g_H2lo);
    cudaGetSymbolAddress((void**)&H1,   g_H1);
    cudaGetSymbolAddress((void**)&H2,   g_H2);
    cudaGetSymbolAddress((void**)&cs,   g_cs);
    cudaGetSymbolAddress((void**)&Wsp,  g_Wsp);

    float* out_rd     = (float*)d_out;
    float* out_pitch  = out_rd + 32 * 512;
    float* out_energy = out_pitch + 32 * 4096;
    float* out_ve     = out_energy + 32 * 4096;

    repack_w_sp<<<9216, 256>>>(w1, w2);

    // ---- duration predictor (fp32 exact; S=512, 16384 tokens) ----
    {
        dim3 g(16384 / 128, 2);
        conv_gemm_kernel<<<g, 256>>>(hidden, w1, b1, H1, 512);
        ln_kernel<<<16384 / 8, 256>>>(H1, l1s, l1b, 16384);
        conv_gemm_kernel<<<g, 256>>>(H1, w2, b2, H2, 512);
        ln_kernel<<<16384 / 8, 256>>>(H2, l2s, l2b, 16384);
        dur_final_kernel<<<16384 / 8, 256>>>(H2, lw, lb, mask, dscale, out_rd, 16384);
    }

    // ---- length regulate ----
    cumsum_kernel<<<32, 512>>>(dur_tgt, cs);
    length_reg_kernel<<<32 * 4096 / 4, 256>>>(hidden, cs, X, Xhi, Xlo);

    const int NT = 131072;
    dim3 gg(NT / 128, 2);

    // ---- pitch predictor (split-bf16 HMMA) ----
    hmma_conv_sp<<<gg, 256, 2 * HSTG>>>(Xhi,  Xlo,  Wsp + 0 * 589824, b1 + 256, H1hi, H1lo, 4096);
    ln_pair_kernel<<<NT / 8, 256>>>(H1hi, H1lo, l1s + 256, l1b + 256, NT);
    hmma_conv_sp<<<gg, 256, 2 * HSTG>>>(H1hi, H1lo, Wsp + 1 * 589824, b2 + 256, H2hi, H2lo, 4096);
    lnlin_pair_kernel<<<NT / 8, 256>>>(H2hi, H2lo, l2s + 256, l2b + 256,
                                       lw + 256, lb + 1, fmask, out_pitch, NT);
    add_emb_kernel<<<NT / 4, 256>>>(X, pitch_tgt, pbins, pemb, X, Xhi, Xlo, 1);

    // ---- energy predictor (split-bf16 HMMA) ----
    hmma_conv_sp<<<gg, 256, 2 * HSTG>>>(Xhi,  Xlo,  Wsp + 2 * 589824, b1 + 512, H1hi, H1lo, 4096);
    ln_pair_kernel<<<NT / 8, 256>>>(H1hi, H1lo, l1s + 512, l1b + 512, NT);
    hmma_conv_sp<<<gg, 256, 2 * HSTG>>>(H1hi, H1lo, Wsp + 3 * 589824, b2 + 512, H2hi, H2lo, 4096);
    lnlin_pair_kernel<<<NT / 8, 256>>>(H2hi, H2lo, l2s + 512, l2b + 512,
                                       lw + 512, lb + 2, fmask, out_energy, NT);
    add_emb_kernel<<<NT / 4, 256>>>(X, energy_tgt, ebins, eemb, out_ve, nullptr, nullptr, 0);
}

// round 12
// speedup vs baseline: 1.0258x; 1.0255x over previous
#include <cuda_runtime.h>
#include <cuda_bf16.h>
#include <math.h>
#include <stdint.h>

typedef __nv_bfloat16 bf16;

// B=32, L=512, T=4096, E=F=256, NB=256
// Output: concat(rounded_duration[B*L], pitch[B*T], energy[B*T], variance_embedding[B*T*E])

// -------- scratch (device globals) --------
__device__ float g_X   [33554432];   // [B,T,E] fp32 length-regulated x (exact path)
__device__ bf16  g_Xhi [33554432];   // hi/lo bf16 split of X
__device__ bf16  g_Xlo [33554432];
__device__ bf16  g_H1hi[33554432];   // hidden1 (post conv1+relu, then LN in-place)
__device__ bf16  g_H1lo[33554432];
__device__ bf16  g_H2hi[33554432];   // hidden2 (post conv2+relu)
__device__ bf16  g_H2lo[33554432];
__device__ float g_H1  [ 4194304];   // duration-path fp32 hiddens
__device__ float g_H2  [ 4194304];
__device__ bf16  g_Dh  [ 4194304];   // duration-path 3-way split A operands
__device__ bf16  g_Dm  [ 4194304];
__device__ bf16  g_Dl  [ 4194304];
__device__ bf16  g_Wsp [4][589824];  // big-path split weights [n=256, k'=2304] = [Whi|Wlo|Whi]
__device__ bf16  g_Wd  [2][1179648]; // duration 6-term weights [n=256, k'=4608]
__device__ int   g_cs  [16384];      // cumsum durations

// ==================================================================
// helpers
// ==================================================================
__device__ __forceinline__ uint32_t smem_u32(const void* p) {
    uint32_t a;
    asm("{ .reg .u64 t; cvta.to.shared.u64 t, %1; cvt.u32.u64 %0, t; }" : "=r"(a) : "l"(p));
    return a;
}
#define SWZ(o) ((o) ^ (((o) >> 3) & 0x70))

__device__ __forceinline__ void cpa16(uint32_t dst, const void* src, int pred) {
    int sz = pred ? 16 : 0;
    asm volatile("cp.async.cg.shared.global [%0], [%1], 16, %2;" :: "r"(dst), "l"(src), "r"(sz));
}
__device__ __forceinline__ uint32_t pack2(float lo, float hi) {
    uint32_t r;
    asm("cvt.rn.bf16x2.f32 %0, %1, %2;" : "=r"(r) : "f"(hi), "f"(lo));
    return r;
}
__device__ __forceinline__ float bf16_round(float v) {
    return __bfloat162float(__float2bfloat16(v));
}
__device__ __forceinline__ void ldm4(uint32_t r[4], uint32_t addr) {
    asm volatile("ldmatrix.sync.aligned.m8n8.x4.shared.b16 {%0,%1,%2,%3}, [%4];"
        : "=r"(r[0]), "=r"(r[1]), "=r"(r[2]), "=r"(r[3]) : "r"(addr));
}
__device__ __forceinline__ void mma16816(float c[4], const uint32_t a[4],
                                         uint32_t b0, uint32_t b1) {
    asm volatile("mma.sync.aligned.m16n8k16.row.col.f32.bf16.bf16.f32 "
        "{%0,%1,%2,%3}, {%4,%5,%6,%7}, {%8,%9}, {%0,%1,%2,%3};"
        : "+f"(c[0]), "+f"(c[1]), "+f"(c[2]), "+f"(c[3])
        : "r"(a[0]), "r"(a[1]), "r"(a[2]), "r"(a[3]), "r"(b0), "r"(b1));
}

// ==================================================================
// unified split-bf16 HMMA conv(k=3, 256->256) GEMM
//  TERMS=3: C = Ahi*Whi + Ahi*Wlo + Alo*Whi          (err ~1e-5)
//  TERMS=6: C = sum of all terms down to 2^-18 scale (err ~2e-8)
//  W layout [n=256, TERMS*768]; A-part select per 768-block.
//  Tile 256(M) x 128(N), 512 threads (8x2 warps, 32x64 microtile),
//  3-stage cp.async pipeline, SW128 swizzle.
//  MODE 0: out = relu(C+bias) as hi/lo bf16 pair.  MODE 1: out fp32.
// ==================================================================
#define HSTG3 49152           // per-stage: A 32KB + B 16KB

template<int TERMS, int MODE>
__global__ __launch_bounds__(512, 1)
void hmma_conv(const bf16* __restrict__ A0, const bf16* __restrict__ A1,
               const bf16* __restrict__ A2,
               const bf16* __restrict__ W, const float* __restrict__ bias,
               bf16* __restrict__ outhi, bf16* __restrict__ outlo,
               float* __restrict__ outf, int S)
{
    extern __shared__ char sm[];
    const int KP = TERMS * 768;
    const int NC = TERMS * 12;
    uint32_t smb = smem_u32(sm);
    int tid  = threadIdx.x;
    int lane = tid & 31;
    int wid  = tid >> 5;
    int warp_m = (wid & 7) * 32;     // 8 warps over M (256)
    int warp_n = (wid >> 3) * 64;    // 2 warps over N (128)

    int m0 = blockIdx.x * 256;
    int b  = m0 / S;
    int t0 = m0 - b * S;
    int n0 = blockIdx.y * 128;

    auto load_chunk = [&](int ci, int stg) {
        int part = ci / 12;
        int cc   = ci - part * 12;
        int k0in = cc * 64;
        int tap = k0in >> 8, c0 = k0in & 255;
        int s;
        if (TERMS == 3) s = (part >= 2) ? 1 : 0;          // {hi,hi,lo}
        else s = (part == 2 || part == 4) ? 1 : (part == 5 ? 2 : 0); // {hi,hi,mid,hi,mid,lo}
        const bf16* Ab = (s == 0 ? A0 : (s == 1 ? A1 : A2)) + (size_t)b * S * 256;
        int k0w = ci * 64;
        uint32_t Asm = smb + stg * HSTG3;
        uint32_t Bsm = Asm + 32768;
        #pragma unroll
        for (int j = 0; j < 4; j++) {                 // A: 256 rows x 128B
            int u = tid + 512 * j, row = u >> 3, c16 = u & 7;
            int tr = t0 + row + tap - 1;
            cpa16(Asm + SWZ(row * 128 + c16 * 16),
                  Ab + (size_t)tr * 256 + c0 + c16 * 8,
                  (unsigned)tr < (unsigned)S);
        }
        #pragma unroll
        for (int j = 0; j < 2; j++) {                 // B: 128 n-rows x 128B
            int u = tid + 512 * j, n = u >> 3, c16 = u & 7;
            cpa16(Bsm + SWZ(n * 128 + c16 * 16),
                  W + (size_t)(n0 + n) * KP + k0w + c16 * 8, 1);
        }
    };

    float acc[2][8][4];
    #pragma unroll
    for (int i = 0; i < 2; i++)
        #pragma unroll
        for (int j = 0; j < 8; j++)
            #pragma unroll
            for (int e = 0; e < 4; e++) acc[i][j][e] = 0.f;

    int g = lane >> 3;
    int arow = ((g & 1) << 3) + (lane & 7);
    int akk  = (g >> 1) << 3;
    int brow = ((g >> 1) << 3) + (lane & 7);
    int bkk  = (g & 1) << 3;

    load_chunk(0, 0);
    asm volatile("cp.async.commit_group;" ::: "memory");
    load_chunk(1, 1);
    asm volatile("cp.async.commit_group;" ::: "memory");

    for (int i = 0; i < NC; i++) {
        if (i + 1 < NC) asm volatile("cp.async.wait_group 1;" ::: "memory");
        else            asm volatile("cp.async.wait_group 0;" ::: "memory");
        __syncthreads();
        if (i + 2 < NC) {
            load_chunk(i + 2, (i + 2) % 3);
            asm volatile("cp.async.commit_group;" ::: "memory");
        }
        uint32_t Asm = smb + (i % 3) * HSTG3;
        uint32_t Bsm = Asm + 32768;
        #pragma unroll
        for (int ks = 0; ks < 4; ks++) {
            int kk = ks * 16;
            uint32_t a[2][4], bq[4][4];
            #pragma unroll
            for (int mt = 0; mt < 2; mt++) {
                int row = warp_m + mt * 16 + arow;
                ldm4(a[mt], Asm + SWZ(row * 128 + (kk + akk) * 2));
            }
            #pragma unroll
            for (int q = 0; q < 4; q++) {
                int n = warp_n + q * 16 + brow;
                ldm4(bq[q], Bsm + SWZ(n * 128 + (kk + bkk) * 2));
            }
            #pragma unroll
            for (int mt = 0; mt < 2; mt++)
                #pragma unroll
                for (int nb = 0; nb < 8; nb++) {
                    int q = nb >> 1, h = (nb & 1) * 2;
                    mma16816(acc[mt][nb], a[mt], bq[q][h], bq[q][h + 1]);
                }
        }
    }

    // epilogue: bias + relu
    int colq = (lane & 3) * 2;
    int rowq = lane >> 2;
    #pragma unroll
    for (int mt = 0; mt < 2; mt++) {
        #pragma unroll
        for (int nb = 0; nb < 8; nb++) {
            int col = n0 + warp_n + nb * 8 + colq;
            float bs0 = bias[col], bs1 = bias[col + 1];
            int tokA = m0 + warp_m + mt * 16 + rowq;
            int tokB = tokA + 8;
            float v0 = fmaxf(acc[mt][nb][0] + bs0, 0.f);
            float v1 = fmaxf(acc[mt][nb][1] + bs1, 0.f);
            float v2 = fmaxf(acc[mt][nb][2] + bs0, 0.f);
            float v3 = fmaxf(acc[mt][nb][3] + bs1, 0.f);
            if (MODE == 1) {
                *(float2*)(outf + (size_t)tokA * 256 + col) = make_float2(v0, v1);
                *(float2*)(outf + (size_t)tokB * 256 + col) = make_float2(v2, v3);
            } else {
                float h0 = bf16_round(v0), h1 = bf16_round(v1);
                float h2 = bf16_round(v2), h3 = bf16_round(v3);
                *(uint32_t*)(outhi + (size_t)tokA * 256 + col) = pack2(h0, h1);
                *(uint32_t*)(outhi + (size_t)tokB * 256 + col) = pack2(h2, h3);
                *(uint32_t*)(outlo + (size_t)tokA * 256 + col) = pack2(v0 - h0, v1 - h1);
                *(uint32_t*)(outlo + (size_t)tokB * 256 + col) = pack2(v2 - h2, v3 - h3);
            }
        }
    }
}

// ==================================================================
// weight repacks
// ==================================================================
// big path: [Whi|Wlo|Whi], mats 0=(w1,p1) 1=(w2,p1) 2=(w1,p2) 3=(w2,p2)
__global__ void repack_w_sp(const float* __restrict__ w1, const float* __restrict__ w2)
{
    int e = blockIdx.x * 256 + threadIdx.x;      // 4 * 589824
    int mat = e / 589824;
    int r   = e - mat * 589824;
    int n = r / 2304, kq = r - n * 2304;
    int blk = kq / 768, k = kq - blk * 768;
    int kk = k >> 8, c = k & 255;
    int p = (mat >> 1) + 1;
    const float* src = (mat & 1) ? w2 : w1;
    float w = src[(((size_t)p * 3 + kk) * 256 + c) * 256 + n];
    float hi = bf16_round(w);
    g_Wsp[mat][r] = __float2bfloat16(blk == 1 ? (w - hi) : w);
}

// duration path, 6-term: W blocks [Whi, Wmid, Whi, Wlo, Wmid, Whi], pred 0
__global__ void repack_w_d6(const float* __restrict__ w1, const float* __restrict__ w2)
{
    int e = blockIdx.x * 256 + threadIdx.x;      // 2 * 1179648
    int mat = e / 1179648;
    int r   = e - mat * 1179648;
    int n = r / 4608, kq = r - n * 4608;
    int blk = kq / 768, k = kq - blk * 768;
    int kk = k >> 8, c = k & 255;
    const float* src = mat ? w2 : w1;
    float w = src[(((size_t)kk) * 256 + c) * 256 + n];   // pred index 0
    float hi  = bf16_round(w);
    float mid = bf16_round(w - hi);
    int t = (blk == 1 || blk == 4) ? 1 : (blk == 3 ? 2 : 0);
    float v = (t == 0) ? w : ((t == 1) ? (w - hi) : (w - hi - mid));
    g_Wd[mat][r] = __float2bfloat16(v);
}

// 3-way split of an fp32 tensor into hi/mid/lo bf16
__global__ void split3_kernel(const float* __restrict__ src, bf16* __restrict__ ph,
                              bf16* __restrict__ pm, bf16* __restrict__ pl, int n4)
{
    int i = blockIdx.x * 256 + threadIdx.x;
    if (i >= n4) return;
    float4 v = ((const float4*)src)[i];
    float a[4] = {v.x, v.y, v.z, v.w};
    float h[4], m[4], l[4];
    #pragma unroll
    for (int j = 0; j < 4; j++) {
        h[j] = bf16_round(a[j]);
        m[j] = bf16_round(a[j] - h[j]);
        l[j] = a[j] - h[j] - m[j];
    }
    ((uint2*)ph)[i] = make_uint2(pack2(h[0], h[1]), pack2(h[2], h[3]));
    ((uint2*)pm)[i] = make_uint2(pack2(m[0], m[1]), pack2(m[2], m[3]));
    ((uint2*)pl)[i] = make_uint2(pack2(l[0], l[1]), pack2(l[2], l[3]));
}

// ==================================================================
// LayerNorm fp32 (duration path)
// ==================================================================
__global__ void ln_kernel(float* __restrict__ h, const float* __restrict__ sc,
                          const float* __restrict__ bi, int ntok)
{
    int w = threadIdx.x >> 5, lane = threadIdx.x & 31;
    int t = blockIdx.x * 8 + w;
    if (t >= ntok) return;
    float* row = h + (size_t)t * 256;
    float4 v0 = *(float4*)(row + lane * 4);
    float4 v1 = *(float4*)(row + 128 + lane * 4);
    float s = v0.x + v0.y + v0.z + v0.w + v1.x + v1.y + v1.z + v1.w;
    float q = v0.x*v0.x + v0.y*v0.y + v0.z*v0.z + v0.w*v0.w
            + v1.x*v1.x + v1.y*v1.y + v1.z*v1.z + v1.w*v1.w;
    #pragma unroll
    for (int o = 16; o; o >>= 1) {
        s += __shfl_xor_sync(0xffffffffu, s, o);
        q += __shfl_xor_sync(0xffffffffu, q, o);
    }
    float m = s * (1.f / 256.f);
    float r = rsqrtf(q * (1.f / 256.f) - m * m + 1e-5f);
    int f0 = lane * 4, f1 = 128 + lane * 4;
    float4 s0 = *(const float4*)(sc + f0), s1 = *(const float4*)(sc + f1);
    float4 b0 = *(const float4*)(bi + f0), b1 = *(const float4*)(bi + f1);
    v0.x = (v0.x - m)*r*s0.x + b0.x;  v0.y = (v0.y - m)*r*s0.y + b0.y;
    v0.z = (v0.z - m)*r*s0.z + b0.z;  v0.w = (v0.w - m)*r*s0.w + b0.w;
    v1.x = (v1.x - m)*r*s1.x + b1.x;  v1.y = (v1.y - m)*r*s1.y + b1.y;
    v1.z = (v1.z - m)*r*s1.z + b1.z;  v1.w = (v1.w - m)*r*s1.w + b1.w;
    *(float4*)(row + lane * 4)       = v0;
    *(float4*)(row + 128 + lane * 4) = v1;
}

__global__ void dur_final_kernel(const float* __restrict__ h, const float* __restrict__ lw,
                                 const float* __restrict__ lb,
                                 const unsigned char* __restrict__ mask,
                                 const int* __restrict__ scale,
                                 float* __restrict__ out, int ntok)
{
    int w = threadIdx.x >> 5, lane = threadIdx.x & 31;
    int t = blockIdx.x * 8 + w;
    if (t >= ntok) return;
    const float* row = h + (size_t)t * 256;
    float4 v0 = *(const float4*)(row + lane * 4);
    float4 v1 = *(const float4*)(row + 128 + lane * 4);
    float4 w0 = *(const float4*)(lw + lane * 4);
    float4 w1 = *(const float4*)(lw + 128 + lane * 4);
    float d = v0.x*w0.x + v0.y*w0.y + v0.z*w0.z + v0.w*w0.w
            + v1.x*w1.x + v1.y*w1.y + v1.z*w1.z + v1.w*w1.w;
    #pragma unroll
    for (int o = 16; o; o >>= 1) d += __shfl_xor_sync(0xffffffffu, d, o);
    if (lane == 0) {
        float val = d + lb[0];
        if (mask[t]) val = 0.f;
        out[t] = fmaxf(rintf(expf(val) * (float)(*scale)), 0.f);
    }
}

// ==================================================================
// LayerNorm on hi/lo pair (big path), fp32 stats, hi/lo out
// ==================================================================
__global__ void ln_pair_kernel(bf16* __restrict__ hi, bf16* __restrict__ lo,
                               const float* __restrict__ sc, const float* __restrict__ bi,
                               int ntok)
{
    int w = threadIdx.x >> 5, lane = threadIdx.x & 31;
    int t = blockIdx.x * 8 + w;
    if (t >= ntok) return;
    size_t base = (size_t)t * 256 + lane * 8;
    uint4 rh = *(uint4*)(hi + base);
    uint4 rl = *(uint4*)(lo + base);
    uint32_t ph[4] = {rh.x, rh.y, rh.z, rh.w};
    uint32_t pl[4] = {rl.x, rl.y, rl.z, rl.w};
    float v[8];
    #pragma unroll
    for (int j = 0; j < 4; j++) {
        v[2*j]   = __bfloat162float(((bf16*)&ph[j])[0]) + __bfloat162float(((bf16*)&pl[j])[0]);
        v[2*j+1] = __bfloat162float(((bf16*)&ph[j])[1]) + __bfloat162float(((bf16*)&pl[j])[1]);
    }
    float s = 0.f, q = 0.f;
    #pragma unroll
    for (int j = 0; j < 8; j++) { s += v[j]; q += v[j] * v[j]; }
    #pragma unroll
    for (int o = 16; o; o >>= 1) {
        s += __shfl_xor_sync(0xffffffffu, s, o);
        q += __shfl_xor_sync(0xffffffffu, q, o);
    }
    float m = s * (1.f / 256.f);
    float r = rsqrtf(q * (1.f / 256.f) - m * m + 1e-5f);
    float4 s0 = *(const float4*)(sc + lane * 8);
    float4 s1 = *(const float4*)(sc + lane * 8 + 4);
    float4 b0 = *(const float4*)(bi + lane * 8);
    float4 b1 = *(const float4*)(bi + lane * 8 + 4);
    float sa[8] = {s0.x, s0.y, s0.z, s0.w, s1.x, s1.y, s1.z, s1.w};
    float ba[8] = {b0.x, b0.y, b0.z, b0.w, b1.x, b1.y, b1.z, b1.w};
    uint32_t oh[4], ol[4];
    #pragma unroll
    for (int j = 0; j < 4; j++) {
        float o0 = (v[2*j]   - m) * r * sa[2*j]   + ba[2*j];
        float o1 = (v[2*j+1] - m) * r * sa[2*j+1] + ba[2*j+1];
        float h0 = bf16_round(o0), h1 = bf16_round(o1);
        oh[j] = pack2(h0, h1);
        ol[j] = pack2(o0 - h0, o1 - h1);
    }
    *(uint4*)(hi + base) = make_uint4(oh[0], oh[1], oh[2], oh[3]);
    *(uint4*)(lo + base) = make_uint4(ol[0], ol[1], ol[2], ol[3]);
}

// ==================================================================
// fused LN + linear F->1 + mask on hi/lo pair
// ==================================================================
__global__ void lnlin_pair_kernel(const bf16* __restrict__ hi, const bf16* __restrict__ lo,
                                  const float* __restrict__ sc, const float* __restrict__ bi,
                                  const float* __restrict__ lw, const float* __restrict__ lb,
                                  const unsigned char* __restrict__ mask,
                                  float* __restrict__ out, int ntok)
{
    int w = threadIdx.x >> 5, lane = threadIdx.x & 31;
    int t = blockIdx.x * 8 + w;
    if (t >= ntok) return;
    size_t base = (size_t)t * 256 + lane * 8;
    uint4 rh = *(const uint4*)(hi + base);
    uint4 rl = *(const uint4*)(lo + base);
    uint32_t ph[4] = {rh.x, rh.y, rh.z, rh.w};
    uint32_t pl[4] = {rl.x, rl.y, rl.z, rl.w};
    float v[8];
    #pragma unroll
    for (int j = 0; j < 4; j++) {
        v[2*j]   = __bfloat162float(((bf16*)&ph[j])[0]) + __bfloat162float(((bf16*)&pl[j])[0]);
        v[2*j+1] = __bfloat162float(((bf16*)&ph[j])[1]) + __bfloat162float(((bf16*)&pl[j])[1]);
    }
    float s = 0.f, q = 0.f;
    #pragma unroll
    for (int j = 0; j < 8; j++) { s += v[j]; q += v[j] * v[j]; }
    #pragma unroll
    for (int o = 16; o; o >>= 1) {
        s += __shfl_xor_sync(0xffffffffu, s, o);
        q += __shfl_xor_sync(0xffffffffu, q, o);
    }
    float m = s * (1.f / 256.f);
    float r = rsqrtf(q * (1.f / 256.f) - m * m + 1e-5f);
    float4 s0 = *(const float4*)(sc + lane * 8);
    float4 s1 = *(const float4*)(sc + lane * 8 + 4);
    float4 b0 = *(const float4*)(bi + lane * 8);
    float4 b1 = *(const float4*)(bi + lane * 8 + 4);
    float4 w0 = *(const float4*)(lw + lane * 8);
    float4 w1 = *(const float4*)(lw + lane * 8 + 4);
    float sa[8] = {s0.x, s0.y, s0.z, s0.w, s1.x, s1.y, s1.z, s1.w};
    float ba[8] = {b0.x, b0.y, b0.z, b0.w, b1.x, b1.y, b1.z, b1.w};
    float wa[8] = {w0.x, w0.y, w0.z, w0.w, w1.x, w1.y, w1.z, w1.w};
    float d = 0.f;
    #pragma unroll
    for (int j = 0; j < 8; j++)
        d += ((v[j] - m) * r * sa[j] + ba[j]) * wa[j];
    #pragma unroll
    for (int o = 16; o; o >>= 1) d += __shfl_xor_sync(0xffffffffu, d, o);
    if (lane == 0) {
        float val = d + lb[0];
        if (mask[t]) val = 0.f;
        out[t] = val;
    }
}

// ==================================================================
// cumsum / length-regulate / embedding add
// ==================================================================
__global__ void cumsum_kernel(const int* __restrict__ dur, int* __restrict__ cs)
{
    __shared__ int s[512];
    int b = blockIdx.x, t = threadIdx.x;
    s[t] = dur[b * 512 + t];
    __syncthreads();
    for (int off = 1; off < 512; off <<= 1) {
        int v = (t >= off) ? s[t - off] : 0;
        __syncthreads();
        s[t] += v;
        __syncthreads();
    }
    cs[b * 512 + t] = s[t];
}

__global__ void length_reg_kernel(const float* __restrict__ hidden,
                                  const int* __restrict__ cs,
                                  float* __restrict__ X,
                                  bf16* __restrict__ Xhi, bf16* __restrict__ Xlo)
{
    __shared__ int scs[512];
    int tid = threadIdx.x;
    int base = blockIdx.x * 4;
    int b    = base >> 12;
    int tloc = base & 4095;
    const int* csb = cs + b * 512;
    scs[tid] = csb[tid];
    scs[tid + 256] = csb[tid + 256];
    __syncthreads();
    int g = tid >> 6, lane = tid & 63;
    int t = tloc + g;
    int lo = 0, hi = 512;
    while (lo < hi) { int mid = (lo + hi) >> 1; if (scs[mid] <= t) lo = mid + 1; else hi = mid; }
    int idx = lo < 512 ? lo : 511;
    bool valid = t < scs[511];
    float4 v = make_float4(0.f, 0.f, 0.f, 0.f);
    if (valid) v = *(const float4*)(hidden + ((size_t)b * 512 + idx) * 256 + lane * 4);
    size_t off = ((size_t)b * 4096 + t) * 256 + lane * 4;
    *(float4*)(X + off) = v;
    float hx = bf16_round(v.x), hy = bf16_round(v.y);
    float hz = bf16_round(v.z), hw = bf16_round(v.w);
    *(uint2*)(Xhi + off) = make_uint2(pack2(hx, hy), pack2(hz, hw));
    *(uint2*)(Xlo + off) = make_uint2(pack2(v.x - hx, v.y - hy), pack2(v.z - hz, v.w - hw));
}

__global__ void add_emb_kernel(const float* __restrict__ X, const float* __restrict__ tgt,
                               const float* __restrict__ bins, const float* __restrict__ emb,
                               float* __restrict__ outp,
                               bf16* __restrict__ Xhi, bf16* __restrict__ Xlo, int wxb)
{
    __shared__ float sb[256];
    int tid = threadIdx.x;
    sb[tid] = bins[tid];
    __syncthreads();
    int base = blockIdx.x * 4;
    int g = tid >> 6, lane = tid & 63;
    int t = base + g;
    float v = tgt[t];
    int lo = 0, hi = 256;
    while (lo < hi) { int mid = (lo + hi) >> 1; if (sb[mid] < v) lo = mid + 1; else hi = mid; }
    int idx = lo < 256 ? lo : 255;
    size_t off = (size_t)t * 256 + lane * 4;
    float4 a = *(const float4*)(X + off);
    float4 e = *(const float4*)(emb + (size_t)idx * 256 + lane * 4);
    a.x += e.x; a.y += e.y; a.z += e.z; a.w += e.w;
    *(float4*)(outp + off) = a;
    if (wxb) {
        float hx = bf16_round(a.x), hy = bf16_round(a.y);
        float hz = bf16_round(a.z), hw = bf16_round(a.w);
        *(uint2*)(Xhi + off) = make_uint2(pack2(hx, hy), pack2(hz, hw));
        *(uint2*)(Xlo + off) = make_uint2(pack2(a.x - hx, a.y - hy), pack2(a.z - hz, a.w - hw));
    }
}

// ==================================================================
// launch
// ==================================================================
extern "C" void kernel_launch(void* const* d_in, const int* in_sizes, int n_in,
                              void* d_out, int out_size)
{
    const float*         hidden    = (const float*)d_in[0];
    const unsigned char* mask      = (const unsigned char*)d_in[1];
    const unsigned char* fmask     = (const unsigned char*)d_in[2];
    const int*           dur_tgt   = (const int*)d_in[3];
    const float*         pitch_tgt = (const float*)d_in[4];
    const float*         energy_tgt= (const float*)d_in[5];
    const int*           dscale    = (const int*)d_in[6];
    const float*         w1        = (const float*)d_in[7];
    const float*         b1        = (const float*)d_in[8];
    const float*         l1s       = (const float*)d_in[9];
    const float*         l1b       = (const float*)d_in[10];
    const float*         w2        = (const float*)d_in[11];
    const float*         b2        = (const float*)d_in[12];
    const float*         l2s       = (const float*)d_in[13];
    const float*         l2b       = (const float*)d_in[14];
    const float*         lw        = (const float*)d_in[15];
    const float*         lb        = (const float*)d_in[16];
    const float*         pbins     = (const float*)d_in[17];
    const float*         pemb      = (const float*)d_in[18];
    const float*         ebins     = (const float*)d_in[19];
    const float*         eemb      = (const float*)d_in[20];

    cudaFuncSetAttribute(hmma_conv<3,0>, cudaFuncAttributeMaxDynamicSharedMemorySize, 3 * HSTG3);
    cudaFuncSetAttribute(hmma_conv<6,1>, cudaFuncAttributeMaxDynamicSharedMemorySize, 3 * HSTG3);

    float* X;  bf16 *Xhi, *Xlo, *H1hi, *H1lo, *H2hi, *H2lo, *Wsp, *Wd, *Dh, *Dm, *Dl;
    float *H1, *H2;  int* cs;
    cudaGetSymbolAddress((void**)&X,    g_X);
    cudaGetSymbolAddress((void**)&Xhi,  g_Xhi);
    cudaGetSymbolAddress((void**)&Xlo,  g_Xlo);
    cudaGetSymbolAddress((void**)&H1hi, g_H1hi);
    cudaGetSymbolAddress((void**)&H1lo, g_H1lo);
    cudaGetSymbolAddress((void**)&H2hi, g_H2hi);
    cudaGetSymbolAddress((void**)&H2lo, g_H2lo);
    cudaGetSymbolAddress((void**)&H1,   g_H1);
    cudaGetSymbolAddress((void**)&H2,   g_H2);
    cudaGetSymbolAddress((void**)&Dh,   g_Dh);
    cudaGetSymbolAddress((void**)&Dm,   g_Dm);
    cudaGetSymbolAddress((void**)&Dl,   g_Dl);
    cudaGetSymbolAddress((void**)&cs,   g_cs);
    cudaGetSymbolAddress((void**)&Wsp,  g_Wsp);
    cudaGetSymbolAddress((void**)&Wd,   g_Wd);

    float* out_rd     = (float*)d_out;
    float* out_pitch  = out_rd + 32 * 512;
    float* out_energy = out_pitch + 32 * 4096;
    float* out_ve     = out_energy + 32 * 4096;

    repack_w_sp<<<9216, 256>>>(w1, w2);
    repack_w_d6<<<9216, 256>>>(w1, w2);

    // ---- duration predictor (6-term split HMMA, err ~2e-8; S=512, 16384 tokens) ----
    {
        dim3 gd(16384 / 256, 2);
        split3_kernel<<<4096, 256>>>(hidden, Dh, Dm, Dl, 1048576);
        hmma_conv<6,1><<<gd, 512, 3 * HSTG3>>>(Dh, Dm, Dl, Wd, b1, nullptr, nullptr, H1, 512);
        ln_kernel<<<16384 / 8, 256>>>(H1, l1s, l1b, 16384);
        split3_kernel<<<4096, 256>>>(H1, Dh, Dm, Dl, 1048576);
        hmma_conv<6,1><<<gd, 512, 3 * HSTG3>>>(Dh, Dm, Dl, Wd + 1179648, b2, nullptr, nullptr, H2, 512);
        ln_kernel<<<16384 / 8, 256>>>(H2, l2s, l2b, 16384);
        dur_final_kernel<<<16384 / 8, 256>>>(H2, lw, lb, mask, dscale, out_rd, 16384);
    }

    // ---- length regulate ----
    cumsum_kernel<<<32, 512>>>(dur_tgt, cs);
    length_reg_kernel<<<32 * 4096 / 4, 256>>>(hidden, cs, X, Xhi, Xlo);

    const int NT = 131072;
    dim3 gg(NT / 256, 2);

    // ---- pitch predictor (3-term split HMMA) ----
    hmma_conv<3,0><<<gg, 512, 3 * HSTG3>>>(Xhi,  Xlo,  nullptr, Wsp + 0 * 589824, b1 + 256,
                                           H1hi, H1lo, nullptr, 4096);
    ln_pair_kernel<<<NT / 8, 256>>>(H1hi, H1lo, l1s + 256, l1b + 256, NT);
    hmma_conv<3,0><<<gg, 512, 3 * HSTG3>>>(H1hi, H1lo, nullptr, Wsp + 1 * 589824, b2 + 256,
                                           H2hi, H2lo, nullptr, 4096);
    lnlin_pair_kernel<<<NT / 8, 256>>>(H2hi, H2lo, l2s + 256, l2b + 256,
                                       lw + 256, lb + 1, fmask, out_pitch, NT);
    add_emb_kernel<<<NT / 4, 256>>>(X, pitch_tgt, pbins, pemb, X, Xhi, Xlo, 1);

    // ---- energy predictor (3-term split HMMA) ----
    hmma_conv<3,0><<<gg, 512, 3 * HSTG3>>>(Xhi,  Xlo,  nullptr, Wsp + 2 * 589824, b1 + 512,
                                           H1hi, H1lo, nullptr, 4096);
    ln_pair_kernel<<<NT / 8, 256>>>(H1hi, H1lo, l1s + 512, l1b + 512, NT);
    hmma_conv<3,0><<<gg, 512, 3 * HSTG3>>>(H1hi, H1lo, nullptr, Wsp + 3 * 589824, b2 + 512,
                                           H2hi, H2lo, nullptr, 4096);
    lnlin_pair_kernel<<<NT / 8, 256>>>(H2hi, H2lo, l2s + 512, l2b + 512,
                                       lw + 512, lb + 2, fmask, out_energy, NT);
    add_emb_kernel<<<NT / 4, 256>>>(X, energy_tgt, ebins, eemb, out_ve, nullptr, nullptr, 0);
}

// round 13
// speedup vs baseline: 1.1978x; 1.1676x over previous
#include <cuda_runtime.h>
#include <cuda_fp16.h>
#include <math.h>
#include <stdint.h>

// B=32, L=512, T=4096, E=F=256, NB=256
// Output: concat(rounded_duration[B*L], pitch[B*T], energy[B*T], variance_embedding[B*T*E])

// -------- scratch (device globals) --------
__device__ float  g_X  [33554432];   // [B,T,E] fp32 length-regulated x (exact path)
__device__ __half g_Xh [33554432];   // hi/lo fp16 split of X
__device__ __half g_Xl [33554432];
__device__ __half g_H1h[33554432];   // hidden1 after fused conv1+relu+LN (split)
__device__ __half g_H1l[33554432];
__device__ __half g_Dh [ 4194304];   // duration input split
__device__ __half g_Dl [ 4194304];
__device__ __half g_W6 [6][589824];  // split weights [n=256, k'=2304] = [Whi|Wlo|Whi]
__device__ int    g_cs [16384];      // cumsum durations

// ==================================================================
// helpers
// ==================================================================
__device__ __forceinline__ uint32_t smem_u32(const void* p) {
    uint32_t a;
    asm("{ .reg .u64 t; cvta.to.shared.u64 t, %1; cvt.u32.u64 %0, t; }" : "=r"(a) : "l"(p));
    return a;
}
#define SWZ(o) ((o) ^ (((o) >> 3) & 0x70))

__device__ __forceinline__ void cpa16(uint32_t dst, const void* src, int pred) {
    int sz = pred ? 16 : 0;
    asm volatile("cp.async.cg.shared.global [%0], [%1], 16, %2;" :: "r"(dst), "l"(src), "r"(sz));
}
__device__ __forceinline__ uint32_t packh2(float a, float b) {
    __half2 h = __floats2half2_rn(a, b);
    return *(uint32_t*)&h;
}
__device__ __forceinline__ void ldm4(uint32_t r[4], uint32_t addr) {
    asm volatile("ldmatrix.sync.aligned.m8n8.x4.shared.b16 {%0,%1,%2,%3}, [%4];"
        : "=r"(r[0]), "=r"(r[1]), "=r"(r[2]), "=r"(r[3]) : "r"(addr));
}
__device__ __forceinline__ void mma16816(float c[4], const uint32_t a[4],
                                         uint32_t b0, uint32_t b1) {
    asm volatile("mma.sync.aligned.m16n8k16.row.col.f32.f16.f16.f32 "
        "{%0,%1,%2,%3}, {%4,%5,%6,%7}, {%8,%9}, {%0,%1,%2,%3};"
        : "+f"(c[0]), "+f"(c[1]), "+f"(c[2]), "+f"(c[3])
        : "r"(a[0]), "r"(a[1]), "r"(a[2]), "r"(a[3]), "r"(b0), "r"(b1));
}

// ==================================================================
// unified split-fp16 HMMA conv(k=3, 256->256) + fused epilogue
//   C = Ahi*Whi + Ahi*Wlo + Alo*Whi   (K' = 2304, 36 chunks of 64)
//   tile 128(M) x 256(N, full), 512 threads = 4(M) x 4(N) warps of 32x64
//   3-slot cp.async ring (48KB/slot), SW128 swizzle
//   epilogue: bias+relu+LayerNorm fused.
//   MODE 0: write LN output as hi/lo fp16 split.
//   MODE 1: LN -> dot(lw)+lb -> mask -> scalar out.
//   MODE 2: MODE1 + round(exp(val)*scale) (duration).
// ==================================================================
#define CHK   49152                  // per-chunk: A 16KB + B 32KB
#define PRMOF (3 * CHK)              // params after the ring
#define TSMEM (PRMOF + 4096)

template<int MODE>
__global__ __launch_bounds__(512, 1)
void hmma_conv(const __half* __restrict__ A0, const __half* __restrict__ A1,
               const __half* __restrict__ W, const float* __restrict__ bias,
               const float* __restrict__ lns, const float* __restrict__ lnb,
               const float* __restrict__ lw, const float* __restrict__ lb,
               const unsigned char* __restrict__ maskp, const int* __restrict__ scale,
               __half* __restrict__ outh, __half* __restrict__ outl,
               float* __restrict__ outs, int S)
{
    extern __shared__ char sm[];
    uint32_t smb = smem_u32(sm);
    int tid  = threadIdx.x;
    int lane = tid & 31;
    int wid  = tid >> 5;
    int warp_m = (wid & 3) * 32;     // 4 warps over M(128)
    int warp_n = (wid >> 2) * 64;    // 4 warps over N(256)
    int wn = wid >> 2;

    // params -> smem (region beyond ring)
    float* sbias = (float*)(sm + PRMOF);
    float* sls   = (float*)(sm + PRMOF + 1024);
    float* slnb  = (float*)(sm + PRMOF + 2048);
    float* slw   = (float*)(sm + PRMOF + 3072);
    if (tid < 256) {
        sbias[tid] = bias[tid];
        sls[tid]   = lns[tid];
        slnb[tid]  = lnb[tid];
        slw[tid]   = (MODE != 0) ? lw[tid] : 0.f;
    }

    int m0 = blockIdx.x * 128;
    int b  = m0 / S;
    int t0 = m0 - b * S;

    auto load_chunk = [&](int ci, int stg) {
        int part = ci / 12;                       // 0:Ahi*Whi 1:Ahi*Wlo 2:Alo*Whi
        int k0in = (ci - part * 12) * 64;
        int tap = k0in >> 8, c0 = k0in & 255;
        const __half* Ab = ((part == 2) ? A1 : A0) + (size_t)b * S * 256;
        int k0w = ci * 64;
        uint32_t Asm = smb + stg * CHK;
        uint32_t Bsm = Asm + 16384;
        #pragma unroll
        for (int j = 0; j < 2; j++) {             // A: 128 rows x 128B
            int u = tid + 512 * j, row = u >> 3, c16 = u & 7;
            int tr = t0 + row + tap - 1;
            cpa16(Asm + SWZ(row * 128 + c16 * 16),
                  Ab + (size_t)tr * 256 + c0 + c16 * 8,
                  (unsigned)tr < (unsigned)S);
        }
        #pragma unroll
        for (int j = 0; j < 4; j++) {             // B: 256 n-rows x 128B
            int u = tid + 512 * j, n = u >> 3, c16 = u & 7;
            cpa16(Bsm + SWZ(n * 128 + c16 * 16),
                  W + (size_t)n * 2304 + k0w + c16 * 8, 1);
        }
    };

    float acc[2][8][4];
    #pragma unroll
    for (int i = 0; i < 2; i++)
        #pragma unroll
        for (int j = 0; j < 8; j++)
            #pragma unroll
            for (int e = 0; e < 4; e++) acc[i][j][e] = 0.f;

    int g = lane >> 3;
    int arow = ((g & 1) << 3) + (lane & 7);
    int akk  = (g >> 1) << 3;
    int brow = ((g >> 1) << 3) + (lane & 7);
    int bkk  = (g & 1) << 3;

    load_chunk(0, 0);
    asm volatile("cp.async.commit_group;" ::: "memory");
    load_chunk(1, 1);
    asm volatile("cp.async.commit_group;" ::: "memory");

    const int NC = 36;
    for (int i = 0; i < NC; i++) {
        if (i + 1 < NC) asm volatile("cp.async.wait_group 1;" ::: "memory");
        else            asm volatile("cp.async.wait_group 0;" ::: "memory");
        __syncthreads();
        if (i + 2 < NC) {
            load_chunk(i + 2, (i + 2) % 3);
            asm volatile("cp.async.commit_group;" ::: "memory");
        }
        uint32_t Asm = smb + (i % 3) * CHK;
        uint32_t Bsm = Asm + 16384;
        #pragma unroll
        for (int ks = 0; ks < 4; ks++) {
            int kk = ks * 16;
            uint32_t a[2][4], bq[4][4];
            #pragma unroll
            for (int mt = 0; mt < 2; mt++) {
                int row = warp_m + mt * 16 + arow;
                ldm4(a[mt], Asm + SWZ(row * 128 + (kk + akk) * 2));
            }
            #pragma unroll
            for (int q = 0; q < 4; q++) {
                int n = warp_n + q * 16 + brow;
                ldm4(bq[q], Bsm + SWZ(n * 128 + (kk + bkk) * 2));
            }
            #pragma unroll
            for (int mt = 0; mt < 2; mt++)
                #pragma unroll
                for (int nb = 0; nb < 8; nb++) {
                    int q = nb >> 1, h = (nb & 1) * 2;
                    mma16816(acc[mt][nb], a[mt], bq[q][h], bq[q][h + 1]);
                }
        }
    }

    // ================= fused epilogue =================
    __syncthreads();                 // all compute done; ring smem reusable
    float* ps = (float*)sm;          // [128][4] row partial sums
    float* qs = (float*)(sm + 2048); // [128][4] row partial sumsq

    int colq = (lane & 3) * 2;
    int rowq = lane >> 2;

    // bias + relu in place
    #pragma unroll
    for (int mt = 0; mt < 2; mt++)
        #pragma unroll
        for (int nb = 0; nb < 8; nb++) {
            int col = warp_n + nb * 8 + colq;
            float b0 = sbias[col], b1 = sbias[col + 1];
            acc[mt][nb][0] = fmaxf(acc[mt][nb][0] + b0, 0.f);
            acc[mt][nb][1] = fmaxf(acc[mt][nb][1] + b1, 0.f);
            acc[mt][nb][2] = fmaxf(acc[mt][nb][2] + b0, 0.f);
            acc[mt][nb][3] = fmaxf(acc[mt][nb][3] + b1, 0.f);
        }

    // row sums / sumsq (quad shfl + cross-N-warp smem)
    #pragma unroll
    for (int mt = 0; mt < 2; mt++)
        #pragma unroll
        for (int h = 0; h < 2; h++) {
            float s = 0.f, q = 0.f;
            #pragma unroll
            for (int nb = 0; nb < 8; nb++) {
                float a = acc[mt][nb][2 * h], c = acc[mt][nb][2 * h + 1];
                s += a + c; q += a * a + c * c;
            }
            s += __shfl_xor_sync(0xffffffffu, s, 1);
            q += __shfl_xor_sync(0xffffffffu, q, 1);
            s += __shfl_xor_sync(0xffffffffu, s, 2);
            q += __shfl_xor_sync(0xffffffffu, q, 2);
            if ((lane & 3) == 0) {
                int r = warp_m + mt * 16 + rowq + h * 8;
                ps[r * 4 + wn] = s;
                qs[r * 4 + wn] = q;
            }
        }
    __syncthreads();

    float mean[2][2], rstd[2][2];
    #pragma unroll
    for (int mt = 0; mt < 2; mt++)
        #pragma unroll
        for (int h = 0; h < 2; h++) {
            int r = warp_m + mt * 16 + rowq + h * 8;
            float s = ps[r * 4] + ps[r * 4 + 1] + ps[r * 4 + 2] + ps[r * 4 + 3];
            float q = qs[r * 4] + qs[r * 4 + 1] + qs[r * 4 + 2] + qs[r * 4 + 3];
            float m = s * (1.f / 256.f);
            mean[mt][h] = m;
            rstd[mt][h] = rsqrtf(q * (1.f / 256.f) - m * m + 1e-5f);
        }

    if (MODE == 0) {
        // LN -> hi/lo fp16 split
        #pragma unroll
        for (int mt = 0; mt < 2; mt++)
            #pragma unroll
            for (int nb = 0; nb < 8; nb++) {
                int col = warp_n + nb * 8 + colq;
                float s0 = sls[col], s1 = sls[col + 1];
                float c0 = slnb[col], c1 = slnb[col + 1];
                #pragma unroll
                for (int h = 0; h < 2; h++) {
                    int tok = m0 + warp_m + mt * 16 + rowq + h * 8;
                    float o0 = (acc[mt][nb][2*h]   - mean[mt][h]) * rstd[mt][h] * s0 + c0;
                    float o1 = (acc[mt][nb][2*h+1] - mean[mt][h]) * rstd[mt][h] * s1 + c1;
                    __half h0 = __float2half_rn(o0);
                    __half h1 = __float2half_rn(o1);
                    __half2 hh = __halves2half2(h0, h1);
                    *(uint32_t*)(outh + (size_t)tok * 256 + col) = *(uint32_t*)&hh;
                    *(uint32_t*)(outl + (size_t)tok * 256 + col) =
                        packh2(o0 - __half2float(h0), o1 - __half2float(h1));
                }
            }
    } else {
        // LN -> dot with lw per row
        float dp[2][2] = {{0.f, 0.f}, {0.f, 0.f}};
        #pragma unroll
        for (int mt = 0; mt < 2; mt++)
            #pragma unroll
            for (int nb = 0; nb < 8; nb++) {
                int col = warp_n + nb * 8 + colq;
                float s0 = sls[col], s1 = sls[col + 1];
                float c0 = slnb[col], c1 = slnb[col + 1];
                float w0 = slw[col], w1 = slw[col + 1];
                #pragma unroll
                for (int h = 0; h < 2; h++) {
                    float o0 = (acc[mt][nb][2*h]   - mean[mt][h]) * rstd[mt][h] * s0 + c0;
                    float o1 = (acc[mt][nb][2*h+1] - mean[mt][h]) * rstd[mt][h] * s1 + c1;
                    dp[mt][h] += o0 * w0 + o1 * w1;
                }
            }
        __syncthreads();             // reuse ps for dot partials
        #pragma unroll
        for (int mt = 0; mt < 2; mt++)
            #pragma unroll
            for (int h = 0; h < 2; h++) {
                float d = dp[mt][h];
                d += __shfl_xor_sync(0xffffffffu, d, 1);
                d += __shfl_xor_sync(0xffffffffu, d, 2);
                if ((lane & 3) == 0) {
                    int r = warp_m + mt * 16 + rowq + h * 8;
                    ps[r * 4 + wn] = d;
                }
            }
        __syncthreads();
        if (tid < 128) {
            int r = tid;
            float d = ps[r * 4] + ps[r * 4 + 1] + ps[r * 4 + 2] + ps[r * 4 + 3] + lb[0];
            int tok = m0 + r;
            if (maskp[tok]) d = 0.f;
            if (MODE == 2)
                d = fmaxf(rintf(expf(d) * (float)(*scale)), 0.f);
            outs[tok] = d;
        }
    }
}

// ==================================================================
// weight repack: w[pred][kk][c][n] f32 -> g_W6[mat][n*2304 + blk*768 + kk*256 + c]
// blocks: 0=Whi 1=Wlo 2=Whi.  mats: 2*pred + (conv-1), preds 0,1,2
// ==================================================================
__global__ void repack_w6(const float* __restrict__ w1, const float* __restrict__ w2)
{
    int e = blockIdx.x * 256 + threadIdx.x;      // 6 * 589824
    if (e >= 6 * 589824) return;
    int mat = e / 589824;
    int r   = e - mat * 589824;
    int n = r / 2304, kq = r - n * 2304;
    int blk = kq / 768, k = kq - blk * 768;
    int kk = k >> 8, c = k & 255;
    int p = mat >> 1;
    const float* src = (mat & 1) ? w2 : w1;
    float w = src[(((size_t)p * 3 + kk) * 256 + c) * 256 + n];
    if (blk == 1) {
        float hi = __half2float(__float2half_rn(w));
        g_W6[mat][r] = __float2half_rn(w - hi);
    } else {
        g_W6[mat][r] = __float2half_rn(w);
    }
}

// fp32 -> fp16 hi/lo split
__global__ void split2_kernel(const float* __restrict__ src, __half* __restrict__ ph,
                              __half* __restrict__ pl, int n4)
{
    int i = blockIdx.x * 256 + threadIdx.x;
    if (i >= n4) return;
    float4 v = ((const float4*)src)[i];
    float a[4] = {v.x, v.y, v.z, v.w};
    uint32_t hh[2], ll[2];
    #pragma unroll
    for (int j = 0; j < 2; j++) {
        __half h0 = __float2half_rn(a[2*j]);
        __half h1 = __float2half_rn(a[2*j+1]);
        __half2 p = __halves2half2(h0, h1);
        hh[j] = *(uint32_t*)&p;
        ll[j] = packh2(a[2*j] - __half2float(h0), a[2*j+1] - __half2float(h1));
    }
    ((uint2*)ph)[i] = make_uint2(hh[0], hh[1]);
    ((uint2*)pl)[i] = make_uint2(ll[0], ll[1]);
}

// ==================================================================
// cumsum / length-regulate / embedding add
// ==================================================================
__global__ void cumsum_kernel(const int* __restrict__ dur, int* __restrict__ cs)
{
    __shared__ int s[512];
    int b = blockIdx.x, t = threadIdx.x;
    s[t] = dur[b * 512 + t];
    __syncthreads();
    for (int off = 1; off < 512; off <<= 1) {
        int v = (t >= off) ? s[t - off] : 0;
        __syncthreads();
        s[t] += v;
        __syncthreads();
    }
    cs[b * 512 + t] = s[t];
}

__global__ void length_reg_kernel(const float* __restrict__ hidden,
                                  const int* __restrict__ cs,
                                  float* __restrict__ X,
                                  __half* __restrict__ Xh, __half* __restrict__ Xl)
{
    __shared__ int scs[512];
    int tid = threadIdx.x;
    int base = blockIdx.x * 4;
    int b    = base >> 12;
    int tloc = base & 4095;
    const int* csb = cs + b * 512;
    scs[tid] = csb[tid];
    scs[tid + 256] = csb[tid + 256];
    __syncthreads();
    int g = tid >> 6, lane = tid & 63;
    int t = tloc + g;
    int lo = 0, hi = 512;
    while (lo < hi) { int mid = (lo + hi) >> 1; if (scs[mid] <= t) lo = mid + 1; else hi = mid; }
    int idx = lo < 512 ? lo : 511;
    bool valid = t < scs[511];
    float4 v = make_float4(0.f, 0.f, 0.f, 0.f);
    if (valid) v = *(const float4*)(hidden + ((size_t)b * 512 + idx) * 256 + lane * 4);
    size_t off = ((size_t)b * 4096 + t) * 256 + lane * 4;
    *(float4*)(X + off) = v;
    __half hx = __float2half_rn(v.x), hy = __float2half_rn(v.y);
    __half hz = __float2half_rn(v.z), hw = __float2half_rn(v.w);
    __half2 p0 = __halves2half2(hx, hy), p1 = __halves2half2(hz, hw);
    *(uint2*)(Xh + off) = make_uint2(*(uint32_t*)&p0, *(uint32_t*)&p1);
    *(uint2*)(Xl + off) = make_uint2(
        packh2(v.x - __half2float(hx), v.y - __half2float(hy)),
        packh2(v.z - __half2float(hz), v.w - __half2float(hw)));
}

__global__ void add_emb_kernel(const float* __restrict__ X, const float* __restrict__ tgt,
                               const float* __restrict__ bins, const float* __restrict__ emb,
                               float* __restrict__ outp,
                               __half* __restrict__ Xh, __half* __restrict__ Xl, int wxb)
{
    __shared__ float sb[256];
    int tid = threadIdx.x;
    sb[tid] = bins[tid];
    __syncthreads();
    int base = blockIdx.x * 4;
    int g = tid >> 6, lane = tid & 63;
    int t = base + g;
    float v = tgt[t];
    int lo = 0, hi = 256;
    while (lo < hi) { int mid = (lo + hi) >> 1; if (sb[mid] < v) lo = mid + 1; else hi = mid; }
    int idx = lo < 256 ? lo : 255;
    size_t off = (size_t)t * 256 + lane * 4;
    float4 a = *(const float4*)(X + off);
    float4 e = *(const float4*)(emb + (size_t)idx * 256 + lane * 4);
    a.x += e.x; a.y += e.y; a.z += e.z; a.w += e.w;
    *(float4*)(outp + off) = a;
    if (wxb) {
        __half hx = __float2half_rn(a.x), hy = __float2half_rn(a.y);
        __half hz = __float2half_rn(a.z), hw = __float2half_rn(a.w);
        __half2 p0 = __halves2half2(hx, hy), p1 = __halves2half2(hz, hw);
        *(uint2*)(Xh + off) = make_uint2(*(uint32_t*)&p0, *(uint32_t*)&p1);
        *(uint2*)(Xl + off) = make_uint2(
            packh2(a.x - __half2float(hx), a.y - __half2float(hy)),
            packh2(a.z - __half2float(hz), a.w - __half2float(hw)));
    }
}

// ==================================================================
// launch
// ==================================================================
extern "C" void kernel_launch(void* const* d_in, const int* in_sizes, int n_in,
                              void* d_out, int out_size)
{
    const float*         hidden    = (const float*)d_in[0];
    const unsigned char* mask      = (const unsigned char*)d_in[1];
    const unsigned char* fmask     = (const unsigned char*)d_in[2];
    const int*           dur_tgt   = (const int*)d_in[3];
    const float*         pitch_tgt = (const float*)d_in[4];
    const float*         energy_tgt= (const float*)d_in[5];
    const int*           dscale    = (const int*)d_in[6];
    const float*         w1        = (const float*)d_in[7];
    const float*         b1        = (const float*)d_in[8];
    const float*         l1s       = (const float*)d_in[9];
    const float*         l1b       = (const float*)d_in[10];
    const float*         w2        = (const float*)d_in[11];
    const float*         b2        = (const float*)d_in[12];
    const float*         l2s       = (const float*)d_in[13];
    const float*         l2b       = (const float*)d_in[14];
    const float*         lw        = (const float*)d_in[15];
    const float*         lb        = (const float*)d_in[16];
    const float*         pbins     = (const float*)d_in[17];
    const float*         pemb      = (const float*)d_in[18];
    const float*         ebins     = (const float*)d_in[19];
    const float*         eemb      = (const float*)d_in[20];

    cudaFuncSetAttribute(hmma_conv<0>, cudaFuncAttributeMaxDynamicSharedMemorySize, TSMEM);
    cudaFuncSetAttribute(hmma_conv<1>, cudaFuncAttributeMaxDynamicSharedMemorySize, TSMEM);
    cudaFuncSetAttribute(hmma_conv<2>, cudaFuncAttributeMaxDynamicSharedMemorySize, TSMEM);

    float* X;  __half *Xh, *Xl, *H1h, *H1l, *Dh, *Dl, *W6;  int* cs;
    cudaGetSymbolAddress((void**)&X,   g_X);
    cudaGetSymbolAddress((void**)&Xh,  g_Xh);
    cudaGetSymbolAddress((void**)&Xl,  g_Xl);
    cudaGetSymbolAddress((void**)&H1h, g_H1h);
    cudaGetSymbolAddress((void**)&H1l, g_H1l);
    cudaGetSymbolAddress((void**)&Dh,  g_Dh);
    cudaGetSymbolAddress((void**)&Dl,  g_Dl);
    cudaGetSymbolAddress((void**)&W6,  g_W6);
    cudaGetSymbolAddress((void**)&cs,  g_cs);

    float* out_rd     = (float*)d_out;
    float* out_pitch  = out_rd + 32 * 512;
    float* out_energy = out_pitch + 32 * 4096;
    float* out_ve     = out_energy + 32 * 4096;

    const size_t WS = 589824;

    repack_w6<<<13824, 256>>>(w1, w2);

    // ---- duration predictor (3-term fp16, err ~2e-7; 16384 tokens, S=512) ----
    split2_kernel<<<4096, 256>>>(hidden, Dh, Dl, 1048576);
    hmma_conv<0><<<128, 512, TSMEM>>>(Dh, Dl, W6 + 0 * WS, b1, l1s, l1b,
                                      nullptr, nullptr, nullptr, nullptr,
                                      H1h, H1l, nullptr, 512);
    hmma_conv<2><<<128, 512, TSMEM>>>(H1h, H1l, W6 + 1 * WS, b2, l2s, l2b,
                                      lw, lb, mask, dscale,
                                      nullptr, nullptr, out_rd, 512);

    // ---- length regulate ----
    cumsum_kernel<<<32, 512>>>(dur_tgt, cs);
    length_reg_kernel<<<32 * 4096 / 4, 256>>>(hidden, cs, X, Xh, Xl);

    const int NT = 131072;
    // ---- pitch predictor ----
    hmma_conv<0><<<NT / 128, 512, TSMEM>>>(Xh, Xl, W6 + 2 * WS, b1 + 256, l1s + 256, l1b + 256,
                                           nullptr, nullptr, nullptr, nullptr,
                                           H1h, H1l, nullptr, 4096);
    hmma_conv<1><<<NT / 128, 512, TSMEM>>>(H1h, H1l, W6 + 3 * WS, b2 + 256, l2s + 256, l2b + 256,
                                           lw + 256, lb + 1, fmask, nullptr,
                                           nullptr, nullptr, out_pitch, 4096);
    add_emb_kernel<<<NT / 4, 256>>>(X, pitch_tgt, pbins, pemb, X, Xh, Xl, 1);

    // ---- energy predictor ----
    hmma_conv<0><<<NT / 128, 512, TSMEM>>>(Xh, Xl, W6 + 4 * WS, b1 + 512, l1s + 512, l1b + 512,
                                           nullptr, nullptr, nullptr, nullptr,
                                           H1h, H1l, nullptr, 4096);
    hmma_conv<1><<<NT / 128, 512, TSMEM>>>(H1h, H1l, W6 + 5 * WS, b2 + 512, l2s + 512, l2b + 512,
                                           lw + 512, lb + 2, fmask, nullptr,
                                           nullptr, nullptr, out_energy, 4096);
    add_emb_kernel<<<NT / 4, 256>>>(X, energy_tgt, ebins, eemb, out_ve, nullptr, nullptr, 0);
}

// round 14
// speedup vs baseline: 1.2108x; 1.0109x over previous
#include <cuda_runtime.h>
#include <cuda_fp16.h>
#include <math.h>
#include <stdint.h>

// B=32, L=512, T=4096, E=F=256, NB=256
// Output: concat(rounded_duration[B*L], pitch[B*T], energy[B*T], variance_embedding[B*T*E])

// -------- scratch (device globals) --------
__device__ float  g_X  [33554432];   // [B,T,E] fp32 length-regulated x (exact path)
__device__ __half g_Xh [33554432];   // hi/lo fp16 split of X
__device__ __half g_Xl [33554432];
__device__ __half g_H1h[33554432];   // hidden1 after fused conv1+relu+LN (split)
__device__ __half g_H1l[33554432];
__device__ __half g_Dh [ 4194304];   // duration input split
__device__ __half g_Dl [ 4194304];
__device__ __half g_W6 [6][589824];  // split weights [n=256, k'=2304] = [Whi|Wlo|Whi]
__device__ int    g_cs [16384];      // cumsum durations

// ==================================================================
// helpers
// ==================================================================
__device__ __forceinline__ uint32_t smem_u32(const void* p) {
    uint32_t a;
    asm("{ .reg .u64 t; cvta.to.shared.u64 t, %1; cvt.u32.u64 %0, t; }" : "=r"(a) : "l"(p));
    return a;
}
#define SWZ(o) ((o) ^ (((o) >> 3) & 0x70))

__device__ __forceinline__ void cpa16(uint32_t dst, const void* src, int pred) {
    int sz = pred ? 16 : 0;
    asm volatile("cp.async.cg.shared.global [%0], [%1], 16, %2;" :: "r"(dst), "l"(src), "r"(sz));
}
__device__ __forceinline__ uint32_t packh2(float a, float b) {
    __half2 h = __floats2half2_rn(a, b);
    return *(uint32_t*)&h;
}
__device__ __forceinline__ void ldm4(uint32_t r[4], uint32_t addr) {
    asm volatile("ldmatrix.sync.aligned.m8n8.x4.shared.b16 {%0,%1,%2,%3}, [%4];"
        : "=r"(r[0]), "=r"(r[1]), "=r"(r[2]), "=r"(r[3]) : "r"(addr));
}
__device__ __forceinline__ void mma16816(float c[4], const uint32_t a[4],
                                         uint32_t b0, uint32_t b1) {
    asm volatile("mma.sync.aligned.m16n8k16.row.col.f32.f16.f16.f32 "
        "{%0,%1,%2,%3}, {%4,%5,%6,%7}, {%8,%9}, {%0,%1,%2,%3};"
        : "+f"(c[0]), "+f"(c[1]), "+f"(c[2]), "+f"(c[3])
        : "r"(a[0]), "r"(a[1]), "r"(a[2]), "r"(a[3]), "r"(b0), "r"(b1));
}

// ==================================================================
// split-fp16 HMMA conv(k=3, 256->256) + fused epilogue
//   C = Ahi*Whi + Ahi*Wlo + Alo*Whi   (K' = 2304, 36 chunks of 64)
//   CTA tile 128(M) x 256(N, full); 256 threads = 8 warps as 2(M) x 4(N)
//   warp tile 64x64 (4 m16 x 8 n8 = 32 mma/k-step, 8 ldm4/k-step = 32 FLOP/B)
//   3-slot cp.async ring (48KB/slot), SW128 swizzle
//   epilogue: bias+relu+LayerNorm fused.
//   MODE 0: LN out as hi/lo fp16 split. MODE 1: LN->dot(lw)+lb->mask->scalar.
//   MODE 2: MODE1 + round(exp(val)*scale) (duration).
// ==================================================================
#define CHK   49152                  // per-chunk: A 16KB + B 32KB
#define PRMOF (3 * CHK)              // params after the ring
#define TSMEM (PRMOF + 4096)

template<int MODE>
__global__ __launch_bounds__(256, 1)
void hmma_conv(const __half* __restrict__ A0, const __half* __restrict__ A1,
               const __half* __restrict__ W, const float* __restrict__ bias,
               const float* __restrict__ lns, const float* __restrict__ lnb,
               const float* __restrict__ lw, const float* __restrict__ lb,
               const unsigned char* __restrict__ maskp, const int* __restrict__ scale,
               __half* __restrict__ outh, __half* __restrict__ outl,
               float* __restrict__ outs, int S)
{
    extern __shared__ char sm[];
    uint32_t smb = smem_u32(sm);
    int tid  = threadIdx.x;
    int lane = tid & 31;
    int wid  = tid >> 5;
    int warp_m = (wid & 1) * 64;     // 2 warps over M(128)
    int warp_n = (wid >> 1) * 64;    // 4 warps over N(256)
    int wn = wid >> 1;

    // params -> smem (region beyond ring)
    float* sbias = (float*)(sm + PRMOF);
    float* sls   = (float*)(sm + PRMOF + 1024);
    float* slnb  = (float*)(sm + PRMOF + 2048);
    float* slw   = (float*)(sm + PRMOF + 3072);
    if (tid < 256) {
        sbias[tid] = bias[tid];
        sls[tid]   = lns[tid];
        slnb[tid]  = lnb[tid];
        slw[tid]   = (MODE != 0) ? lw[tid] : 0.f;
    }

    int m0 = blockIdx.x * 128;
    int b  = m0 / S;
    int t0 = m0 - b * S;

    auto load_chunk = [&](int ci, int stg) {
        int part = ci / 12;                       // 0:Ahi*Whi 1:Ahi*Wlo 2:Alo*Whi
        int k0in = (ci - part * 12) * 64;
        int tap = k0in >> 8, c0 = k0in & 255;
        const __half* Ab = ((part == 2) ? A1 : A0) + (size_t)b * S * 256;
        int k0w = ci * 64;
        uint32_t Asm = smb + stg * CHK;
        uint32_t Bsm = Asm + 16384;
        #pragma unroll
        for (int j = 0; j < 4; j++) {             // A: 128 rows x 128B
            int u = tid + 256 * j, row = u >> 3, c16 = u & 7;
            int tr = t0 + row + tap - 1;
            cpa16(Asm + SWZ(row * 128 + c16 * 16),
                  Ab + (size_t)tr * 256 + c0 + c16 * 8,
                  (unsigned)tr < (unsigned)S);
        }
        #pragma unroll
        for (int j = 0; j < 8; j++) {             // B: 256 n-rows x 128B
            int u = tid + 256 * j, n = u >> 3, c16 = u & 7;
            cpa16(Bsm + SWZ(n * 128 + c16 * 16),
                  W + (size_t)n * 2304 + k0w + c16 * 8, 1);
        }
    };

    float acc[4][8][4];
    #pragma unroll
    for (int i = 0; i < 4; i++)
        #pragma unroll
        for (int j = 0; j < 8; j++)
            #pragma unroll
            for (int e = 0; e < 4; e++) acc[i][j][e] = 0.f;

    int g = lane >> 3;
    int arow = ((g & 1) << 3) + (lane & 7);
    int akk  = (g >> 1) << 3;
    int brow = ((g >> 1) << 3) + (lane & 7);
    int bkk  = (g & 1) << 3;

    load_chunk(0, 0);
    asm volatile("cp.async.commit_group;" ::: "memory");
    load_chunk(1, 1);
    asm volatile("cp.async.commit_group;" ::: "memory");

    const int NC = 36;
    for (int i = 0; i < NC; i++) {
        if (i + 1 < NC) asm volatile("cp.async.wait_group 1;" ::: "memory");
        else            asm volatile("cp.async.wait_group 0;" ::: "memory");
        __syncthreads();
        if (i + 2 < NC) {
            load_chunk(i + 2, (i + 2) % 3);
            asm volatile("cp.async.commit_group;" ::: "memory");
        }
        uint32_t Asm = smb + (i % 3) * CHK;
        uint32_t Bsm = Asm + 16384;
        #pragma unroll
        for (int ks = 0; ks < 4; ks++) {
            int kk = ks * 16;
            uint32_t a[4][4], bq[4][4];
            #pragma unroll
            for (int mt = 0; mt < 4; mt++) {
                int row = warp_m + mt * 16 + arow;
                ldm4(a[mt], Asm + SWZ(row * 128 + (kk + akk) * 2));
            }
            #pragma unroll
            for (int q = 0; q < 4; q++) {
                int n = warp_n + q * 16 + brow;
                ldm4(bq[q], Bsm + SWZ(n * 128 + (kk + bkk) * 2));
            }
            #pragma unroll
            for (int mt = 0; mt < 4; mt++)
                #pragma unroll
                for (int nb = 0; nb < 8; nb++) {
                    int q = nb >> 1, h = (nb & 1) * 2;
                    mma16816(acc[mt][nb], a[mt], bq[q][h], bq[q][h + 1]);
                }
        }
    }

    // ================= fused epilogue =================
    __syncthreads();                 // all compute done; ring smem reusable
    float* ps = (float*)sm;          // [128][4] row partial sums
    float* qs = (float*)(sm + 2048); // [128][4] row partial sumsq

    int colq = (lane & 3) * 2;
    int rowq = lane >> 2;

    // bias + relu in place
    #pragma unroll
    for (int mt = 0; mt < 4; mt++)
        #pragma unroll
        for (int nb = 0; nb < 8; nb++) {
            int col = warp_n + nb * 8 + colq;
            float b0 = sbias[col], b1 = sbias[col + 1];
            acc[mt][nb][0] = fmaxf(acc[mt][nb][0] + b0, 0.f);
            acc[mt][nb][1] = fmaxf(acc[mt][nb][1] + b1, 0.f);
            acc[mt][nb][2] = fmaxf(acc[mt][nb][2] + b0, 0.f);
            acc[mt][nb][3] = fmaxf(acc[mt][nb][3] + b1, 0.f);
        }

    // row sums / sumsq (quad shfl + cross-N-warp smem)
    #pragma unroll
    for (int mt = 0; mt < 4; mt++)
        #pragma unroll
        for (int h = 0; h < 2; h++) {
            float s = 0.f, q = 0.f;
            #pragma unroll
            for (int nb = 0; nb < 8; nb++) {
                float a = acc[mt][nb][2 * h], c = acc[mt][nb][2 * h + 1];
                s += a + c; q += a * a + c * c;
            }
            s += __shfl_xor_sync(0xffffffffu, s, 1);
            q += __shfl_xor_sync(0xffffffffu, q, 1);
            s += __shfl_xor_sync(0xffffffffu, s, 2);
            q += __shfl_xor_sync(0xffffffffu, q, 2);
            if ((lane & 3) == 0) {
                int r = warp_m + mt * 16 + rowq + h * 8;
                ps[r * 4 + wn] = s;
                qs[r * 4 + wn] = q;
            }
        }
    __syncthreads();

    float mean[4][2], rstd[4][2];
    #pragma unroll
    for (int mt = 0; mt < 4; mt++)
        #pragma unroll
        for (int h = 0; h < 2; h++) {
            int r = warp_m + mt * 16 + rowq + h * 8;
            float s = ps[r * 4] + ps[r * 4 + 1] + ps[r * 4 + 2] + ps[r * 4 + 3];
            float q = qs[r * 4] + qs[r * 4 + 1] + qs[r * 4 + 2] + qs[r * 4 + 3];
            float m = s * (1.f / 256.f);
            mean[mt][h] = m;
            rstd[mt][h] = rsqrtf(q * (1.f / 256.f) - m * m + 1e-5f);
        }

    if (MODE == 0) {
        // LN -> hi/lo fp16 split
        #pragma unroll
        for (int mt = 0; mt < 4; mt++)
            #pragma unroll
            for (int nb = 0; nb < 8; nb++) {
                int col = warp_n + nb * 8 + colq;
                float s0 = sls[col], s1 = sls[col + 1];
                float c0 = slnb[col], c1 = slnb[col + 1];
                #pragma unroll
                for (int h = 0; h < 2; h++) {
                    int tok = m0 + warp_m + mt * 16 + rowq + h * 8;
                    float o0 = (acc[mt][nb][2*h]   - mean[mt][h]) * rstd[mt][h] * s0 + c0;
                    float o1 = (acc[mt][nb][2*h+1] - mean[mt][h]) * rstd[mt][h] * s1 + c1;
                    __half h0 = __float2half_rn(o0);
                    __half h1 = __float2half_rn(o1);
                    __half2 hh = __halves2half2(h0, h1);
                    *(uint32_t*)(outh + (size_t)tok * 256 + col) = *(uint32_t*)&hh;
                    *(uint32_t*)(outl + (size_t)tok * 256 + col) =
                        packh2(o0 - __half2float(h0), o1 - __half2float(h1));
                }
            }
    } else {
        // LN -> dot with lw per row
        float dp[4][2] = {{0.f, 0.f}, {0.f, 0.f}, {0.f, 0.f}, {0.f, 0.f}};
        #pragma unroll
        for (int mt = 0; mt < 4; mt++)
            #pragma unroll
            for (int nb = 0; nb < 8; nb++) {
                int col = warp_n + nb * 8 + colq;
                float s0 = sls[col], s1 = sls[col + 1];
                float c0 = slnb[col], c1 = slnb[col + 1];
                float w0 = slw[col], w1 = slw[col + 1];
                #pragma unroll
                for (int h = 0; h < 2; h++) {
                    float o0 = (acc[mt][nb][2*h]   - mean[mt][h]) * rstd[mt][h] * s0 + c0;
                    float o1 = (acc[mt][nb][2*h+1] - mean[mt][h]) * rstd[mt][h] * s1 + c1;
                    dp[mt][h] += o0 * w0 + o1 * w1;
                }
            }
        __syncthreads();             // reuse ps for dot partials
        #pragma unroll
        for (int mt = 0; mt < 4; mt++)
            #pragma unroll
            for (int h = 0; h < 2; h++) {
                float d = dp[mt][h];
                d += __shfl_xor_sync(0xffffffffu, d, 1);
                d += __shfl_xor_sync(0xffffffffu, d, 2);
                if ((lane & 3) == 0) {
                    int r = warp_m + mt * 16 + rowq + h * 8;
                    ps[r * 4 + wn] = d;
                }
            }
        __syncthreads();
        if (tid < 128) {
            int r = tid;
            float d = ps[r * 4] + ps[r * 4 + 1] + ps[r * 4 + 2] + ps[r * 4 + 3] + lb[0];
            int tok = m0 + r;
            if (maskp[tok]) d = 0.f;
            if (MODE == 2)
                d = fmaxf(rintf(expf(d) * (float)(*scale)), 0.f);
            outs[tok] = d;
        }
    }
}

// ==================================================================
// weight repack: w[pred][kk][c][n] f32 -> g_W6[mat][n*2304 + blk*768 + kk*256 + c]
// blocks: 0=Whi 1=Wlo 2=Whi.  mats: 2*pred + (conv-1), preds 0,1,2
// ==================================================================
__global__ void repack_w6(const float* __restrict__ w1, const float* __restrict__ w2)
{
    int e = blockIdx.x * 256 + threadIdx.x;      // 6 * 589824
    if (e >= 6 * 589824) return;
    int mat = e / 589824;
    int r   = e - mat * 589824;
    int n = r / 2304, kq = r - n * 2304;
    int blk = kq / 768, k = kq - blk * 768;
    int kk = k >> 8, c = k & 255;
    int p = mat >> 1;
    const float* src = (mat & 1) ? w2 : w1;
    float w = src[(((size_t)p * 3 + kk) * 256 + c) * 256 + n];
    if (blk == 1) {
        float hi = __half2float(__float2half_rn(w));
        g_W6[mat][r] = __float2half_rn(w - hi);
    } else {
        g_W6[mat][r] = __float2half_rn(w);
    }
}

// fp32 -> fp16 hi/lo split
__global__ void split2_kernel(const float* __restrict__ src, __half* __restrict__ ph,
                              __half* __restrict__ pl, int n4)
{
    int i = blockIdx.x * 256 + threadIdx.x;
    if (i >= n4) return;
    float4 v = ((const float4*)src)[i];
    float a[4] = {v.x, v.y, v.z, v.w};
    uint32_t hh[2], ll[2];
    #pragma unroll
    for (int j = 0; j < 2; j++) {
        __half h0 = __float2half_rn(a[2*j]);
        __half h1 = __float2half_rn(a[2*j+1]);
        __half2 p = __halves2half2(h0, h1);
        hh[j] = *(uint32_t*)&p;
        ll[j] = packh2(a[2*j] - __half2float(h0), a[2*j+1] - __half2float(h1));
    }
    ((uint2*)ph)[i] = make_uint2(hh[0], hh[1]);
    ((uint2*)pl)[i] = make_uint2(ll[0], ll[1]);
}

// ==================================================================
// cumsum / length-regulate / embedding add
// ==================================================================
__global__ void cumsum_kernel(const int* __restrict__ dur, int* __restrict__ cs)
{
    __shared__ int s[512];
    int b = blockIdx.x, t = threadIdx.x;
    s[t] = dur[b * 512 + t];
    __syncthreads();
    for (int off = 1; off < 512; off <<= 1) {
        int v = (t >= off) ? s[t - off] : 0;
        __syncthreads();
        s[t] += v;
        __syncthreads();
    }
    cs[b * 512 + t] = s[t];
}

__global__ void length_reg_kernel(const float* __restrict__ hidden,
                                  const int* __restrict__ cs,
                                  float* __restrict__ X,
                                  __half* __restrict__ Xh, __half* __restrict__ Xl)
{
    __shared__ int scs[512];
    int tid = threadIdx.x;
    int base = blockIdx.x * 4;
    int b    = base >> 12;
    int tloc = base & 4095;
    const int* csb = cs + b * 512;
    scs[tid] = csb[tid];
    scs[tid + 256] = csb[tid + 256];
    __syncthreads();
    int g = tid >> 6, lane = tid & 63;
    int t = tloc + g;
    int lo = 0, hi = 512;
    while (lo < hi) { int mid = (lo + hi) >> 1; if (scs[mid] <= t) lo = mid + 1; else hi = mid; }
    int idx = lo < 512 ? lo : 511;
    bool valid = t < scs[511];
    float4 v = make_float4(0.f, 0.f, 0.f, 0.f);
    if (valid) v = *(const float4*)(hidden + ((size_t)b * 512 + idx) * 256 + lane * 4);
    size_t off = ((size_t)b * 4096 + t) * 256 + lane * 4;
    *(float4*)(X + off) = v;
    __half hx = __float2half_rn(v.x), hy = __float2half_rn(v.y);
    __half hz = __float2half_rn(v.z), hw = __float2half_rn(v.w);
    __half2 p0 = __halves2half2(hx, hy), p1 = __halves2half2(hz, hw);
    *(uint2*)(Xh + off) = make_uint2(*(uint32_t*)&p0, *(uint32_t*)&p1);
    *(uint2*)(Xl + off) = make_uint2(
        packh2(v.x - __half2float(hx), v.y - __half2float(hy)),
        packh2(v.z - __half2float(hz), v.w - __half2float(hw)));
}

__global__ void add_emb_kernel(const float* __restrict__ X, const float* __restrict__ tgt,
                               const float* __restrict__ bins, const float* __restrict__ emb,
                               float* __restrict__ outp,
                               __half* __restrict__ Xh, __half* __restrict__ Xl, int wxb)
{
    __shared__ float sb[256];
    int tid = threadIdx.x;
    sb[tid] = bins[tid];
    __syncthreads();
    int base = blockIdx.x * 4;
    int g = tid >> 6, lane = tid & 63;
    int t = base + g;
    float v = tgt[t];
    int lo = 0, hi = 256;
    while (lo < hi) { int mid = (lo + hi) >> 1; if (sb[mid] < v) lo = mid + 1; else hi = mid; }
    int idx = lo < 256 ? lo : 255;
    size_t off = (size_t)t * 256 + lane * 4;
    float4 a = *(const float4*)(X + off);
    float4 e = *(const float4*)(emb + (size_t)idx * 256 + lane * 4);
    a.x += e.x; a.y += e.y; a.z += e.z; a.w += e.w;
    *(float4*)(outp + off) = a;
    if (wxb) {
        __half hx = __float2half_rn(a.x), hy = __float2half_rn(a.y);
        __half hz = __float2half_rn(a.z), hw = __float2half_rn(a.w);
        __half2 p0 = __halves2half2(hx, hy), p1 = __halves2half2(hz, hw);
        *(uint2*)(Xh + off) = make_uint2(*(uint32_t*)&p0, *(uint32_t*)&p1);
        *(uint2*)(Xl + off) = make_uint2(
            packh2(a.x - __half2float(hx), a.y - __half2float(hy)),
            packh2(a.z - __half2float(hz), a.w - __half2float(hw)));
    }
}

// ==================================================================
// launch
// ==================================================================
extern "C" void kernel_launch(void* const* d_in, const int* in_sizes, int n_in,
                              void* d_out, int out_size)
{
    const float*         hidden    = (const float*)d_in[0];
    const unsigned char* mask      = (const unsigned char*)d_in[1];
    const unsigned char* fmask     = (const unsigned char*)d_in[2];
    const int*           dur_tgt   = (const int*)d_in[3];
    const float*         pitch_tgt = (const float*)d_in[4];
    const float*         energy_tgt= (const float*)d_in[5];
    const int*           dscale    = (const int*)d_in[6];
    const float*         w1        = (const float*)d_in[7];
    const float*         b1        = (const float*)d_in[8];
    const float*         l1s       = (const float*)d_in[9];
    const float*         l1b       = (const float*)d_in[10];
    const float*         w2        = (const float*)d_in[11];
    const float*         b2        = (const float*)d_in[12];
    const float*         l2s       = (const float*)d_in[13];
    const float*         l2b       = (const float*)d_in[14];
    const float*         lw        = (const float*)d_in[15];
    const float*         lb        = (const float*)d_in[16];
    const float*         pbins     = (const float*)d_in[17];
    const float*         pemb      = (const float*)d_in[18];
    const float*         ebins     = (const float*)d_in[19];
    const float*         eemb      = (const float*)d_in[20];

    cudaFuncSetAttribute(hmma_conv<0>, cudaFuncAttributeMaxDynamicSharedMemorySize, TSMEM);
    cudaFuncSetAttribute(hmma_conv<1>, cudaFuncAttributeMaxDynamicSharedMemorySize, TSMEM);
    cudaFuncSetAttribute(hmma_conv<2>, cudaFuncAttributeMaxDynamicSharedMemorySize, TSMEM);

    float* X;  __half *Xh, *Xl, *H1h, *H1l, *Dh, *Dl, *W6;  int* cs;
    cudaGetSymbolAddress((void**)&X,   g_X);
    cudaGetSymbolAddress((void**)&Xh,  g_Xh);
    cudaGetSymbolAddress((void**)&Xl,  g_Xl);
    cudaGetSymbolAddress((void**)&H1h, g_H1h);
    cudaGetSymbolAddress((void**)&H1l, g_H1l);
    cudaGetSymbolAddress((void**)&Dh,  g_Dh);
    cudaGetSymbolAddress((void**)&Dl,  g_Dl);
    cudaGetSymbolAddress((void**)&W6,  g_W6);
    cudaGetSymbolAddress((void**)&cs,  g_cs);

    float* out_rd     = (float*)d_out;
    float* out_pitch  = out_rd + 32 * 512;
    float* out_energy = out_pitch + 32 * 4096;
    float* out_ve     = out_energy + 32 * 4096;

    const size_t WS = 589824;

    repack_w6<<<13824, 256>>>(w1, w2);

    // ---- duration predictor (3-term fp16, err ~2e-7; 16384 tokens, S=512) ----
    split2_kernel<<<4096, 256>>>(hidden, Dh, Dl, 1048576);
    hmma_conv<0><<<128, 256, TSMEM>>>(Dh, Dl, W6 + 0 * WS, b1, l1s, l1b,
                                      nullptr, nullptr, nullptr, nullptr,
                                      H1h, H1l, nullptr, 512);
    hmma_conv<2><<<128, 256, TSMEM>>>(H1h, H1l, W6 + 1 * WS, b2, l2s, l2b,
                                      lw, lb, mask, dscale,
                                      nullptr, nullptr, out_rd, 512);

    // ---- length regulate ----
    cumsum_kernel<<<32, 512>>>(dur_tgt, cs);
    length_reg_kernel<<<32 * 4096 / 4, 256>>>(hidden, cs, X, Xh, Xl);

    const int NT = 131072;
    // ---- pitch predictor ----
    hmma_conv<0><<<NT / 128, 256, TSMEM>>>(Xh, Xl, W6 + 2 * WS, b1 + 256, l1s + 256, l1b + 256,
                                           nullptr, nullptr, nullptr, nullptr,
                                           H1h, H1l, nullptr, 4096);
    hmma_conv<1><<<NT / 128, 256, TSMEM>>>(H1h, H1l, W6 + 3 * WS, b2 + 256, l2s + 256, l2b + 256,
                                           lw + 256, lb + 1, fmask, nullptr,
                                           nullptr, nullptr, out_pitch, 4096);
    add_emb_kernel<<<NT / 4, 256>>>(X, pitch_tgt, pbins, pemb, X, Xh, Xl, 1);

    // ---- energy predictor ----
    hmma_conv<0><<<NT / 128, 256, TSMEM>>>(Xh, Xl, W6 + 4 * WS, b1 + 512, l1s + 512, l1b + 512,
                                           nullptr, nullptr, nullptr, nullptr,
                                           H1h, H1l, nullptr, 4096);
    hmma_conv<1><<<NT / 128, 256, TSMEM>>>(H1h, H1l, W6 + 5 * WS, b2 + 512, l2s + 512, l2b + 512,
                                           lw + 512, lb + 2, fmask, nullptr,
                                           nullptr, nullptr, out_energy, 4096);
    add_emb_kernel<<<NT / 4, 256>>>(X, energy_tgt, ebins, eemb, out_ve, nullptr, nullptr, 0);
}

// round 15
// speedup vs baseline: 1.2264x; 1.0129x over previous
#include <cuda_runtime.h>
#include <cuda_fp16.h>
#include <math.h>
#include <stdint.h>

// B=32, L=512, T=4096, E=F=256, NB=256
// Output: concat(rounded_duration[B*L], pitch[B*T], energy[B*T], variance_embedding[B*T*E])

// -------- scratch (device globals) --------
__device__ float  g_X  [33554432];   // [B,T,E] fp32 length-regulated x (exact path)
__device__ __half g_Xh [33554432];   // hi/lo fp16 split of X
__device__ __half g_Xl [33554432];
__device__ __half g_H1h[33554432];   // hidden1 after fused conv1+relu+LN (split)
__device__ __half g_H1l[33554432];
__device__ __half g_Dh [ 4194304];   // duration input split
__device__ __half g_Dl [ 4194304];
__device__ __half g_W6 [6][589824];  // split weights [n=256, k'=2304] = [Whi|Wlo|Whi]
__device__ int    g_cs [16384];      // cumsum durations

// ==================================================================
// helpers
// ==================================================================
__device__ __forceinline__ uint32_t smem_u32(const void* p) {
    uint32_t a;
    asm("{ .reg .u64 t; cvta.to.shared.u64 t, %1; cvt.u32.u64 %0, t; }" : "=r"(a) : "l"(p));
    return a;
}
#define SWZ(o) ((o) ^ (((o) >> 3) & 0x70))

__device__ __forceinline__ void cpa16(uint32_t dst, const void* src, int pred) {
    int sz = pred ? 16 : 0;
    asm volatile("cp.async.cg.shared.global [%0], [%1], 16, %2;" :: "r"(dst), "l"(src), "r"(sz));
}
__device__ __forceinline__ uint32_t packh2(float a, float b) {
    __half2 h = __floats2half2_rn(a, b);
    return *(uint32_t*)&h;
}
__device__ __forceinline__ void ldm4(uint32_t r[4], uint32_t addr) {
    asm volatile("ldmatrix.sync.aligned.m8n8.x4.shared.b16 {%0,%1,%2,%3}, [%4];"
        : "=r"(r[0]), "=r"(r[1]), "=r"(r[2]), "=r"(r[3]) : "r"(addr));
}
__device__ __forceinline__ void mma16816(float c[4], const uint32_t a[4],
                                         uint32_t b0, uint32_t b1) {
    asm volatile("mma.sync.aligned.m16n8k16.row.col.f32.f16.f16.f32 "
        "{%0,%1,%2,%3}, {%4,%5,%6,%7}, {%8,%9}, {%0,%1,%2,%3};"
        : "+f"(c[0]), "+f"(c[1]), "+f"(c[2]), "+f"(c[3])
        : "r"(a[0]), "r"(a[1]), "r"(a[2]), "r"(a[3]), "r"(b0), "r"(b1));
}

// ==================================================================
// split-fp16 HMMA conv(k=3, 256->256) + fused epilogue
//   C = Ahi*Whi + Ahi*Wlo + Alo*Whi   (K' = 2304, 36 chunks of 64)
//   CTA tile 64(M) x 256(N, full); 256 threads = 8 N-warps, warp tile 64x32
//   acc = 64 regs/thread -> <=128 total -> 2 CTAs/SM (independent sync domains
//   hide each other's pipeline bubbles).
//   2-slot cp.async ring (40KB/slot: A 8KB + B 32KB), SW128 swizzle.
//   epilogue: bias+relu+LayerNorm fused.
//   MODE 0: LN out as hi/lo fp16 split. MODE 1: LN->dot(lw)+lb->mask->scalar.
//   MODE 2: MODE1 + round(exp(val)*scale) (duration).
// ==================================================================
#define CHK   40960                  // per-chunk: A 8KB + B 32KB
#define PRMOF (2 * CHK)              // params after the ring
#define TSMEM (PRMOF + 4096)

template<int MODE>
__global__ __launch_bounds__(256, 2)
void hmma_conv(const __half* __restrict__ A0, const __half* __restrict__ A1,
               const __half* __restrict__ W, const float* __restrict__ bias,
               const float* __restrict__ lns, const float* __restrict__ lnb,
               const float* __restrict__ lw, const float* __restrict__ lb,
               const unsigned char* __restrict__ maskp, const int* __restrict__ scale,
               __half* __restrict__ outh, __half* __restrict__ outl,
               float* __restrict__ outs, int S)
{
    extern __shared__ char sm[];
    uint32_t smb = smem_u32(sm);
    int tid  = threadIdx.x;
    int lane = tid & 31;
    int wid  = tid >> 5;
    int warp_n = wid * 32;           // 8 warps over N(256); all warps span M(64)

    // params -> smem (region beyond ring)
    float* sbias = (float*)(sm + PRMOF);
    float* sls   = (float*)(sm + PRMOF + 1024);
    float* slnb  = (float*)(sm + PRMOF + 2048);
    float* slw   = (float*)(sm + PRMOF + 3072);
    sbias[tid] = bias[tid];
    sls[tid]   = lns[tid];
    slnb[tid]  = lnb[tid];
    slw[tid]   = (MODE != 0) ? lw[tid] : 0.f;

    int m0 = blockIdx.x * 64;
    int b  = m0 / S;
    int t0 = m0 - b * S;

    auto load_chunk = [&](int ci, int stg) {
        int part = ci / 12;                       // 0:Ahi*Whi 1:Ahi*Wlo 2:Alo*Whi
        int k0in = (ci - part * 12) * 64;
        int tap = k0in >> 8, c0 = k0in & 255;
        const __half* Ab = ((part == 2) ? A1 : A0) + (size_t)b * S * 256;
        int k0w = ci * 64;
        uint32_t Asm = smb + stg * CHK;
        uint32_t Bsm = Asm + 8192;
        #pragma unroll
        for (int j = 0; j < 2; j++) {             // A: 64 rows x 128B
            int u = tid + 256 * j, row = u >> 3, c16 = u & 7;
            int tr = t0 + row + tap - 1;
            cpa16(Asm + SWZ(row * 128 + c16 * 16),
                  Ab + (size_t)tr * 256 + c0 + c16 * 8,
                  (unsigned)tr < (unsigned)S);
        }
        #pragma unroll
        for (int j = 0; j < 8; j++) {             // B: 256 n-rows x 128B
            int u = tid + 256 * j, n = u >> 3, c16 = u & 7;
            cpa16(Bsm + SWZ(n * 128 + c16 * 16),
                  W + (size_t)n * 2304 + k0w + c16 * 8, 1);
        }
    };

    float acc[4][4][4];
    #pragma unroll
    for (int i = 0; i < 4; i++)
        #pragma unroll
        for (int j = 0; j < 4; j++)
            #pragma unroll
            for (int e = 0; e < 4; e++) acc[i][j][e] = 0.f;

    int g = lane >> 3;
    int arow = ((g & 1) << 3) + (lane & 7);
    int akk  = (g >> 1) << 3;
    int brow = ((g >> 1) << 3) + (lane & 7);
    int bkk  = (g & 1) << 3;

    load_chunk(0, 0);
    asm volatile("cp.async.commit_group;" ::: "memory");

    const int NC = 36;
    for (int i = 0; i < NC; i++) {
        asm volatile("cp.async.wait_group 0;" ::: "memory");
        __syncthreads();
        if (i + 1 < NC) {
            load_chunk(i + 1, (i + 1) & 1);
            asm volatile("cp.async.commit_group;" ::: "memory");
        }
        uint32_t Asm = smb + (i & 1) * CHK;
        uint32_t Bsm = Asm + 8192;
        #pragma unroll
        for (int ks = 0; ks < 4; ks++) {
            int kk = ks * 16;
            uint32_t a[4][4], bq[2][4];
            #pragma unroll
            for (int mt = 0; mt < 4; mt++) {
                int row = mt * 16 + arow;
                ldm4(a[mt], Asm + SWZ(row * 128 + (kk + akk) * 2));
            }
            #pragma unroll
            for (int q = 0; q < 2; q++) {
                int n = warp_n + q * 16 + brow;
                ldm4(bq[q], Bsm + SWZ(n * 128 + (kk + bkk) * 2));
            }
            #pragma unroll
            for (int mt = 0; mt < 4; mt++)
                #pragma unroll
                for (int nb = 0; nb < 4; nb++) {
                    int q = nb >> 1, h = (nb & 1) * 2;
                    mma16816(acc[mt][nb], a[mt], bq[q][h], bq[q][h + 1]);
                }
        }
    }

    // ================= fused epilogue =================
    __syncthreads();                 // all compute done; ring smem reusable
    float* ps = (float*)sm;          // [64][8] row partial sums
    float* qs = (float*)(sm + 2048); // [64][8] row partial sumsq

    int colq = (lane & 3) * 2;
    int rowq = lane >> 2;

    // bias + relu in place
    #pragma unroll
    for (int mt = 0; mt < 4; mt++)
        #pragma unroll
        for (int nb = 0; nb < 4; nb++) {
            int col = warp_n + nb * 8 + colq;
            float b0 = sbias[col], b1 = sbias[col + 1];
            acc[mt][nb][0] = fmaxf(acc[mt][nb][0] + b0, 0.f);
            acc[mt][nb][1] = fmaxf(acc[mt][nb][1] + b1, 0.f);
            acc[mt][nb][2] = fmaxf(acc[mt][nb][2] + b0, 0.f);
            acc[mt][nb][3] = fmaxf(acc[mt][nb][3] + b1, 0.f);
        }

    // row sums / sumsq (quad shfl + cross-N-warp smem)
    #pragma unroll
    for (int mt = 0; mt < 4; mt++)
        #pragma unroll
        for (int h = 0; h < 2; h++) {
            float s = 0.f, q = 0.f;
            #pragma unroll
            for (int nb = 0; nb < 4; nb++) {
                float a = acc[mt][nb][2 * h], c = acc[mt][nb][2 * h + 1];
                s += a + c; q += a * a + c * c;
            }
            s += __shfl_xor_sync(0xffffffffu, s, 1);
            q += __shfl_xor_sync(0xffffffffu, q, 1);
            s += __shfl_xor_sync(0xffffffffu, s, 2);
            q += __shfl_xor_sync(0xffffffffu, q, 2);
            if ((lane & 3) == 0) {
                int r = mt * 16 + rowq + h * 8;
                ps[r * 8 + wid] = s;
                qs[r * 8 + wid] = q;
            }
        }
    __syncthreads();

    float mean[4][2], rstd[4][2];
    #pragma unroll
    for (int mt = 0; mt < 4; mt++)
        #pragma unroll
        for (int h = 0; h < 2; h++) {
            int r = mt * 16 + rowq + h * 8;
            float s = 0.f, q = 0.f;
            #pragma unroll
            for (int k = 0; k < 8; k++) { s += ps[r * 8 + k]; q += qs[r * 8 + k]; }
            float m = s * (1.f / 256.f);
            mean[mt][h] = m;
            rstd[mt][h] = rsqrtf(q * (1.f / 256.f) - m * m + 1e-5f);
        }

    if (MODE == 0) {
        // LN -> hi/lo fp16 split
        #pragma unroll
        for (int mt = 0; mt < 4; mt++)
            #pragma unroll
            for (int nb = 0; nb < 4; nb++) {
                int col = warp_n + nb * 8 + colq;
                float s0 = sls[col], s1 = sls[col + 1];
                float c0 = slnb[col], c1 = slnb[col + 1];
                #pragma unroll
                for (int h = 0; h < 2; h++) {
                    int tok = m0 + mt * 16 + rowq + h * 8;
                    float o0 = (acc[mt][nb][2*h]   - mean[mt][h]) * rstd[mt][h] * s0 + c0;
                    float o1 = (acc[mt][nb][2*h+1] - mean[mt][h]) * rstd[mt][h] * s1 + c1;
                    __half h0 = __float2half_rn(o0);
                    __half h1 = __float2half_rn(o1);
                    __half2 hh = __halves2half2(h0, h1);
                    *(uint32_t*)(outh + (size_t)tok * 256 + col) = *(uint32_t*)&hh;
                    *(uint32_t*)(outl + (size_t)tok * 256 + col) =
                        packh2(o0 - __half2float(h0), o1 - __half2float(h1));
                }
            }
    } else {
        // LN -> dot with lw per row
        float dp[4][2] = {{0.f, 0.f}, {0.f, 0.f}, {0.f, 0.f}, {0.f, 0.f}};
        #pragma unroll
        for (int mt = 0; mt < 4; mt++)
            #pragma unroll
            for (int nb = 0; nb < 4; nb++) {
                int col = warp_n + nb * 8 + colq;
                float s0 = sls[col], s1 = sls[col + 1];
                float c0 = slnb[col], c1 = slnb[col + 1];
                float w0 = slw[col], w1 = slw[col + 1];
                #pragma unroll
                for (int h = 0; h < 2; h++) {
                    float o0 = (acc[mt][nb][2*h]   - mean[mt][h]) * rstd[mt][h] * s0 + c0;
                    float o1 = (acc[mt][nb][2*h+1] - mean[mt][h]) * rstd[mt][h] * s1 + c1;
                    dp[mt][h] += o0 * w0 + o1 * w1;
                }
            }
        __syncthreads();             // reuse ps for dot partials
        #pragma unroll
        for (int mt = 0; mt < 4; mt++)
            #pragma unroll
            for (int h = 0; h < 2; h++) {
                float d = dp[mt][h];
                d += __shfl_xor_sync(0xffffffffu, d, 1);
                d += __shfl_xor_sync(0xffffffffu, d, 2);
                if ((lane & 3) == 0) {
                    int r = mt * 16 + rowq + h * 8;
                    ps[r * 8 + wid] = d;
                }
            }
        __syncthreads();
        if (tid < 64) {
            int r = tid;
            float d = lb[0];
            #pragma unroll
            for (int k = 0; k < 8; k++) d += ps[r * 8 + k];
            int tok = m0 + r;
            if (maskp[tok]) d = 0.f;
            if (MODE == 2)
                d = fmaxf(rintf(expf(d) * (float)(*scale)), 0.f);
            outs[tok] = d;
        }
    }
}

// ==================================================================
// weight repack: w[pred][kk][c][n] f32 -> g_W6[mat][n*2304 + blk*768 + kk*256 + c]
// blocks: 0=Whi 1=Wlo 2=Whi.  mats: 2*pred + (conv-1), preds 0,1,2
// ==================================================================
__global__ void repack_w6(const float* __restrict__ w1, const float* __restrict__ w2)
{
    int e = blockIdx.x * 256 + threadIdx.x;      // 6 * 589824
    if (e >= 6 * 589824) return;
    int mat = e / 589824;
    int r   = e - mat * 589824;
    int n = r / 2304, kq = r - n * 2304;
    int blk = kq / 768, k = kq - blk * 768;
    int kk = k >> 8, c = k & 255;
    int p = mat >> 1;
    const float* src = (mat & 1) ? w2 : w1;
    float w = src[(((size_t)p * 3 + kk) * 256 + c) * 256 + n];
    if (blk == 1) {
        float hi = __half2float(__float2half_rn(w));
        g_W6[mat][r] = __float2half_rn(w - hi);
    } else {
        g_W6[mat][r] = __float2half_rn(w);
    }
}

// fp32 -> fp16 hi/lo split
__global__ void split2_kernel(const float* __restrict__ src, __half* __restrict__ ph,
                              __half* __restrict__ pl, int n4)
{
    int i = blockIdx.x * 256 + threadIdx.x;
    if (i >= n4) return;
    float4 v = ((const float4*)src)[i];
    float a[4] = {v.x, v.y, v.z, v.w};
    uint32_t hh[2], ll[2];
    #pragma unroll
    for (int j = 0; j < 2; j++) {
        __half h0 = __float2half_rn(a[2*j]);
        __half h1 = __float2half_rn(a[2*j+1]);
        __half2 p = __halves2half2(h0, h1);
        hh[j] = *(uint32_t*)&p;
        ll[j] = packh2(a[2*j] - __half2float(h0), a[2*j+1] - __half2float(h1));
    }
    ((uint2*)ph)[i] = make_uint2(hh[0], hh[1]);
    ((uint2*)pl)[i] = make_uint2(ll[0], ll[1]);
}

// ==================================================================
// cumsum / length-regulate / embedding add
// ==================================================================
__global__ void cumsum_kernel(const int* __restrict__ dur, int* __restrict__ cs)
{
    __shared__ int s[512];
    int b = blockIdx.x, t = threadIdx.x;
    s[t] = dur[b * 512 + t];
    __syncthreads();
    for (int off = 1; off < 512; off <<= 1) {
        int v = (t >= off) ? s[t - off] : 0;
        __syncthreads();
        s[t] += v;
        __syncthreads();
    }
    cs[b * 512 + t] = s[t];
}

__global__ void length_reg_kernel(const float* __restrict__ hidden,
                                  const int* __restrict__ cs,
                                  float* __restrict__ X,
                                  __half* __restrict__ Xh, __half* __restrict__ Xl)
{
    __shared__ int scs[512];
    int tid = threadIdx.x;
    int base = blockIdx.x * 4;
    int b    = base >> 12;
    int tloc = base & 4095;
    const int* csb = cs + b * 512;
    scs[tid] = csb[tid];
    scs[tid + 256] = csb[tid + 256];
    __syncthreads();
    int g = tid >> 6, lane = tid & 63;
    int t = tloc + g;
    int lo = 0, hi = 512;
    while (lo < hi) { int mid = (lo + hi) >> 1; if (scs[mid] <= t) lo = mid + 1; else hi = mid; }
    int idx = lo < 512 ? lo : 511;
    bool valid = t < scs[511];
    float4 v = make_float4(0.f, 0.f, 0.f, 0.f);
    if (valid) v = *(const float4*)(hidden + ((size_t)b * 512 + idx) * 256 + lane * 4);
    size_t off = ((size_t)b * 4096 + t) * 256 + lane * 4;
    *(float4*)(X + off) = v;
    __half hx = __float2half_rn(v.x), hy = __float2half_rn(v.y);
    __half hz = __float2half_rn(v.z), hw = __float2half_rn(v.w);
    __half2 p0 = __halves2half2(hx, hy), p1 = __halves2half2(hz, hw);
    *(uint2*)(Xh + off) = make_uint2(*(uint32_t*)&p0, *(uint32_t*)&p1);
    *(uint2*)(Xl + off) = make_uint2(
        packh2(v.x - __half2float(hx), v.y - __half2float(hy)),
        packh2(v.z - __half2float(hz), v.w - __half2float(hw)));
}

__global__ void add_emb_kernel(const float* __restrict__ X, const float* __restrict__ tgt,
                               const float* __restrict__ bins, const float* __restrict__ emb,
                               float* __restrict__ outp,
                               __half* __restrict__ Xh, __half* __restrict__ Xl, int wxb)
{
    __shared__ float sb[256];
    int tid = threadIdx.x;
    sb[tid] = bins[tid];
    __syncthreads();
    int base = blockIdx.x * 4;
    int g = tid >> 6, lane = tid & 63;
    int t = base + g;
    float v = tgt[t];
    int lo = 0, hi = 256;
    while (lo < hi) { int mid = (lo + hi) >> 1; if (sb[mid] < v) lo = mid + 1; else hi = mid; }
    int idx = lo < 256 ? lo : 255;
    size_t off = (size_t)t * 256 + lane * 4;
    float4 a = *(const float4*)(X + off);
    float4 e = *(const float4*)(emb + (size_t)idx * 256 + lane * 4);
    a.x += e.x; a.y += e.y; a.z += e.z; a.w += e.w;
    *(float4*)(outp + off) = a;
    if (wxb) {
        __half hx = __float2half_rn(a.x), hy = __float2half_rn(a.y);
        __half hz = __float2half_rn(a.z), hw = __float2half_rn(a.w);
        __half2 p0 = __halves2half2(hx, hy), p1 = __halves2half2(hz, hw);
        *(uint2*)(Xh + off) = make_uint2(*(uint32_t*)&p0, *(uint32_t*)&p1);
        *(uint2*)(Xl + off) = make_uint2(
            packh2(a.x - __half2float(hx), a.y - __half2float(hy)),
            packh2(a.z - __half2float(hz), a.w - __half2float(hw)));
    }
}

// ==================================================================
// launch
// ==================================================================
extern "C" void kernel_launch(void* const* d_in, const int* in_sizes, int n_in,
                              void* d_out, int out_size)
{
    const float*         hidden    = (const float*)d_in[0];
    const unsigned char* mask      = (const unsigned char*)d_in[1];
    const unsigned char* fmask     = (const unsigned char*)d_in[2];
    const int*           dur_tgt   = (const int*)d_in[3];
    const float*         pitch_tgt = (const float*)d_in[4];
    const float*         energy_tgt= (const float*)d_in[5];
    const int*           dscale    = (const int*)d_in[6];
    const float*         w1        = (const float*)d_in[7];
    const float*         b1        = (const float*)d_in[8];
    const float*         l1s       = (const float*)d_in[9];
    const float*         l1b       = (const float*)d_in[10];
    const float*         w2        = (const float*)d_in[11];
    const float*         b2        = (const float*)d_in[12];
    const float*         l2s       = (const float*)d_in[13];
    const float*         l2b       = (const float*)d_in[14];
    const float*         lw        = (const float*)d_in[15];
    const float*         lb        = (const float*)d_in[16];
    const float*         pbins     = (const float*)d_in[17];
    const float*         pemb      = (const float*)d_in[18];
    const float*         ebins     = (const float*)d_in[19];
    const float*         eemb      = (const float*)d_in[20];

    cudaFuncSetAttribute(hmma_conv<0>, cudaFuncAttributeMaxDynamicSharedMemorySize, TSMEM);
    cudaFuncSetAttribute(hmma_conv<1>, cudaFuncAttributeMaxDynamicSharedMemorySize, TSMEM);
    cudaFuncSetAttribute(hmma_conv<2>, cudaFuncAttributeMaxDynamicSharedMemorySize, TSMEM);

    float* X;  __half *Xh, *Xl, *H1h, *H1l, *Dh, *Dl, *W6;  int* cs;
    cudaGetSymbolAddress((void**)&X,   g_X);
    cudaGetSymbolAddress((void**)&Xh,  g_Xh);
    cudaGetSymbolAddress((void**)&Xl,  g_Xl);
    cudaGetSymbolAddress((void**)&H1h, g_H1h);
    cudaGetSymbolAddress((void**)&H1l, g_H1l);
    cudaGetSymbolAddress((void**)&Dh,  g_Dh);
    cudaGetSymbolAddress((void**)&Dl,  g_Dl);
    cudaGetSymbolAddress((void**)&W6,  g_W6);
    cudaGetSymbolAddress((void**)&cs,  g_cs);

    float* out_rd     = (float*)d_out;
    float* out_pitch  = out_rd + 32 * 512;
    float* out_energy = out_pitch + 32 * 4096;
    float* out_ve     = out_energy + 32 * 4096;

    const size_t WS = 589824;

    repack_w6<<<13824, 256>>>(w1, w2);

    // ---- duration predictor (3-term fp16, err ~2e-7; 16384 tokens, S=512) ----
    split2_kernel<<<4096, 256>>>(hidden, Dh, Dl, 1048576);
    hmma_conv<0><<<256, 256, TSMEM>>>(Dh, Dl, W6 + 0 * WS, b1, l1s, l1b,
                                      nullptr, nullptr, nullptr, nullptr,
                                      H1h, H1l, nullptr, 512);
    hmma_conv<2><<<256, 256, TSMEM>>>(H1h, H1l, W6 + 1 * WS, b2, l2s, l2b,
                                      lw, lb, mask, dscale,
                                      nullptr, nullptr, out_rd, 512);

    // ---- length regulate ----
    cumsum_kernel<<<32, 512>>>(dur_tgt, cs);
    length_reg_kernel<<<32 * 4096 / 4, 256>>>(hidden, cs, X, Xh, Xl);

    const int NT = 131072;
    // ---- pitch predictor ----
    hmma_conv<0><<<NT / 64, 256, TSMEM>>>(Xh, Xl, W6 + 2 * WS, b1 + 256, l1s + 256, l1b + 256,
                                          nullptr, nullptr, nullptr, nullptr,
                                          H1h, H1l, nullptr, 4096);
    hmma_conv<1><<<NT / 64, 256, TSMEM>>>(H1h, H1l, W6 + 3 * WS, b2 + 256, l2s + 256, l2b + 256,
                                          lw + 256, lb + 1, fmask, nullptr,
                                          nullptr, nullptr, out_pitch, 4096);
    add_emb_kernel<<<NT / 4, 256>>>(X, pitch_tgt, pbins, pemb, X, Xh, Xl, 1);

    // ---- energy predictor ----
    hmma_conv<0><<<NT / 64, 256, TSMEM>>>(Xh, Xl, W6 + 4 * WS, b1 + 512, l1s + 512, l1b + 512,
                                          nullptr, nullptr, nullptr, nullptr,
                                          H1h, H1l, nullptr, 4096);
    hmma_conv<1><<<NT / 64, 256, TSMEM>>>(H1h, H1l, W6 + 5 * WS, b2 + 512, l2s + 512, l2b + 512,
                                          lw + 512, lb + 2, fmask, nullptr,
                                          nullptr, nullptr, out_energy, 4096);
    add_emb_kernel<<<NT / 4, 256>>>(X, energy_tgt, ebins, eemb, out_ve, nullptr, nullptr, 0);
}

// round 16
// speedup vs baseline: 1.2402x; 1.0112x over previous
#include <cuda_runtime.h>
#include <cuda_fp16.h>
#include <math.h>
#include <stdint.h>

// B=32, L=512, T=4096, E=F=256, NB=256
// Output: concat(rounded_duration[B*L], pitch[B*T], energy[B*T], variance_embedding[B*T*E])

// -------- scratch (device globals) --------
__device__ float  g_X  [33554432];   // [B,T,E] fp32 length-regulated x (exact path)
__device__ __half g_Xh [33554432];   // hi/lo fp16 split of X
__device__ __half g_Xl [33554432];
__device__ __half g_H1h[33554432];   // hidden1 after fused conv1+relu+LN (split)
__device__ __half g_H1l[33554432];
__device__ __half g_Dh [ 4194304];   // duration input split
__device__ __half g_Dl [ 4194304];
__device__ __half g_DH1h[4194304];   // duration hidden1 split (separate from big path
__device__ __half g_DH1l[4194304];   //  so the two streams never share buffers)
__device__ __half g_W6 [6][589824];  // split weights [n=256, k'=2304] = [Whi|Wlo|Whi]
__device__ int    g_cs [16384];      // cumsum durations

// ==================================================================
// helpers
// ==================================================================
__device__ __forceinline__ uint32_t smem_u32(const void* p) {
    uint32_t a;
    asm("{ .reg .u64 t; cvta.to.shared.u64 t, %1; cvt.u32.u64 %0, t; }" : "=r"(a) : "l"(p));
    return a;
}
#define SWZ(o) ((o) ^ (((o) >> 3) & 0x70))

__device__ __forceinline__ void cpa16(uint32_t dst, const void* src, int pred) {
    int sz = pred ? 16 : 0;
    asm volatile("cp.async.cg.shared.global [%0], [%1], 16, %2;" :: "r"(dst), "l"(src), "r"(sz));
}
__device__ __forceinline__ uint32_t packh2(float a, float b) {
    __half2 h = __floats2half2_rn(a, b);
    return *(uint32_t*)&h;
}
__device__ __forceinline__ void ldm4(uint32_t r[4], uint32_t addr) {
    asm volatile("ldmatrix.sync.aligned.m8n8.x4.shared.b16 {%0,%1,%2,%3}, [%4];"
        : "=r"(r[0]), "=r"(r[1]), "=r"(r[2]), "=r"(r[3]) : "r"(addr));
}
__device__ __forceinline__ void mma16816(float c[4], const uint32_t a[4],
                                         uint32_t b0, uint32_t b1) {
    asm volatile("mma.sync.aligned.m16n8k16.row.col.f32.f16.f16.f32 "
        "{%0,%1,%2,%3}, {%4,%5,%6,%7}, {%8,%9}, {%0,%1,%2,%3};"
        : "+f"(c[0]), "+f"(c[1]), "+f"(c[2]), "+f"(c[3])
        : "r"(a[0]), "r"(a[1]), "r"(a[2]), "r"(a[3]), "r"(b0), "r"(b1));
}

// ==================================================================
// split-fp16 HMMA conv(k=3, 256->256) + fused epilogue  (R12 config)
//   C = Ahi*Whi + Ahi*Wlo + Alo*Whi   (K' = 2304, 36 chunks of 64)
//   tile 128(M) x 256(N, full), 512 threads = 4(M) x 4(N) warps of 32x64
//   3-slot cp.async ring (48KB/slot), SW128 swizzle
//   epilogue: bias+relu+LayerNorm fused.
//   MODE 0: LN out as hi/lo fp16 split. MODE 1: LN->dot(lw)+lb->mask->scalar.
//   MODE 2: MODE1 + round(exp(val)*scale) (duration).
// ==================================================================
#define CHK   49152                  // per-chunk: A 16KB + B 32KB
#define PRMOF (3 * CHK)              // params after the ring
#define TSMEM (PRMOF + 4096)

template<int MODE>
__global__ __launch_bounds__(512, 1)
void hmma_conv(const __half* __restrict__ A0, const __half* __restrict__ A1,
               const __half* __restrict__ W, const float* __restrict__ bias,
               const float* __restrict__ lns, const float* __restrict__ lnb,
               const float* __restrict__ lw, const float* __restrict__ lb,
               const unsigned char* __restrict__ maskp, const int* __restrict__ scale,
               __half* __restrict__ outh, __half* __restrict__ outl,
               float* __restrict__ outs, int S)
{
    extern __shared__ char sm[];
    uint32_t smb = smem_u32(sm);
    int tid  = threadIdx.x;
    int lane = tid & 31;
    int wid  = tid >> 5;
    int warp_m = (wid & 3) * 32;     // 4 warps over M(128)
    int warp_n = (wid >> 2) * 64;    // 4 warps over N(256)
    int wn = wid >> 2;

    // params -> smem (region beyond ring)
    float* sbias = (float*)(sm + PRMOF);
    float* sls   = (float*)(sm + PRMOF + 1024);
    float* slnb  = (float*)(sm + PRMOF + 2048);
    float* slw   = (float*)(sm + PRMOF + 3072);
    if (tid < 256) {
        sbias[tid] = bias[tid];
        sls[tid]   = lns[tid];
        slnb[tid]  = lnb[tid];
        slw[tid]   = (MODE != 0) ? lw[tid] : 0.f;
    }

    int m0 = blockIdx.x * 128;
    int b  = m0 / S;
    int t0 = m0 - b * S;

    auto load_chunk = [&](int ci, int stg) {
        int part = ci / 12;                       // 0:Ahi*Whi 1:Ahi*Wlo 2:Alo*Whi
        int k0in = (ci - part * 12) * 64;
        int tap = k0in >> 8, c0 = k0in & 255;
        const __half* Ab = ((part == 2) ? A1 : A0) + (size_t)b * S * 256;
        int k0w = ci * 64;
        uint32_t Asm = smb + stg * CHK;
        uint32_t Bsm = Asm + 16384;
        #pragma unroll
        for (int j = 0; j < 2; j++) {             // A: 128 rows x 128B
            int u = tid + 512 * j, row = u >> 3, c16 = u & 7;
            int tr = t0 + row + tap - 1;
            cpa16(Asm + SWZ(row * 128 + c16 * 16),
                  Ab + (size_t)tr * 256 + c0 + c16 * 8,
                  (unsigned)tr < (unsigned)S);
        }
        #pragma unroll
        for (int j = 0; j < 4; j++) {             // B: 256 n-rows x 128B
            int u = tid + 512 * j, n = u >> 3, c16 = u & 7;
            cpa16(Bsm + SWZ(n * 128 + c16 * 16),
                  W + (size_t)n * 2304 + k0w + c16 * 8, 1);
        }
    };

    float acc[2][8][4];
    #pragma unroll
    for (int i = 0; i < 2; i++)
        #pragma unroll
        for (int j = 0; j < 8; j++)
            #pragma unroll
            for (int e = 0; e < 4; e++) acc[i][j][e] = 0.f;

    int g = lane >> 3;
    int arow = ((g & 1) << 3) + (lane & 7);
    int akk  = (g >> 1) << 3;
    int brow = ((g >> 1) << 3) + (lane & 7);
    int bkk  = (g & 1) << 3;

    load_chunk(0, 0);
    asm volatile("cp.async.commit_group;" ::: "memory");
    load_chunk(1, 1);
    asm volatile("cp.async.commit_group;" ::: "memory");

    const int NC = 36;
    for (int i = 0; i < NC; i++) {
        if (i + 1 < NC) asm volatile("cp.async.wait_group 1;" ::: "memory");
        else            asm volatile("cp.async.wait_group 0;" ::: "memory");
        __syncthreads();
        if (i + 2 < NC) {
            load_chunk(i + 2, (i + 2) % 3);
            asm volatile("cp.async.commit_group;" ::: "memory");
        }
        uint32_t Asm = smb + (i % 3) * CHK;
        uint32_t Bsm = Asm + 16384;
        #pragma unroll
        for (int ks = 0; ks < 4; ks++) {
            int kk = ks * 16;
            uint32_t a[2][4], bq[4][4];
            #pragma unroll
            for (int mt = 0; mt < 2; mt++) {
                int row = warp_m + mt * 16 + arow;
                ldm4(a[mt], Asm + SWZ(row * 128 + (kk + akk) * 2));
            }
            #pragma unroll
            for (int q = 0; q < 4; q++) {
                int n = warp_n + q * 16 + brow;
                ldm4(bq[q], Bsm + SWZ(n * 128 + (kk + bkk) * 2));
            }
            #pragma unroll
            for (int mt = 0; mt < 2; mt++)
                #pragma unroll
                for (int nb = 0; nb < 8; nb++) {
                    int q = nb >> 1, h = (nb & 1) * 2;
                    mma16816(acc[mt][nb], a[mt], bq[q][h], bq[q][h + 1]);
                }
        }
    }

    // ================= fused epilogue =================
    __syncthreads();                 // all compute done; ring smem reusable
    float* ps = (float*)sm;          // [128][4] row partial sums
    float* qs = (float*)(sm + 2048); // [128][4] row partial sumsq

    int colq = (lane & 3) * 2;
    int rowq = lane >> 2;

    // bias + relu in place
    #pragma unroll
    for (int mt = 0; mt < 2; mt++)
        #pragma unroll
        for (int nb = 0; nb < 8; nb++) {
            int col = warp_n + nb * 8 + colq;
            float b0 = sbias[col], b1 = sbias[col + 1];
            acc[mt][nb][0] = fmaxf(acc[mt][nb][0] + b0, 0.f);
            acc[mt][nb][1] = fmaxf(acc[mt][nb][1] + b1, 0.f);
            acc[mt][nb][2] = fmaxf(acc[mt][nb][2] + b0, 0.f);
            acc[mt][nb][3] = fmaxf(acc[mt][nb][3] + b1, 0.f);
        }

    // row sums / sumsq (quad shfl + cross-N-warp smem)
    #pragma unroll
    for (int mt = 0; mt < 2; mt++)
        #pragma unroll
        for (int h = 0; h < 2; h++) {
            float s = 0.f, q = 0.f;
            #pragma unroll
            for (int nb = 0; nb < 8; nb++) {
                float a = acc[mt][nb][2 * h], c = acc[mt][nb][2 * h + 1];
                s += a + c; q += a * a + c * c;
            }
            s += __shfl_xor_sync(0xffffffffu, s, 1);
            q += __shfl_xor_sync(0xffffffffu, q, 1);
            s += __shfl_xor_sync(0xffffffffu, s, 2);
            q += __shfl_xor_sync(0xffffffffu, q, 2);
            if ((lane & 3) == 0) {
                int r = warp_m + mt * 16 + rowq + h * 8;
                ps[r * 4 + wn] = s;
                qs[r * 4 + wn] = q;
            }
        }
    __syncthreads();

    float mean[2][2], rstd[2][2];
    #pragma unroll
    for (int mt = 0; mt < 2; mt++)
        #pragma unroll
        for (int h = 0; h < 2; h++) {
            int r = warp_m + mt * 16 + rowq + h * 8;
            float s = ps[r * 4] + ps[r * 4 + 1] + ps[r * 4 + 2] + ps[r * 4 + 3];
            float q = qs[r * 4] + qs[r * 4 + 1] + qs[r * 4 + 2] + qs[r * 4 + 3];
            float m = s * (1.f / 256.f);
            mean[mt][h] = m;
            rstd[mt][h] = rsqrtf(q * (1.f / 256.f) - m * m + 1e-5f);
        }

    if (MODE == 0) {
        // LN -> hi/lo fp16 split
        #pragma unroll
        for (int mt = 0; mt < 2; mt++)
            #pragma unroll
            for (int nb = 0; nb < 8; nb++) {
                int col = warp_n + nb * 8 + colq;
                float s0 = sls[col], s1 = sls[col + 1];
                float c0 = slnb[col], c1 = slnb[col + 1];
                #pragma unroll
                for (int h = 0; h < 2; h++) {
                    int tok = m0 + warp_m + mt * 16 + rowq + h * 8;
                    float o0 = (acc[mt][nb][2*h]   - mean[mt][h]) * rstd[mt][h] * s0 + c0;
                    float o1 = (acc[mt][nb][2*h+1] - mean[mt][h]) * rstd[mt][h] * s1 + c1;
                    __half h0 = __float2half_rn(o0);
                    __half h1 = __float2half_rn(o1);
                    __half2 hh = __halves2half2(h0, h1);
                    *(uint32_t*)(outh + (size_t)tok * 256 + col) = *(uint32_t*)&hh;
                    *(uint32_t*)(outl + (size_t)tok * 256 + col) =
                        packh2(o0 - __half2float(h0), o1 - __half2float(h1));
                }
            }
    } else {
        // LN -> dot with lw per row
        float dp[2][2] = {{0.f, 0.f}, {0.f, 0.f}};
        #pragma unroll
        for (int mt = 0; mt < 2; mt++)
            #pragma unroll
            for (int nb = 0; nb < 8; nb++) {
                int col = warp_n + nb * 8 + colq;
                float s0 = sls[col], s1 = sls[col + 1];
                float c0 = slnb[col], c1 = slnb[col + 1];
                float w0 = slw[col], w1 = slw[col + 1];
                #pragma unroll
                for (int h = 0; h < 2; h++) {
                    float o0 = (acc[mt][nb][2*h]   - mean[mt][h]) * rstd[mt][h] * s0 + c0;
                    float o1 = (acc[mt][nb][2*h+1] - mean[mt][h]) * rstd[mt][h] * s1 + c1;
                    dp[mt][h] += o0 * w0 + o1 * w1;
                }
            }
        __syncthreads();             // reuse ps for dot partials
        #pragma unroll
        for (int mt = 0; mt < 2; mt++)
            #pragma unroll
            for (int h = 0; h < 2; h++) {
                float d = dp[mt][h];
                d += __shfl_xor_sync(0xffffffffu, d, 1);
                d += __shfl_xor_sync(0xffffffffu, d, 2);
                if ((lane & 3) == 0) {
                    int r = warp_m + mt * 16 + rowq + h * 8;
                    ps[r * 4 + wn] = d;
                }
            }
        __syncthreads();
        if (tid < 128) {
            int r = tid;
            float d = ps[r * 4] + ps[r * 4 + 1] + ps[r * 4 + 2] + ps[r * 4 + 3] + lb[0];
            int tok = m0 + r;
            if (maskp[tok]) d = 0.f;
            if (MODE == 2)
                d = fmaxf(rintf(expf(d) * (float)(*scale)), 0.f);
            outs[tok] = d;
        }
    }
}

// ==================================================================
// weight repack: w[pred][kk][c][n] f32 -> g_W6[mat][n*2304 + blk*768 + kk*256 + c]
// blocks: 0=Whi 1=Wlo 2=Whi.  mats: 2*pred + (conv-1), preds 0,1,2
// ==================================================================
__global__ void repack_w6(const float* __restrict__ w1, const float* __restrict__ w2)
{
    int e = blockIdx.x * 256 + threadIdx.x;      // 6 * 589824
    if (e >= 6 * 589824) return;
    int mat = e / 589824;
    int r   = e - mat * 589824;
    int n = r / 2304, kq = r - n * 2304;
    int blk = kq / 768, k = kq - blk * 768;
    int kk = k >> 8, c = k & 255;
    int p = mat >> 1;
    const float* src = (mat & 1) ? w2 : w1;
    float w = src[(((size_t)p * 3 + kk) * 256 + c) * 256 + n];
    if (blk == 1) {
        float hi = __half2float(__float2half_rn(w));
        g_W6[mat][r] = __float2half_rn(w - hi);
    } else {
        g_W6[mat][r] = __float2half_rn(w);
    }
}

// fp32 -> fp16 hi/lo split
__global__ void split2_kernel(const float* __restrict__ src, __half* __restrict__ ph,
                              __half* __restrict__ pl, int n4)
{
    int i = blockIdx.x * 256 + threadIdx.x;
    if (i >= n4) return;
    float4 v = ((const float4*)src)[i];
    float a[4] = {v.x, v.y, v.z, v.w};
    uint32_t hh[2], ll[2];
    #pragma unroll
    for (int j = 0; j < 2; j++) {
        __half h0 = __float2half_rn(a[2*j]);
        __half h1 = __float2half_rn(a[2*j+1]);
        __half2 p = __halves2half2(h0, h1);
        hh[j] = *(uint32_t*)&p;
        ll[j] = packh2(a[2*j] - __half2float(h0), a[2*j+1] - __half2float(h1));
    }
    ((uint2*)ph)[i] = make_uint2(hh[0], hh[1]);
    ((uint2*)pl)[i] = make_uint2(ll[0], ll[1]);
}

// ==================================================================
// cumsum / length-regulate / embedding add
// ==================================================================
__global__ void cumsum_kernel(const int* __restrict__ dur, int* __restrict__ cs)
{
    __shared__ int s[512];
    int b = blockIdx.x, t = threadIdx.x;
    s[t] = dur[b * 512 + t];
    __syncthreads();
    for (int off = 1; off < 512; off <<= 1) {
        int v = (t >= off) ? s[t - off] : 0;
        __syncthreads();
        s[t] += v;
        __syncthreads();
    }
    cs[b * 512 + t] = s[t];
}

__global__ void length_reg_kernel(const float* __restrict__ hidden,
                                  const int* __restrict__ cs,
                                  float* __restrict__ X,
                                  __half* __restrict__ Xh, __half* __restrict__ Xl)
{
    __shared__ int scs[512];
    int tid = threadIdx.x;
    int base = blockIdx.x * 4;
    int b    = base >> 12;
    int tloc = base & 4095;
    const int* csb = cs + b * 512;
    scs[tid] = csb[tid];
    scs[tid + 256] = csb[tid + 256];
    __syncthreads();
    int g = tid >> 6, lane = tid & 63;
    int t = tloc + g;
    int lo = 0, hi = 512;
    while (lo < hi) { int mid = (lo + hi) >> 1; if (scs[mid] <= t) lo = mid + 1; else hi = mid; }
    int idx = lo < 512 ? lo : 511;
    bool valid = t < scs[511];
    float4 v = make_float4(0.f, 0.f, 0.f, 0.f);
    if (valid) v = *(const float4*)(hidden + ((size_t)b * 512 + idx) * 256 + lane * 4);
    size_t off = ((size_t)b * 4096 + t) * 256 + lane * 4;
    *(float4*)(X + off) = v;
    __half hx = __float2half_rn(v.x), hy = __float2half_rn(v.y);
    __half hz = __float2half_rn(v.z), hw = __float2half_rn(v.w);
    __half2 p0 = __halves2half2(hx, hy), p1 = __halves2half2(hz, hw);
    *(uint2*)(Xh + off) = make_uint2(*(uint32_t*)&p0, *(uint32_t*)&p1);
    *(uint2*)(Xl + off) = make_uint2(
        packh2(v.x - __half2float(hx), v.y - __half2float(hy)),
        packh2(v.z - __half2float(hz), v.w - __half2float(hw)));
}

__global__ void add_emb_kernel(const float* __restrict__ X, const float* __restrict__ tgt,
                               const float* __restrict__ bins, const float* __restrict__ emb,
                               float* __restrict__ outp,
                               __half* __restrict__ Xh, __half* __restrict__ Xl, int wxb)
{
    __shared__ float sb[256];
    int tid = threadIdx.x;
    sb[tid] = bins[tid];
    __syncthreads();
    int base = blockIdx.x * 4;
    int g = tid >> 6, lane = tid & 63;
    int t = base + g;
    float v = tgt[t];
    int lo = 0, hi = 256;
    while (lo < hi) { int mid = (lo + hi) >> 1; if (sb[mid] < v) lo = mid + 1; else hi = mid; }
    int idx = lo < 256 ? lo : 255;
    size_t off = (size_t)t * 256 + lane * 4;
    float4 a = *(const float4*)(X + off);
    float4 e = *(const float4*)(emb + (size_t)idx * 256 + lane * 4);
    a.x += e.x; a.y += e.y; a.z += e.z; a.w += e.w;
    *(float4*)(outp + off) = a;
    if (wxb) {
        __half hx = __float2half_rn(a.x), hy = __float2half_rn(a.y);
        __half hz = __float2half_rn(a.z), hw = __float2half_rn(a.w);
        __half2 p0 = __halves2half2(hx, hy), p1 = __halves2half2(hz, hw);
        *(uint2*)(Xh + off) = make_uint2(*(uint32_t*)&p0, *(uint32_t*)&p1);
        *(uint2*)(Xl + off) = make_uint2(
            packh2(a.x - __half2float(hx), a.y - __half2float(hy)),
            packh2(a.z - __half2float(hz), a.w - __half2float(hw)));
    }
}

// ==================================================================
// launch — dual-stream fork/join: s1 carries the independent duration
// path + length-regulate; main stream carries the big pitch/energy chain.
// ==================================================================
extern "C" void kernel_launch(void* const* d_in, const int* in_sizes, int n_in,
                              void* d_out, int out_size)
{
    const float*         hidden    = (const float*)d_in[0];
    const unsigned char* mask      = (const unsigned char*)d_in[1];
    const unsigned char* fmask     = (const unsigned char*)d_in[2];
    const int*           dur_tgt   = (const int*)d_in[3];
    const float*         pitch_tgt = (const float*)d_in[4];
    const float*         energy_tgt= (const float*)d_in[5];
    const int*           dscale    = (const int*)d_in[6];
    const float*         w1        = (const float*)d_in[7];
    const float*         b1        = (const float*)d_in[8];
    const float*         l1s       = (const float*)d_in[9];
    const float*         l1b       = (const float*)d_in[10];
    const float*         w2        = (const float*)d_in[11];
    const float*         b2        = (const float*)d_in[12];
    const float*         l2s       = (const float*)d_in[13];
    const float*         l2b       = (const float*)d_in[14];
    const float*         lw        = (const float*)d_in[15];
    const float*         lb        = (const float*)d_in[16];
    const float*         pbins     = (const float*)d_in[17];
    const float*         pemb      = (const float*)d_in[18];
    const float*         ebins     = (const float*)d_in[19];
    const float*         eemb      = (const float*)d_in[20];

    static cudaStream_t s1 = nullptr;
    static cudaEvent_t eFork = nullptr, eRepack = nullptr, eLenReg = nullptr, eDur = nullptr;
    if (!s1) {
        cudaStreamCreateWithFlags(&s1, cudaStreamNonBlocking);
        cudaEventCreateWithFlags(&eFork,   cudaEventDisableTiming);
        cudaEventCreateWithFlags(&eRepack, cudaEventDisableTiming);
        cudaEventCreateWithFlags(&eLenReg, cudaEventDisableTiming);
        cudaEventCreateWithFlags(&eDur,    cudaEventDisableTiming);
        cudaFuncSetAttribute(hmma_conv<0>, cudaFuncAttributeMaxDynamicSharedMemorySize, TSMEM);
        cudaFuncSetAttribute(hmma_conv<1>, cudaFuncAttributeMaxDynamicSharedMemorySize, TSMEM);
        cudaFuncSetAttribute(hmma_conv<2>, cudaFuncAttributeMaxDynamicSharedMemorySize, TSMEM);
    }

    float* X;  __half *Xh, *Xl, *H1h, *H1l, *Dh, *Dl, *DH1h, *DH1l, *W6;  int* cs;
    cudaGetSymbolAddress((void**)&X,    g_X);
    cudaGetSymbolAddress((void**)&Xh,   g_Xh);
    cudaGetSymbolAddress((void**)&Xl,   g_Xl);
    cudaGetSymbolAddress((void**)&H1h,  g_H1h);
    cudaGetSymbolAddress((void**)&H1l,  g_H1l);
    cudaGetSymbolAddress((void**)&Dh,   g_Dh);
    cudaGetSymbolAddress((void**)&Dl,   g_Dl);
    cudaGetSymbolAddress((void**)&DH1h, g_DH1h);
    cudaGetSymbolAddress((void**)&DH1l, g_DH1l);
    cudaGetSymbolAddress((void**)&W6,   g_W6);
    cudaGetSymbolAddress((void**)&cs,   g_cs);

    float* out_rd     = (float*)d_out;
    float* out_pitch  = out_rd + 32 * 512;
    float* out_energy = out_pitch + 32 * 4096;
    float* out_ve     = out_energy + 32 * 4096;

    const size_t WS = 589824;
    const int NT = 131072;

    // ---- fork s1 from the capture (main) stream ----
    cudaEventRecord(eFork, 0);
    cudaStreamWaitEvent(s1, eFork, 0);

    // ---- main stream: weight repack (needed by every conv) ----
    repack_w6<<<13824, 256>>>(w1, w2);
    cudaEventRecord(eRepack, 0);

    // ---- s1: cumsum + length-regulate (independent of repack) ----
    cumsum_kernel<<<32, 512, 0, s1>>>(dur_tgt, cs);
    length_reg_kernel<<<32 * 4096 / 4, 256, 0, s1>>>(hidden, cs, X, Xh, Xl);
    cudaEventRecord(eLenReg, s1);

    // ---- s1: duration predictor (waits for weights) ----
    split2_kernel<<<4096, 256, 0, s1>>>(hidden, Dh, Dl, 1048576);
    cudaStreamWaitEvent(s1, eRepack, 0);
    hmma_conv<0><<<128, 512, TSMEM, s1>>>(Dh, Dl, W6 + 0 * WS, b1, l1s, l1b,
                                          nullptr, nullptr, nullptr, nullptr,
                                          DH1h, DH1l, nullptr, 512);
    hmma_conv<2><<<128, 512, TSMEM, s1>>>(DH1h, DH1l, W6 + 1 * WS, b2, l2s, l2b,
                                          lw, lb, mask, dscale,
                                          nullptr, nullptr, out_rd, 512);
    cudaEventRecord(eDur, s1);

    // ---- main stream: pitch predictor (waits for length-regulate) ----
    cudaStreamWaitEvent(0, eLenReg, 0);
    hmma_conv<0><<<NT / 128, 512, TSMEM>>>(Xh, Xl, W6 + 2 * WS, b1 + 256, l1s + 256, l1b + 256,
                                           nullptr, nullptr, nullptr, nullptr,
                                           H1h, H1l, nullptr, 4096);
    hmma_conv<1><<<NT / 128, 512, TSMEM>>>(H1h, H1l, W6 + 3 * WS, b2 + 256, l2s + 256, l2b + 256,
                                           lw + 256, lb + 1, fmask, nullptr,
                                           nullptr, nullptr, out_pitch, 4096);
    add_emb_kernel<<<NT / 4, 256>>>(X, pitch_tgt, pbins, pemb, X, Xh, Xl, 1);

    // ---- main stream: energy predictor ----
    hmma_conv<0><<<NT / 128, 512, TSMEM>>>(Xh, Xl, W6 + 4 * WS, b1 + 512, l1s + 512, l1b + 512,
                                           nullptr, nullptr, nullptr, nullptr,
                                           H1h, H1l, nullptr, 4096);
    hmma_conv<1><<<NT / 128, 512, TSMEM>>>(H1h, H1l, W6 + 5 * WS, b2 + 512, l2s + 512, l2b + 512,
                                           lw + 512, lb + 2, fmask, nullptr,
                                           nullptr, nullptr, out_energy, 4096);
    add_emb_kernel<<<NT / 4, 256>>>(X, energy_tgt, ebins, eemb, out_ve, nullptr, nullptr, 0);

    // ---- join s1 back into the capture stream ----
    cudaStreamWaitEvent(0, eDur, 0);
}

// round 17
// speedup vs baseline: 1.4449x; 1.1650x over previous
#include <cuda_runtime.h>
#include <cuda_fp16.h>
#include <math.h>
#include <stdint.h>

// B=32, L=512, T=4096, E=F=256, NB=256
// Output: concat(rounded_duration[B*L], pitch[B*T], energy[B*T], variance_embedding[B*T*E])

// -------- scratch (device globals) --------
__device__ float  g_X  [33554432];   // [B,T,E] fp32 length-regulated x (exact path)
__device__ __half g_Xh [33554432];   // fp16 of X (big-path conv1 A operand; 2-block)
__device__ __half g_H1h[33554432];   // hidden1 after fused conv1+relu+LN (split)
__device__ __half g_H1l[33554432];
__device__ __half g_Dh [ 4194304];   // duration input split
__device__ __half g_Dl [ 4194304];
__device__ __half g_DH1h[4194304];   // duration hidden1 split
__device__ __half g_DH1l[4194304];
__device__ __half g_W6 [4][589824];  // 3-block weights [n,2304]=[Whi|Wlo|Whi]:
                                     //  0=dur w1, 1=dur w2, 2=pitch w2, 3=energy w2
__device__ __half g_W2 [2][393216];  // 2-block weights [n,1536]=[Whi|Wlo]:
                                     //  0=pitch w1, 1=energy w1
__device__ int    g_cs [16384];      // cumsum durations

// ==================================================================
// helpers
// ==================================================================
__device__ __forceinline__ uint32_t smem_u32(const void* p) {
    uint32_t a;
    asm("{ .reg .u64 t; cvta.to.shared.u64 t, %1; cvt.u32.u64 %0, t; }" : "=r"(a) : "l"(p));
    return a;
}
#define SWZ(o) ((o) ^ (((o) >> 3) & 0x70))

__device__ __forceinline__ void cpa16(uint32_t dst, const void* src, int pred) {
    int sz = pred ? 16 : 0;
    asm volatile("cp.async.cg.shared.global [%0], [%1], 16, %2;" :: "r"(dst), "l"(src), "r"(sz));
}
__device__ __forceinline__ uint32_t packh2(float a, float b) {
    __half2 h = __floats2half2_rn(a, b);
    return *(uint32_t*)&h;
}
__device__ __forceinline__ void ldm4(uint32_t r[4], uint32_t addr) {
    asm volatile("ldmatrix.sync.aligned.m8n8.x4.shared.b16 {%0,%1,%2,%3}, [%4];"
        : "=r"(r[0]), "=r"(r[1]), "=r"(r[2]), "=r"(r[3]) : "r"(addr));
}
__device__ __forceinline__ void mma16816(float c[4], const uint32_t a[4],
                                         uint32_t b0, uint32_t b1) {
    asm volatile("mma.sync.aligned.m16n8k16.row.col.f32.f16.f16.f32 "
        "{%0,%1,%2,%3}, {%4,%5,%6,%7}, {%8,%9}, {%0,%1,%2,%3};"
        : "+f"(c[0]), "+f"(c[1]), "+f"(c[2]), "+f"(c[3])
        : "r"(a[0]), "r"(a[1]), "r"(a[2]), "r"(a[3]), "r"(b0), "r"(b1));
}

// ==================================================================
// split-fp16 HMMA conv(k=3, 256->256) + fused epilogue
//   NBLK=3: C = Ahi*Whi + Ahi*Wlo + Alo*Whi   (K'=2304, err ~2e-6)
//   NBLK=2: C = Ahi*Whi + Ahi*Wlo  (= fp16(A) * W exact; K'=1536, err ~3.6e-4)
//   tile 128(M) x 256(N, full), 512 threads = 4(M) x 4(N) warps of 32x64
//   3-slot cp.async ring (48KB/slot), SW128 swizzle
//   epilogue: bias+relu+LayerNorm fused.
//   MODE 0: LN out as hi/lo fp16 split. MODE 1: LN->dot(lw)+lb->mask->scalar.
//   MODE 2: MODE1 + round(exp(val)*scale) (duration).
// ==================================================================
#define CHK   49152                  // per-chunk: A 16KB + B 32KB
#define PRMOF (3 * CHK)              // params after the ring
#define TSMEM (PRMOF + 4096)

template<int MODE, int NBLK>
__global__ __launch_bounds__(512, 1)
void hmma_conv(const __half* __restrict__ A0, const __half* __restrict__ A1,
               const __half* __restrict__ W, const float* __restrict__ bias,
               const float* __restrict__ lns, const float* __restrict__ lnb,
               const float* __restrict__ lw, const float* __restrict__ lb,
               const unsigned char* __restrict__ maskp, const int* __restrict__ scale,
               __half* __restrict__ outh, __half* __restrict__ outl,
               float* __restrict__ outs, int S)
{
    extern __shared__ char sm[];
    uint32_t smb = smem_u32(sm);
    const int KP = NBLK * 768;
    int tid  = threadIdx.x;
    int lane = tid & 31;
    int wid  = tid >> 5;
    int warp_m = (wid & 3) * 32;     // 4 warps over M(128)
    int warp_n = (wid >> 2) * 64;    // 4 warps over N(256)
    int wn = wid >> 2;

    // params -> smem (region beyond ring)
    float* sbias = (float*)(sm + PRMOF);
    float* sls   = (float*)(sm + PRMOF + 1024);
    float* slnb  = (float*)(sm + PRMOF + 2048);
    float* slw   = (float*)(sm + PRMOF + 3072);
    if (tid < 256) {
        sbias[tid] = bias[tid];
        sls[tid]   = lns[tid];
        slnb[tid]  = lnb[tid];
        slw[tid]   = (MODE != 0) ? lw[tid] : 0.f;
    }

    int m0 = blockIdx.x * 128;
    int b  = m0 / S;
    int t0 = m0 - b * S;

    auto load_chunk = [&](int ci, int stg) {
        int part = ci / 12;           // NBLK=3: 0:Ahi*Whi 1:Ahi*Wlo 2:Alo*Whi
        int k0in = (ci - part * 12) * 64;
        int tap = k0in >> 8, c0 = k0in & 255;
        const __half* Ab = ((NBLK == 3 && part == 2) ? A1 : A0) + (size_t)b * S * 256;
        int k0w = ci * 64;
        uint32_t Asm = smb + stg * CHK;
        uint32_t Bsm = Asm + 16384;
        #pragma unroll
        for (int j = 0; j < 2; j++) {             // A: 128 rows x 128B
            int u = tid + 512 * j, row = u >> 3, c16 = u & 7;
            int tr = t0 + row + tap - 1;
            cpa16(Asm + SWZ(row * 128 + c16 * 16),
                  Ab + (size_t)tr * 256 + c0 + c16 * 8,
                  (unsigned)tr < (unsigned)S);
        }
        #pragma unroll
        for (int j = 0; j < 4; j++) {             // B: 256 n-rows x 128B
            int u = tid + 512 * j, n = u >> 3, c16 = u & 7;
            cpa16(Bsm + SWZ(n * 128 + c16 * 16),
                  W + (size_t)n * KP + k0w + c16 * 8, 1);
        }
    };

    float acc[2][8][4];
    #pragma unroll
    for (int i = 0; i < 2; i++)
        #pragma unroll
        for (int j = 0; j < 8; j++)
            #pragma unroll
            for (int e = 0; e < 4; e++) acc[i][j][e] = 0.f;

    int g = lane >> 3;
    int arow = ((g & 1) << 3) + (lane & 7);
    int akk  = (g >> 1) << 3;
    int brow = ((g >> 1) << 3) + (lane & 7);
    int bkk  = (g & 1) << 3;

    load_chunk(0, 0);
    asm volatile("cp.async.commit_group;" ::: "memory");
    load_chunk(1, 1);
    asm volatile("cp.async.commit_group;" ::: "memory");

    const int NC = NBLK * 12;
    for (int i = 0; i < NC; i++) {
        if (i + 1 < NC) asm volatile("cp.async.wait_group 1;" ::: "memory");
        else            asm volatile("cp.async.wait_group 0;" ::: "memory");
        __syncthreads();
        if (i + 2 < NC) {
            load_chunk(i + 2, (i + 2) % 3);
            asm volatile("cp.async.commit_group;" ::: "memory");
        }
        uint32_t Asm = smb + (i % 3) * CHK;
        uint32_t Bsm = Asm + 16384;
        #pragma unroll
        for (int ks = 0; ks < 4; ks++) {
            int kk = ks * 16;
            uint32_t a[2][4], bq[4][4];
            #pragma unroll
            for (int mt = 0; mt < 2; mt++) {
                int row = warp_m + mt * 16 + arow;
                ldm4(a[mt], Asm + SWZ(row * 128 + (kk + akk) * 2));
            }
            #pragma unroll
            for (int q = 0; q < 4; q++) {
                int n = warp_n + q * 16 + brow;
                ldm4(bq[q], Bsm + SWZ(n * 128 + (kk + bkk) * 2));
            }
            #pragma unroll
            for (int mt = 0; mt < 2; mt++)
                #pragma unroll
                for (int nb = 0; nb < 8; nb++) {
                    int q = nb >> 1, h = (nb & 1) * 2;
                    mma16816(acc[mt][nb], a[mt], bq[q][h], bq[q][h + 1]);
                }
        }
    }

    // ================= fused epilogue =================
    __syncthreads();                 // all compute done; ring smem reusable
    float* ps = (float*)sm;          // [128][4] row partial sums
    float* qs = (float*)(sm + 2048); // [128][4] row partial sumsq

    int colq = (lane & 3) * 2;
    int rowq = lane >> 2;

    // bias + relu in place
    #pragma unroll
    for (int mt = 0; mt < 2; mt++)
        #pragma unroll
        for (int nb = 0; nb < 8; nb++) {
            int col = warp_n + nb * 8 + colq;
            float b0 = sbias[col], b1 = sbias[col + 1];
            acc[mt][nb][0] = fmaxf(acc[mt][nb][0] + b0, 0.f);
            acc[mt][nb][1] = fmaxf(acc[mt][nb][1] + b1, 0.f);
            acc[mt][nb][2] = fmaxf(acc[mt][nb][2] + b0, 0.f);
            acc[mt][nb][3] = fmaxf(acc[mt][nb][3] + b1, 0.f);
        }

    // row sums / sumsq (quad shfl + cross-N-warp smem)
    #pragma unroll
    for (int mt = 0; mt < 2; mt++)
        #pragma unroll
        for (int h = 0; h < 2; h++) {
            float s = 0.f, q = 0.f;
            #pragma unroll
            for (int nb = 0; nb < 8; nb++) {
                float a = acc[mt][nb][2 * h], c = acc[mt][nb][2 * h + 1];
                s += a + c; q += a * a + c * c;
            }
            s += __shfl_xor_sync(0xffffffffu, s, 1);
            q += __shfl_xor_sync(0xffffffffu, q, 1);
            s += __shfl_xor_sync(0xffffffffu, s, 2);
            q += __shfl_xor_sync(0xffffffffu, q, 2);
            if ((lane & 3) == 0) {
                int r = warp_m + mt * 16 + rowq + h * 8;
                ps[r * 4 + wn] = s;
                qs[r * 4 + wn] = q;
            }
        }
    __syncthreads();

    float mean[2][2], rstd[2][2];
    #pragma unroll
    for (int mt = 0; mt < 2; mt++)
        #pragma unroll
        for (int h = 0; h < 2; h++) {
            int r = warp_m + mt * 16 + rowq + h * 8;
            float s = ps[r * 4] + ps[r * 4 + 1] + ps[r * 4 + 2] + ps[r * 4 + 3];
            float q = qs[r * 4] + qs[r * 4 + 1] + qs[r * 4 + 2] + qs[r * 4 + 3];
            float m = s * (1.f / 256.f);
            mean[mt][h] = m;
            rstd[mt][h] = rsqrtf(q * (1.f / 256.f) - m * m + 1e-5f);
        }

    if (MODE == 0) {
        // LN -> hi/lo fp16 split
        #pragma unroll
        for (int mt = 0; mt < 2; mt++)
            #pragma unroll
            for (int nb = 0; nb < 8; nb++) {
                int col = warp_n + nb * 8 + colq;
                float s0 = sls[col], s1 = sls[col + 1];
                float c0 = slnb[col], c1 = slnb[col + 1];
                #pragma unroll
                for (int h = 0; h < 2; h++) {
                    int tok = m0 + warp_m + mt * 16 + rowq + h * 8;
                    float o0 = (acc[mt][nb][2*h]   - mean[mt][h]) * rstd[mt][h] * s0 + c0;
                    float o1 = (acc[mt][nb][2*h+1] - mean[mt][h]) * rstd[mt][h] * s1 + c1;
                    __half h0 = __float2half_rn(o0);
                    __half h1 = __float2half_rn(o1);
                    __half2 hh = __halves2half2(h0, h1);
                    *(uint32_t*)(outh + (size_t)tok * 256 + col) = *(uint32_t*)&hh;
                    *(uint32_t*)(outl + (size_t)tok * 256 + col) =
                        packh2(o0 - __half2float(h0), o1 - __half2float(h1));
                }
            }
    } else {
        // LN -> dot with lw per row
        float dp[2][2] = {{0.f, 0.f}, {0.f, 0.f}};
        #pragma unroll
        for (int mt = 0; mt < 2; mt++)
            #pragma unroll
            for (int nb = 0; nb < 8; nb++) {
                int col = warp_n + nb * 8 + colq;
                float s0 = sls[col], s1 = sls[col + 1];
                float c0 = slnb[col], c1 = slnb[col + 1];
                float w0 = slw[col], w1 = slw[col + 1];
                #pragma unroll
                for (int h = 0; h < 2; h++) {
                    float o0 = (acc[mt][nb][2*h]   - mean[mt][h]) * rstd[mt][h] * s0 + c0;
                    float o1 = (acc[mt][nb][2*h+1] - mean[mt][h]) * rstd[mt][h] * s1 + c1;
                    dp[mt][h] += o0 * w0 + o1 * w1;
                }
            }
        __syncthreads();             // reuse ps for dot partials
        #pragma unroll
        for (int mt = 0; mt < 2; mt++)
            #pragma unroll
            for (int h = 0; h < 2; h++) {
                float d = dp[mt][h];
                d += __shfl_xor_sync(0xffffffffu, d, 1);
                d += __shfl_xor_sync(0xffffffffu, d, 2);
                if ((lane & 3) == 0) {
                    int r = warp_m + mt * 16 + rowq + h * 8;
                    ps[r * 4 + wn] = d;
                }
            }
        __syncthreads();
        if (tid < 128) {
            int r = tid;
            float d = ps[r * 4] + ps[r * 4 + 1] + ps[r * 4 + 2] + ps[r * 4 + 3] + lb[0];
            int tok = m0 + r;
            if (maskp[tok]) d = 0.f;
            if (MODE == 2)
                d = fmaxf(rintf(expf(d) * (float)(*scale)), 0.f);
            outs[tok] = d;
        }
    }
}

// ==================================================================
// weight repacks
// ==================================================================
// 3-block [Whi|Wlo|Whi]: mats 0=(w1,p0) 1=(w2,p0) 2=(w2,p1) 3=(w2,p2)
__global__ void repack_w6(const float* __restrict__ w1, const float* __restrict__ w2)
{
    int e = blockIdx.x * 256 + threadIdx.x;      // 4 * 589824
    if (e >= 4 * 589824) return;
    int mat = e / 589824;
    int r   = e - mat * 589824;
    int n = r / 2304, kq = r - n * 2304;
    int blk = kq / 768, k = kq - blk * 768;
    int kk = k >> 8, c = k & 255;
    int p = (mat <= 1) ? 0 : (mat - 1);           // 0,0,1,2
    const float* src = (mat == 0) ? w1 : w2;
    float w = src[(((size_t)p * 3 + kk) * 256 + c) * 256 + n];
    if (blk == 1) {
        float hi = __half2float(__float2half_rn(w));
        g_W6[mat][r] = __float2half_rn(w - hi);
    } else {
        g_W6[mat][r] = __float2half_rn(w);
    }
}

// 2-block [Whi|Wlo]: mats 0=(w1,p1) 1=(w1,p2)
__global__ void repack_w2(const float* __restrict__ w1)
{
    int e = blockIdx.x * 256 + threadIdx.x;      // 2 * 393216
    if (e >= 2 * 393216) return;
    int mat = e / 393216;
    int r   = e - mat * 393216;
    int n = r / 1536, kq = r - n * 1536;
    int blk = kq / 768, k = kq - blk * 768;
    int kk = k >> 8, c = k & 255;
    int p = mat + 1;
    float w = w1[(((size_t)p * 3 + kk) * 256 + c) * 256 + n];
    if (blk == 1) {
        float hi = __half2float(__float2half_rn(w));
        g_W2[mat][r] = __float2half_rn(w - hi);
    } else {
        g_W2[mat][r] = __float2half_rn(w);
    }
}

// fp32 -> fp16 hi/lo split (duration input)
__global__ void split2_kernel(const float* __restrict__ src, __half* __restrict__ ph,
                              __half* __restrict__ pl, int n4)
{
    int i = blockIdx.x * 256 + threadIdx.x;
    if (i >= n4) return;
    float4 v = ((const float4*)src)[i];
    float a[4] = {v.x, v.y, v.z, v.w};
    uint32_t hh[2], ll[2];
    #pragma unroll
    for (int j = 0; j < 2; j++) {
        __half h0 = __float2half_rn(a[2*j]);
        __half h1 = __float2half_rn(a[2*j+1]);
        __half2 p = __halves2half2(h0, h1);
        hh[j] = *(uint32_t*)&p;
        ll[j] = packh2(a[2*j] - __half2float(h0), a[2*j+1] - __half2float(h1));
    }
    ((uint2*)ph)[i] = make_uint2(hh[0], hh[1]);
    ((uint2*)pl)[i] = make_uint2(ll[0], ll[1]);
}

// ==================================================================
// cumsum / length-regulate / embedding add
// ==================================================================
__global__ void cumsum_kernel(const int* __restrict__ dur, int* __restrict__ cs)
{
    __shared__ int s[512];
    int b = blockIdx.x, t = threadIdx.x;
    s[t] = dur[b * 512 + t];
    __syncthreads();
    for (int off = 1; off < 512; off <<= 1) {
        int v = (t >= off) ? s[t - off] : 0;
        __syncthreads();
        s[t] += v;
        __syncthreads();
    }
    cs[b * 512 + t] = s[t];
}

__global__ void length_reg_kernel(const float* __restrict__ hidden,
                                  const int* __restrict__ cs,
                                  float* __restrict__ X, __half* __restrict__ Xh)
{
    __shared__ int scs[512];
    int tid = threadIdx.x;
    int base = blockIdx.x * 4;
    int b    = base >> 12;
    int tloc = base & 4095;
    const int* csb = cs + b * 512;
    scs[tid] = csb[tid];
    scs[tid + 256] = csb[tid + 256];
    __syncthreads();
    int g = tid >> 6, lane = tid & 63;
    int t = tloc + g;
    int lo = 0, hi = 512;
    while (lo < hi) { int mid = (lo + hi) >> 1; if (scs[mid] <= t) lo = mid + 1; else hi = mid; }
    int idx = lo < 512 ? lo : 511;
    bool valid = t < scs[511];
    float4 v = make_float4(0.f, 0.f, 0.f, 0.f);
    if (valid) v = *(const float4*)(hidden + ((size_t)b * 512 + idx) * 256 + lane * 4);
    size_t off = ((size_t)b * 4096 + t) * 256 + lane * 4;
    *(float4*)(X + off) = v;
    *(uint2*)(Xh + off) = make_uint2(packh2(v.x, v.y), packh2(v.z, v.w));
}

__global__ void add_emb_kernel(const float* __restrict__ X, const float* __restrict__ tgt,
                               const float* __restrict__ bins, const float* __restrict__ emb,
                               float* __restrict__ outp, __half* __restrict__ Xh, int wxb)
{
    __shared__ float sb[256];
    int tid = threadIdx.x;
    sb[tid] = bins[tid];
    __syncthreads();
    int base = blockIdx.x * 4;
    int g = tid >> 6, lane = tid & 63;
    int t = base + g;
    float v = tgt[t];
    int lo = 0, hi = 256;
    while (lo < hi) { int mid = (lo + hi) >> 1; if (sb[mid] < v) lo = mid + 1; else hi = mid; }
    int idx = lo < 256 ? lo : 255;
    size_t off = (size_t)t * 256 + lane * 4;
    float4 a = *(const float4*)(X + off);
    float4 e = *(const float4*)(emb + (size_t)idx * 256 + lane * 4);
    a.x += e.x; a.y += e.y; a.z += e.z; a.w += e.w;
    *(float4*)(outp + off) = a;
    if (wxb)
        *(uint2*)(Xh + off) = make_uint2(packh2(a.x, a.y), packh2(a.z, a.w));
}

// ==================================================================
// launch — dual-stream fork/join (R15 structure)
// ==================================================================
extern "C" void kernel_launch(void* const* d_in, const int* in_sizes, int n_in,
                              void* d_out, int out_size)
{
    const float*         hidden    = (const float*)d_in[0];
    const unsigned char* mask      = (const unsigned char*)d_in[1];
    const unsigned char* fmask     = (const unsigned char*)d_in[2];
    const int*           dur_tgt   = (const int*)d_in[3];
    const float*         pitch_tgt = (const float*)d_in[4];
    const float*         energy_tgt= (const float*)d_in[5];
    const int*           dscale    = (const int*)d_in[6];
    const float*         w1        = (const float*)d_in[7];
    const float*         b1        = (const float*)d_in[8];
    const float*         l1s       = (const float*)d_in[9];
    const float*         l1b       = (const float*)d_in[10];
    const float*         w2        = (const float*)d_in[11];
    const float*         b2        = (const float*)d_in[12];
    const float*         l2s       = (const float*)d_in[13];
    const float*         l2b       = (const float*)d_in[14];
    const float*         lw        = (const float*)d_in[15];
    const float*         lb        = (const float*)d_in[16];
    const float*         pbins     = (const float*)d_in[17];
    const float*         pemb      = (const float*)d_in[18];
    const float*         ebins     = (const float*)d_in[19];
    const float*         eemb      = (const float*)d_in[20];

    static cudaStream_t s1 = nullptr;
    static cudaEvent_t eFork = nullptr, eRepack = nullptr, eLenReg = nullptr, eDur = nullptr;
    if (!s1) {
        cudaStreamCreateWithFlags(&s1, cudaStreamNonBlocking);
        cudaEventCreateWithFlags(&eFork,   cudaEventDisableTiming);
        cudaEventCreateWithFlags(&eRepack, cudaEventDisableTiming);
        cudaEventCreateWithFlags(&eLenReg, cudaEventDisableTiming);
        cudaEventCreateWithFlags(&eDur,    cudaEventDisableTiming);
        cudaFuncSetAttribute((const void*)hmma_conv<0,3>, cudaFuncAttributeMaxDynamicSharedMemorySize, TSMEM);
        cudaFuncSetAttribute((const void*)hmma_conv<1,3>, cudaFuncAttributeMaxDynamicSharedMemorySize, TSMEM);
        cudaFuncSetAttribute((const void*)hmma_conv<2,3>, cudaFuncAttributeMaxDynamicSharedMemorySize, TSMEM);
        cudaFuncSetAttribute((const void*)hmma_conv<0,2>, cudaFuncAttributeMaxDynamicSharedMemorySize, TSMEM);
    }

    float* X;  __half *Xh, *H1h, *H1l, *Dh, *Dl, *DH1h, *DH1l, *W6, *W2;  int* cs;
    cudaGetSymbolAddress((void**)&X,    g_X);
    cudaGetSymbolAddress((void**)&Xh,   g_Xh);
    cudaGetSymbolAddress((void**)&H1h,  g_H1h);
    cudaGetSymbolAddress((void**)&H1l,  g_H1l);
    cudaGetSymbolAddress((void**)&Dh,   g_Dh);
    cudaGetSymbolAddress((void**)&Dl,   g_Dl);
    cudaGetSymbolAddress((void**)&DH1h, g_DH1h);
    cudaGetSymbolAddress((void**)&DH1l, g_DH1l);
    cudaGetSymbolAddress((void**)&W6,   g_W6);
    cudaGetSymbolAddress((void**)&W2,   g_W2);
    cudaGetSymbolAddress((void**)&cs,   g_cs);

    float* out_rd     = (float*)d_out;
    float* out_pitch  = out_rd + 32 * 512;
    float* out_energy = out_pitch + 32 * 4096;
    float* out_ve     = out_energy + 32 * 4096;

    const size_t WS6 = 589824, WS2 = 393216;
    const int NT = 131072;

    // ---- fork s1 from the capture (main) stream ----
    cudaEventRecord(eFork, 0);
    cudaStreamWaitEvent(s1, eFork, 0);

    // ---- main stream: weight repacks ----
    repack_w6<<<9216, 256>>>(w1, w2);
    repack_w2<<<3072, 256>>>(w1);
    cudaEventRecord(eRepack, 0);

    // ---- s1: cumsum + length-regulate (independent of repack) ----
    cumsum_kernel<<<32, 512, 0, s1>>>(dur_tgt, cs);
    length_reg_kernel<<<32 * 4096 / 4, 256, 0, s1>>>(hidden, cs, X, Xh);
    cudaEventRecord(eLenReg, s1);

    // ---- s1: duration predictor (3-block both convs; exactness for rounding) ----
    split2_kernel<<<4096, 256, 0, s1>>>(hidden, Dh, Dl, 1048576);
    cudaStreamWaitEvent(s1, eRepack, 0);
    hmma_conv<0,3><<<128, 512, TSMEM, s1>>>(Dh, Dl, W6 + 0 * WS6, b1, l1s, l1b,
                                            nullptr, nullptr, nullptr, nullptr,
                                            DH1h, DH1l, nullptr, 512);
    hmma_conv<2,3><<<128, 512, TSMEM, s1>>>(DH1h, DH1l, W6 + 1 * WS6, b2, l2s, l2b,
                                            lw, lb, mask, dscale,
                                            nullptr, nullptr, out_rd, 512);
    cudaEventRecord(eDur, s1);

    // ---- main stream: pitch predictor (conv1 2-block, conv2 3-block) ----
    cudaStreamWaitEvent(0, eLenReg, 0);
    hmma_conv<0,2><<<NT / 128, 512, TSMEM>>>(Xh, nullptr, W2 + 0 * WS2, b1 + 256, l1s + 256, l1b + 256,
                                             nullptr, nullptr, nullptr, nullptr,
                                             H1h, H1l, nullptr, 4096);
    hmma_conv<1,3><<<NT / 128, 512, TSMEM>>>(H1h, H1l, W6 + 2 * WS6, b2 + 256, l2s + 256, l2b + 256,
                                             lw + 256, lb + 1, fmask, nullptr,
                                             nullptr, nullptr, out_pitch, 4096);
    add_emb_kernel<<<NT / 4, 256>>>(X, pitch_tgt, pbins, pemb, X, Xh, 1);

    // ---- main stream: energy predictor ----
    hmma_conv<0,2><<<NT / 128, 512, TSMEM>>>(Xh, nullptr, W2 + 1 * WS2, b1 + 512, l1s + 512, l1b + 512,
                                             nullptr, nullptr, nullptr, nullptr,
                                             H1h, H1l, nullptr, 4096);
    hmma_conv<1,3><<<NT / 128, 512, TSMEM>>>(H1h, H1l, W6 + 3 * WS6, b2 + 512, l2s + 512, l2b + 512,
                                             lw + 512, lb + 2, fmask, nullptr,
                                             nullptr, nullptr, out_energy, 4096);
    add_emb_kernel<<<NT / 4, 256>>>(X, energy_tgt, ebins, eemb, out_ve, nullptr, 0);

    // ---- join s1 back into the capture stream ----
    cudaStreamWaitEvent(0, eDur, 0);
}